// round 6
// baseline (speedup 1.0000x reference)
#include <cuda_runtime.h>
#include <cuda_bf16.h>
#include <cstdint>

// Problem constants
#define DMODEL 768
#define NHEADS 12
#define DK     64
#define DFF    3072
#define BB     2
#define SS     2048
#define MTOK   (BB * SS)          // 4096 tokens
#define L2E    1.44269504088896f

// ---------------------------------------------------------------------------
// Scratch (__device__ globals; no allocation allowed in kernel_launch)
// ---------------------------------------------------------------------------
__device__ float g_h  [MTOK * DMODEL];                 // LN output (reused for LN1 and LN2)
__device__ float g_q  [MTOK * DMODEL];                 // [B,S,H*dk]
__device__ float g_k  [MTOK * DMODEL];
__device__ float g_v  [MTOK * DMODEL];
__device__ float g_ctx[MTOK * DMODEL];                 // [B,S,D]
__device__ float g_x1 [MTOK * DMODEL];                 // residual-1 output
__device__ float g_ff [MTOK * DFF];                    // FFN hidden
__device__ float g_scores[(long long)BB * NHEADS * SS * SS];  // 402 MB scores/attn

// ---------------------------------------------------------------------------
// LayerNorm (torch-style: unbiased std, scalar alpha/bias)
//   out = alpha * (x - mean) / (std + eps) + bias,  std = sqrt(sum((x-m)^2)/(D-1))
// One block (256 threads) per 768-element row. Two-pass for accuracy.
// ---------------------------------------------------------------------------
__global__ void ln_kernel(const float* __restrict__ x, float* __restrict__ out,
                          const float* __restrict__ alpha, const float* __restrict__ beta)
{
    const int row = blockIdx.x;
    const float* xr = x + (size_t)row * DMODEL;
    float* orow = out + (size_t)row * DMODEL;
    const int tid = threadIdx.x;   // 256

    float v0 = xr[tid], v1 = xr[tid + 256], v2 = xr[tid + 512];
    float s = v0 + v1 + v2;

    __shared__ float red[8];
    #pragma unroll
    for (int o = 16; o; o >>= 1) s += __shfl_xor_sync(0xffffffffu, s, o);
    if ((tid & 31) == 0) red[tid >> 5] = s;
    __syncthreads();
    if (tid < 32) {
        float t = (tid < 8) ? red[tid] : 0.0f;
        #pragma unroll
        for (int o = 4; o; o >>= 1) t += __shfl_xor_sync(0xffffffffu, t, o);
        if (tid == 0) red[0] = t;
    }
    __syncthreads();
    const float mean = red[0] * (1.0f / DMODEL);
    const float d0 = v0 - mean, d1 = v1 - mean, d2 = v2 - mean;
    float q = d0 * d0 + d1 * d1 + d2 * d2;
    __syncthreads();   // protect red[] before reuse

    #pragma unroll
    for (int o = 16; o; o >>= 1) q += __shfl_xor_sync(0xffffffffu, q, o);
    if ((tid & 31) == 0) red[tid >> 5] = q;
    __syncthreads();
    if (tid < 32) {
        float t = (tid < 8) ? red[tid] : 0.0f;
        #pragma unroll
        for (int o = 4; o; o >>= 1) t += __shfl_xor_sync(0xffffffffu, t, o);
        if (tid == 0) red[0] = t;
    }
    __syncthreads();
    const float var = red[0] * (1.0f / (DMODEL - 1));
    const float inv = alpha[0] / (sqrtf(var) + 1e-6f);
    const float bb  = beta[0];

    orow[tid]       = d0 * inv + bb;
    orow[tid + 256] = d1 * inv + bb;
    orow[tid + 512] = d2 * inv + bb;
}

// ---------------------------------------------------------------------------
// Masked scaled softmax over scores rows. One block (256 thr) per row (S=2048).
//   s' = s * 1/sqrt(dk); mask==0 -> -1e9; softmax (max-subtracted).
// ---------------------------------------------------------------------------
__global__ void softmax_kernel(float* __restrict__ scores, const int* __restrict__ mask)
{
    const long long row = blockIdx.x;                 // 0 .. B*H*S-1
    const int b = (int)(row / ((long long)NHEADS * SS));
    float* sr = scores + row * (long long)SS;
    const int* mrow = mask + (long long)b * SS;
    const int tid = threadIdx.x;

    float v[8];
    float mx = -3.0e38f;
    #pragma unroll
    for (int i = 0; i < 8; i++) {
        const int c = tid + i * 256;
        float s = sr[c] * 0.125f;
        if (mrow[c] == 0) s = -1e9f;
        v[i] = s;
        mx = fmaxf(mx, s);
    }

    __shared__ float red[8];
    #pragma unroll
    for (int o = 16; o; o >>= 1) mx = fmaxf(mx, __shfl_xor_sync(0xffffffffu, mx, o));
    if ((tid & 31) == 0) red[tid >> 5] = mx;
    __syncthreads();
    if (tid < 32) {
        float t = (tid < 8) ? red[tid] : -3.0e38f;
        #pragma unroll
        for (int o = 4; o; o >>= 1) t = fmaxf(t, __shfl_xor_sync(0xffffffffu, t, o));
        if (tid == 0) red[0] = t;
    }
    __syncthreads();
    mx = red[0];
    __syncthreads();   // protect red[] before reuse

    float sum = 0.0f;
    #pragma unroll
    for (int i = 0; i < 8; i++) {
        const float p = exp2f((v[i] - mx) * L2E);
        v[i] = p;
        sum += p;
    }
    #pragma unroll
    for (int o = 16; o; o >>= 1) sum += __shfl_xor_sync(0xffffffffu, sum, o);
    if ((tid & 31) == 0) red[tid >> 5] = sum;
    __syncthreads();
    if (tid < 32) {
        float t = (tid < 8) ? red[tid] : 0.0f;
        #pragma unroll
        for (int o = 4; o; o >>= 1) t += __shfl_xor_sync(0xffffffffu, t, o);
        if (tid == 0) red[0] = t;
    }
    __syncthreads();
    const float inv = 1.0f / red[0];
    #pragma unroll
    for (int i = 0; i < 8; i++) sr[tid + i * 256] = v[i] * inv;
}

// ---------------------------------------------------------------------------
// Templated register-tiled SGEMM (fp32).
//   C[m][n] = sum_k A[m][k] * B[k][n] (+bias[n]) (+Res[m][n]) (relu?)
// TRANSB: logical B[k][n] read as Bm[n*ldb + k]  (for Q @ K^T)
// Batched via blockIdx.z with composite offsets: z -> (za = z/ZB, zb = z%ZB),
//   ptr += za*off1 + zb*off2   (lets one kernel index [B,S,H*dk] sub-matrices)
// Requires: M%BM==0, N%BN==0, K%BK==0, all ld's and base offsets %4==0.
// ---------------------------------------------------------------------------
template<int BM, int BN, int BK, int TM, int TN, bool TRANSB>
__global__ __launch_bounds__(256, 2)
void gemm_kernel(const float* __restrict__ A, const float* __restrict__ Bm,
                 const float* __restrict__ bias, const float* __restrict__ Res,
                 float* __restrict__ C,
                 int K, int lda, int ldb, int ldc,
                 long long offA1, long long offA2,
                 long long offB1, long long offB2,
                 long long offC1, long long offC2,
                 int ZB, int relu)
{
    constexpr int NTH  = (BM / TM) * (BN / TN);     // must be 256
    constexpr int ASL  = BM + 4;
    constexpr int BSL  = BN + 4;
    __shared__ float As[BK][ASL];
    __shared__ float Bs[BK][BSL];

    const int z  = blockIdx.z;
    const int za = z / ZB, zb = z % ZB;
    A  += (long long)za * offA1 + (long long)zb * offA2;
    Bm += (long long)za * offB1 + (long long)zb * offB2;
    const long long coff = (long long)za * offC1 + (long long)zb * offC2;
    C += coff;
    if (Res) Res += coff;

    const int tid = threadIdx.x;
    const int tx  = tid % (BN / TN);
    const int ty  = tid / (BN / TN);
    const int m0  = blockIdx.y * BM;
    const int n0  = blockIdx.x * BN;

    float acc[TM][TN];
    #pragma unroll
    for (int i = 0; i < TM; i++)
        #pragma unroll
        for (int j = 0; j < TN; j++) acc[i][j] = 0.0f;

    constexpr int ALD  = BM * BK / 4;   // float4 loads per A tile
    constexpr int BLD  = BK * BN / 4;   // float4 loads per B tile

    for (int k0 = 0; k0 < K; k0 += BK) {
        // --- A tile: transpose-store As[k][m] ---
        #pragma unroll
        for (int u = 0; u < ALD / NTH; u++) {
            const int f  = u * NTH + tid;
            const int m  = f / (BK / 4);
            const int kc = (f % (BK / 4)) * 4;
            const float4 val = *(const float4*)(A + (long long)(m0 + m) * lda + k0 + kc);
            As[kc + 0][m] = val.x; As[kc + 1][m] = val.y;
            As[kc + 2][m] = val.z; As[kc + 3][m] = val.w;
        }
        // --- B tile ---
        if (TRANSB) {
            #pragma unroll
            for (int u = 0; u < BLD / NTH; u++) {
                const int f  = u * NTH + tid;
                const int n  = f / (BK / 4);
                const int kc = (f % (BK / 4)) * 4;
                const float4 val = *(const float4*)(Bm + (long long)(n0 + n) * ldb + k0 + kc);
                Bs[kc + 0][n] = val.x; Bs[kc + 1][n] = val.y;
                Bs[kc + 2][n] = val.z; Bs[kc + 3][n] = val.w;
            }
        } else {
            #pragma unroll
            for (int u = 0; u < BLD / NTH; u++) {
                const int f  = u * NTH + tid;
                const int k  = f / (BN / 4);
                const int nc = (f % (BN / 4)) * 4;
                *(float4*)&Bs[k][nc] = *(const float4*)(Bm + (long long)(k0 + k) * ldb + n0 + nc);
            }
        }
        __syncthreads();

        #pragma unroll
        for (int kk = 0; kk < BK; kk++) {
            float a[TM], b[TN];
            #pragma unroll
            for (int i = 0; i < TM; i += 4)
                *(float4*)&a[i] = *(const float4*)&As[kk][ty * TM + i];
            #pragma unroll
            for (int j = 0; j < TN; j += 4)
                *(float4*)&b[j] = *(const float4*)&Bs[kk][tx * TN + j];
            #pragma unroll
            for (int i = 0; i < TM; i++)
                #pragma unroll
                for (int j = 0; j < TN; j++)
                    acc[i][j] += a[i] * b[j];
        }
        __syncthreads();
    }

    // --- epilogue ---
    #pragma unroll
    for (int i = 0; i < TM; i++) {
        const int m = m0 + ty * TM + i;
        #pragma unroll
        for (int j = 0; j < TN; j += 4) {
            const int n = n0 + tx * TN + j;
            float4 r;
            r.x = acc[i][j];     r.y = acc[i][j + 1];
            r.z = acc[i][j + 2]; r.w = acc[i][j + 3];
            if (bias) {
                r.x += bias[n];     r.y += bias[n + 1];
                r.z += bias[n + 2]; r.w += bias[n + 3];
            }
            if (Res) {
                const float4 rv = *(const float4*)(Res + (long long)m * ldc + n);
                r.x += rv.x; r.y += rv.y; r.z += rv.z; r.w += rv.w;
            }
            if (relu) {
                r.x = fmaxf(r.x, 0.0f); r.y = fmaxf(r.y, 0.0f);
                r.z = fmaxf(r.z, 0.0f); r.w = fmaxf(r.w, 0.0f);
            }
            *(float4*)(C + (long long)m * ldc + n) = r;
        }
    }
}

// ---------------------------------------------------------------------------
// Launch driver
// ---------------------------------------------------------------------------
extern "C" void kernel_launch(void* const* d_in, const int* in_sizes, int n_in,
                              void* d_out, int out_size)
{
    (void)in_sizes; (void)n_in; (void)out_size;
    const float* x    = (const float*)d_in[0];
    const int*   mask = (const int*)  d_in[1];
    const float* wq = (const float*)d_in[2],  *bq = (const float*)d_in[3];
    const float* wk = (const float*)d_in[4],  *bk = (const float*)d_in[5];
    const float* wv = (const float*)d_in[6],  *bv = (const float*)d_in[7];
    const float* wo = (const float*)d_in[8],  *bo = (const float*)d_in[9];
    const float* w1 = (const float*)d_in[10], *b1 = (const float*)d_in[11];
    const float* w2 = (const float*)d_in[12], *b2 = (const float*)d_in[13];
    const float* ln1a = (const float*)d_in[14], *ln1b = (const float*)d_in[15];
    const float* ln2a = (const float*)d_in[16], *ln2b = (const float*)d_in[17];
    float* out = (float*)d_out;

    float *h, *q, *k, *v, *ctx, *x1, *ff, *sc;
    cudaGetSymbolAddress((void**)&h,   g_h);
    cudaGetSymbolAddress((void**)&q,   g_q);
    cudaGetSymbolAddress((void**)&k,   g_k);
    cudaGetSymbolAddress((void**)&v,   g_v);
    cudaGetSymbolAddress((void**)&ctx, g_ctx);
    cudaGetSymbolAddress((void**)&x1,  g_x1);
    cudaGetSymbolAddress((void**)&ff,  g_ff);
    cudaGetSymbolAddress((void**)&sc,  g_scores);

    const long long SSsq = (long long)SS * SS;

    // 1) LN1: h = ln(x)
    ln_kernel<<<MTOK, 256>>>(x, h, ln1a, ln1b);

    // 2-4) QKV projections: [4096,768] @ [768,768] + bias -> [B,S,H*dk]
    {
        dim3 grid(DMODEL / 128, MTOK / 128, 1);
        gemm_kernel<128,128,16,8,8,false><<<grid, 256>>>(
            h, wq, bq, nullptr, q, DMODEL, DMODEL, DMODEL, DMODEL,
            0,0, 0,0, 0,0, 1, 0);
        gemm_kernel<128,128,16,8,8,false><<<grid, 256>>>(
            h, wk, bk, nullptr, k, DMODEL, DMODEL, DMODEL, DMODEL,
            0,0, 0,0, 0,0, 1, 0);
        gemm_kernel<128,128,16,8,8,false><<<grid, 256>>>(
            h, wv, bv, nullptr, v, DMODEL, DMODEL, DMODEL, DMODEL,
            0,0, 0,0, 0,0, 1, 0);
    }

    // 5) scores[b,h] = Q_bh @ K_bh^T   (M=S, N=S, K=dk), batched z = b*H + h
    {
        dim3 grid(SS / 128, SS / 128, BB * NHEADS);
        gemm_kernel<128,128,16,8,8,true><<<grid, 256>>>(
            q, k, nullptr, nullptr, sc,
            /*K=*/DK, /*lda=*/DMODEL, /*ldb=*/DMODEL, /*ldc=*/SS,
            /*offA1(b)=*/(long long)SS * DMODEL, /*offA2(h)=*/DK,
            /*offB1(b)=*/(long long)SS * DMODEL, /*offB2(h)=*/DK,
            /*offC1(b)=*/ (long long)NHEADS * SSsq, /*offC2(h)=*/ SSsq,
            /*ZB=*/NHEADS, 0);
    }

    // 6) masked scaled softmax, in place on scores
    softmax_kernel<<<BB * NHEADS * SS, 256>>>(sc, mask);

    // 7) ctx[b,h] = attn_bh @ V_bh   (M=S, N=dk, K=S), write into [B,S,D]
    {
        dim3 grid(DK / 64, SS / 128, BB * NHEADS);
        gemm_kernel<128,64,16,8,4,false><<<grid, 256>>>(
            sc, v, nullptr, nullptr, ctx,
            /*K=*/SS, /*lda=*/SS, /*ldb=*/DMODEL, /*ldc=*/DMODEL,
            /*offA1(b)=*/(long long)NHEADS * SSsq, /*offA2(h)=*/SSsq,
            /*offB1(b)=*/(long long)SS * DMODEL, /*offB2(h)=*/DK,
            /*offC1(b)=*/(long long)SS * DMODEL, /*offC2(h)=*/DK,
            /*ZB=*/NHEADS, 0);
    }

    // 8) x1 = x + ctx @ wo + bo
    {
        dim3 grid(DMODEL / 128, MTOK / 128, 1);
        gemm_kernel<128,128,16,8,8,false><<<grid, 256>>>(
            ctx, wo, bo, x, x1, DMODEL, DMODEL, DMODEL, DMODEL,
            0,0, 0,0, 0,0, 1, 0);
    }

    // 9) LN2: h = ln(x1)
    ln_kernel<<<MTOK, 256>>>(x1, h, ln2a, ln2b);

    // 10) ff = relu(h @ w1 + b1)
    {
        dim3 grid(DFF / 128, MTOK / 128, 1);
        gemm_kernel<128,128,16,8,8,false><<<grid, 256>>>(
            h, w1, b1, nullptr, ff, DMODEL, DMODEL, DFF, DFF,
            0,0, 0,0, 0,0, 1, 1);
    }

    // 11) out = x1 + ff @ w2 + b2
    {
        dim3 grid(DMODEL / 128, MTOK / 128, 1);
        gemm_kernel<128,128,16,8,8,false><<<grid, 256>>>(
            ff, w2, b2, x1, out, DFF, DFF, DMODEL, DMODEL,
            0,0, 0,0, 0,0, 1, 0);
    }
}

// round 8
// speedup vs baseline: 1.8037x; 1.8037x over previous
#include <cuda_runtime.h>
#include <cuda_bf16.h>
#include <cstdint>

// Problem constants
#define DMODEL 768
#define NHEADS 12
#define DK     64
#define DFF    3072
#define BB     2
#define SS     2048
#define MTOK   (BB * SS)          // 4096 tokens
#define L2E    1.44269504088896f

// ---------------------------------------------------------------------------
// Scratch (__device__ globals; no allocation allowed in kernel_launch)
// ---------------------------------------------------------------------------
__device__ float g_h  [MTOK * DMODEL];
__device__ float g_q  [MTOK * DMODEL];
__device__ float g_k  [MTOK * DMODEL];
__device__ float g_v  [MTOK * DMODEL];
__device__ float g_ctx[MTOK * DMODEL];
__device__ float g_x1 [MTOK * DMODEL];
__device__ float g_ff [MTOK * DFF];
__device__ float g_scores[(long long)BB * NHEADS * SS * SS];  // 402 MB

// ---------------------------------------------------------------------------
// LayerNorm (torch-style: unbiased std, scalar alpha/bias). 1 block / row.
// ---------------------------------------------------------------------------
__global__ void ln_kernel(const float* __restrict__ x, float* __restrict__ out,
                          const float* __restrict__ alpha, const float* __restrict__ beta)
{
    const int row = blockIdx.x;
    const float* xr = x + (size_t)row * DMODEL;
    float* orow = out + (size_t)row * DMODEL;
    const int tid = threadIdx.x;   // 256

    float v0 = xr[tid], v1 = xr[tid + 256], v2 = xr[tid + 512];
    float s = v0 + v1 + v2;

    __shared__ float red[8];
    #pragma unroll
    for (int o = 16; o; o >>= 1) s += __shfl_xor_sync(0xffffffffu, s, o);
    if ((tid & 31) == 0) red[tid >> 5] = s;
    __syncthreads();
    if (tid < 32) {
        float t = (tid < 8) ? red[tid] : 0.0f;
        #pragma unroll
        for (int o = 4; o; o >>= 1) t += __shfl_xor_sync(0xffffffffu, t, o);
        if (tid == 0) red[0] = t;
    }
    __syncthreads();
    const float mean = red[0] * (1.0f / DMODEL);
    const float d0 = v0 - mean, d1 = v1 - mean, d2 = v2 - mean;
    float q = d0 * d0 + d1 * d1 + d2 * d2;
    __syncthreads();

    #pragma unroll
    for (int o = 16; o; o >>= 1) q += __shfl_xor_sync(0xffffffffu, q, o);
    if ((tid & 31) == 0) red[tid >> 5] = q;
    __syncthreads();
    if (tid < 32) {
        float t = (tid < 8) ? red[tid] : 0.0f;
        #pragma unroll
        for (int o = 4; o; o >>= 1) t += __shfl_xor_sync(0xffffffffu, t, o);
        if (tid == 0) red[0] = t;
    }
    __syncthreads();
    const float var = red[0] * (1.0f / (DMODEL - 1));
    const float inv = alpha[0] / (sqrtf(var) + 1e-6f);
    const float bb  = beta[0];

    orow[tid]       = d0 * inv + bb;
    orow[tid + 256] = d1 * inv + bb;
    orow[tid + 512] = d2 * inv + bb;
}

// ---------------------------------------------------------------------------
// Masked scaled softmax over scores rows. One block (256 thr) per row (S=2048).
// ---------------------------------------------------------------------------
__global__ void softmax_kernel(float* __restrict__ scores, const int* __restrict__ mask)
{
    const long long row = blockIdx.x;
    const int b = (int)(row / ((long long)NHEADS * SS));
    float* sr = scores + row * (long long)SS;
    const int* mrow = mask + (long long)b * SS;
    const int tid = threadIdx.x;

    float v[8];
    float mx = -3.0e38f;
    #pragma unroll
    for (int i = 0; i < 8; i++) {
        const int c = tid + i * 256;
        float s = sr[c] * 0.125f;
        if (mrow[c] == 0) s = -1e9f;
        v[i] = s;
        mx = fmaxf(mx, s);
    }

    __shared__ float red[8];
    #pragma unroll
    for (int o = 16; o; o >>= 1) mx = fmaxf(mx, __shfl_xor_sync(0xffffffffu, mx, o));
    if ((tid & 31) == 0) red[tid >> 5] = mx;
    __syncthreads();
    if (tid < 32) {
        float t = (tid < 8) ? red[tid] : -3.0e38f;
        #pragma unroll
        for (int o = 4; o; o >>= 1) t = fmaxf(t, __shfl_xor_sync(0xffffffffu, t, o));
        if (tid == 0) red[0] = t;
    }
    __syncthreads();
    mx = red[0];
    __syncthreads();

    float sum = 0.0f;
    #pragma unroll
    for (int i = 0; i < 8; i++) {
        const float p = exp2f((v[i] - mx) * L2E);
        v[i] = p;
        sum += p;
    }
    #pragma unroll
    for (int o = 16; o; o >>= 1) sum += __shfl_xor_sync(0xffffffffu, sum, o);
    if ((tid & 31) == 0) red[tid >> 5] = sum;
    __syncthreads();
    if (tid < 32) {
        float t = (tid < 8) ? red[tid] : 0.0f;
        #pragma unroll
        for (int o = 4; o; o >>= 1) t += __shfl_xor_sync(0xffffffffu, t, o);
        if (tid == 0) red[0] = t;
    }
    __syncthreads();
    const float inv = 1.0f / red[0];
    #pragma unroll
    for (int i = 0; i < 8; i++) sr[tid + i * 256] = v[i] * inv;
}

// ---------------------------------------------------------------------------
// Tensor-core GEMM: mma.sync.m16n8k8 tf32, fp32 accumulate.
//   C = A @ B (+bias) (+Res) (relu?), TRANSB reads B[k][n] as Bm[n*ldb+k].
// Block tile BM x BN x 32, 8 warps (256 thr), warp tile WM x WN.
// Double-buffered smem, register-prefetch of the next gmem tile.
// Fragment layout (m16n8k8, row.col):
//   a0=A[g][t]  a1=A[g+8][t]  a2=A[g][t+4]  a3=A[g+8][t+4]
//   b0=B[t][g]  b1=B[t+4][g]
//   c0=C[g][2t] c1=C[g][2t+1] c2=C[g+8][2t] c3=C[g+8][2t+1]
// Smem padded +8 floats/row -> frag LDS addresses (8t+g mod 32) conflict-free.
// ---------------------------------------------------------------------------
__device__ __forceinline__ uint32_t f2tf32(float f) {
    uint32_t r;
    asm("cvt.rna.tf32.f32 %0, %1;" : "=r"(r) : "f"(f));
    return r;
}

__device__ __forceinline__ void mma_tf32(float* c, const uint32_t* a, const uint32_t* b) {
    asm volatile(
        "mma.sync.aligned.m16n8k8.row.col.f32.tf32.tf32.f32 "
        "{%0,%1,%2,%3}, {%4,%5,%6,%7}, {%8,%9}, {%0,%1,%2,%3};"
        : "+f"(c[0]), "+f"(c[1]), "+f"(c[2]), "+f"(c[3])
        : "r"(a[0]), "r"(a[1]), "r"(a[2]), "r"(a[3]), "r"(b[0]), "r"(b[1]));
}

template<int BM, int BN, int WM, int WN, bool TRANSB>
__global__ __launch_bounds__(256)
void mma_gemm(const float* __restrict__ A, const float* __restrict__ Bm,
              const float* __restrict__ bias, const float* __restrict__ Res,
              float* __restrict__ C,
              int K, int lda, int ldb, int ldc,
              long long offA1, long long offA2,
              long long offB1, long long offB2,
              long long offC1, long long offC2,
              int ZB, int relu)
{
    constexpr int BK   = 32;
    constexpr int ASTR = BM + 8;
    constexpr int BSTR = BN + 8;
    constexpr int MT   = WM / 16;
    constexpr int NT   = WN / 8;
    constexpr int WCOLS = BN / WN;
    constexpr int ALD4 = BM * BK / (4 * 256);
    constexpr int BLD4 = BN * BK / (4 * 256);

    extern __shared__ float sm[];
    float* As = sm;                       // [2][BK][ASTR], stored [k][m]
    float* Bs = sm + 2 * BK * ASTR;       // [2][BK][BSTR], stored [k][n]

    const int z  = blockIdx.z;
    const int za = z / ZB, zb = z % ZB;
    A  += (long long)za * offA1 + (long long)zb * offA2;
    Bm += (long long)za * offB1 + (long long)zb * offB2;
    const long long coff = (long long)za * offC1 + (long long)zb * offC2;
    C += coff;
    if (Res) Res += coff;

    const int tid  = threadIdx.x;
    const int warp = tid >> 5, lane = tid & 31;
    const int g = lane >> 2, t = lane & 3;
    const int wm0 = (warp / WCOLS) * WM;
    const int wn0 = (warp % WCOLS) * WN;
    const int m0 = blockIdx.y * BM;
    const int n0 = blockIdx.x * BN;

    float acc[MT][NT][4] = {};

    const int nk = K / BK;
    float4 pa[ALD4], pb[BLD4];

    auto LDG = [&](int it) {
        const int k0 = it * BK;
        #pragma unroll
        for (int u = 0; u < ALD4; ++u) {
            const int f = u * 256 + tid;
            const int m = f >> 3;             // BK/4 == 8
            const int kc = (f & 7) * 4;
            pa[u] = *(const float4*)(A + (long long)(m0 + m) * lda + k0 + kc);
        }
        #pragma unroll
        for (int u = 0; u < BLD4; ++u) {
            const int f = u * 256 + tid;
            if (TRANSB) {
                const int n = f >> 3;
                const int kc = (f & 7) * 4;
                pb[u] = *(const float4*)(Bm + (long long)(n0 + n) * ldb + k0 + kc);
            } else {
                const int k  = f / (BN / 4);
                const int nc = (f % (BN / 4)) * 4;
                pb[u] = *(const float4*)(Bm + (long long)(k0 + k) * ldb + n0 + nc);
            }
        }
    };

    auto STS = [&](int buf) {
        float* Ad = As + buf * BK * ASTR;
        float* Bd = Bs + buf * BK * BSTR;
        #pragma unroll
        for (int u = 0; u < ALD4; ++u) {
            const int f = u * 256 + tid;
            const int m = f >> 3;
            const int kc = (f & 7) * 4;
            Ad[(kc + 0) * ASTR + m] = __uint_as_float(f2tf32(pa[u].x));
            Ad[(kc + 1) * ASTR + m] = __uint_as_float(f2tf32(pa[u].y));
            Ad[(kc + 2) * ASTR + m] = __uint_as_float(f2tf32(pa[u].z));
            Ad[(kc + 3) * ASTR + m] = __uint_as_float(f2tf32(pa[u].w));
        }
        #pragma unroll
        for (int u = 0; u < BLD4; ++u) {
            const int f = u * 256 + tid;
            if (TRANSB) {
                const int n = f >> 3;
                const int kc = (f & 7) * 4;
                Bd[(kc + 0) * BSTR + n] = __uint_as_float(f2tf32(pb[u].x));
                Bd[(kc + 1) * BSTR + n] = __uint_as_float(f2tf32(pb[u].y));
                Bd[(kc + 2) * BSTR + n] = __uint_as_float(f2tf32(pb[u].z));
                Bd[(kc + 3) * BSTR + n] = __uint_as_float(f2tf32(pb[u].w));
            } else {
                const int k  = f / (BN / 4);
                const int nc = (f % (BN / 4)) * 4;
                float4 cv;
                cv.x = __uint_as_float(f2tf32(pb[u].x));
                cv.y = __uint_as_float(f2tf32(pb[u].y));
                cv.z = __uint_as_float(f2tf32(pb[u].z));
                cv.w = __uint_as_float(f2tf32(pb[u].w));
                *(float4*)(Bd + k * BSTR + nc) = cv;
            }
        }
    };

    // Prologue: tile 0 into buffer 0
    LDG(0);
    STS(0);
    __syncthreads();

    for (int it = 0; it < nk; ++it) {
        const int buf = it & 1;
        if (it + 1 < nk) LDG(it + 1);          // overlap gmem latency with MMAs

        const float* Ab = As + buf * BK * ASTR;
        const float* Bb = Bs + buf * BK * BSTR;
        #pragma unroll
        for (int ks = 0; ks < BK / 8; ++ks) {
            const int kb = ks * 8;
            uint32_t af[MT][4], bf[NT][2];
            #pragma unroll
            for (int mt = 0; mt < MT; ++mt) {
                const float* p = Ab + (kb + t) * ASTR + wm0 + mt * 16 + g;
                af[mt][0] = __float_as_uint(p[0]);
                af[mt][1] = __float_as_uint(p[8]);
                af[mt][2] = __float_as_uint(p[4 * ASTR]);
                af[mt][3] = __float_as_uint(p[4 * ASTR + 8]);
            }
            #pragma unroll
            for (int nt = 0; nt < NT; ++nt) {
                const float* p = Bb + (kb + t) * BSTR + wn0 + nt * 8 + g;
                bf[nt][0] = __float_as_uint(p[0]);
                bf[nt][1] = __float_as_uint(p[4 * BSTR]);
            }
            #pragma unroll
            for (int mt = 0; mt < MT; ++mt)
                #pragma unroll
                for (int nt = 0; nt < NT; ++nt)
                    mma_tf32(acc[mt][nt], af[mt], bf[nt]);
        }

        if (it + 1 < nk) STS((it + 1) & 1);
        __syncthreads();
    }

    // Epilogue: c0,c1 -> row r0 cols (c, c+1); c2,c3 -> row r0+8
    #pragma unroll
    for (int mt = 0; mt < MT; ++mt) {
        const int r0 = m0 + wm0 + mt * 16 + g;
        #pragma unroll
        for (int nt = 0; nt < NT; ++nt) {
            const int c = n0 + wn0 + nt * 8 + 2 * t;
            float2 v0 = make_float2(acc[mt][nt][0], acc[mt][nt][1]);
            float2 v1 = make_float2(acc[mt][nt][2], acc[mt][nt][3]);
            if (bias) {
                const float2 bv = *(const float2*)(bias + c);
                v0.x += bv.x; v0.y += bv.y;
                v1.x += bv.x; v1.y += bv.y;
            }
            if (Res) {
                const float2 r0v = *(const float2*)(Res + (long long)r0 * ldc + c);
                const float2 r1v = *(const float2*)(Res + (long long)(r0 + 8) * ldc + c);
                v0.x += r0v.x; v0.y += r0v.y;
                v1.x += r1v.x; v1.y += r1v.y;
            }
            if (relu) {
                v0.x = fmaxf(v0.x, 0.0f); v0.y = fmaxf(v0.y, 0.0f);
                v1.x = fmaxf(v1.x, 0.0f); v1.y = fmaxf(v1.y, 0.0f);
            }
            *(float2*)(C + (long long)r0 * ldc + c) = v0;
            *(float2*)(C + (long long)(r0 + 8) * ldc + c) = v1;
        }
    }
}

// Dynamic smem sizes per config
#define SMEM_BYTES(BM, BN) (2 * 32 * ((BM + 8) + (BN + 8)) * 4)

// ---------------------------------------------------------------------------
// Launch driver
// ---------------------------------------------------------------------------
extern "C" void kernel_launch(void* const* d_in, const int* in_sizes, int n_in,
                              void* d_out, int out_size)
{
    (void)in_sizes; (void)n_in; (void)out_size;
    const float* x    = (const float*)d_in[0];
    const int*   mask = (const int*)  d_in[1];
    const float* wq = (const float*)d_in[2],  *bq = (const float*)d_in[3];
    const float* wk = (const float*)d_in[4],  *bk = (const float*)d_in[5];
    const float* wv = (const float*)d_in[6],  *bv = (const float*)d_in[7];
    const float* wo = (const float*)d_in[8],  *bo = (const float*)d_in[9];
    const float* w1 = (const float*)d_in[10], *b1 = (const float*)d_in[11];
    const float* w2 = (const float*)d_in[12], *b2 = (const float*)d_in[13];
    const float* ln1a = (const float*)d_in[14], *ln1b = (const float*)d_in[15];
    const float* ln2a = (const float*)d_in[16], *ln2b = (const float*)d_in[17];
    float* out = (float*)d_out;

    float *h, *q, *k, *v, *ctx, *x1, *ff, *sc;
    cudaGetSymbolAddress((void**)&h,   g_h);
    cudaGetSymbolAddress((void**)&q,   g_q);
    cudaGetSymbolAddress((void**)&k,   g_k);
    cudaGetSymbolAddress((void**)&v,   g_v);
    cudaGetSymbolAddress((void**)&ctx, g_ctx);
    cudaGetSymbolAddress((void**)&x1,  g_x1);
    cudaGetSymbolAddress((void**)&ff,  g_ff);
    cudaGetSymbolAddress((void**)&sc,  g_scores);

    const long long SSsq = (long long)SS * SS;
    constexpr int SM1 = SMEM_BYTES(128, 128);   // 69632
    constexpr int SM2 = SMEM_BYTES(128, 64);    // 53248

    // Opt-in >48KB dynamic smem (idempotent; host API calls are legal in capture)
    cudaFuncSetAttribute((const void*)mma_gemm<128,128,64,32,false>,
                         cudaFuncAttributeMaxDynamicSharedMemorySize, SM1);
    cudaFuncSetAttribute((const void*)mma_gemm<128,128,64,32,true>,
                         cudaFuncAttributeMaxDynamicSharedMemorySize, SM1);
    cudaFuncSetAttribute((const void*)mma_gemm<128,64,32,32,false>,
                         cudaFuncAttributeMaxDynamicSharedMemorySize, SM2);

    // 1) LN1: h = ln(x)
    ln_kernel<<<MTOK, 256>>>(x, h, ln1a, ln1b);

    // 2-4) QKV projections: [4096,768] @ [768,768] + bias
    {
        dim3 grid(DMODEL / 128, MTOK / 128, 1);
        mma_gemm<128,128,64,32,false><<<grid, 256, SM1>>>(
            h, wq, bq, nullptr, q, DMODEL, DMODEL, DMODEL, DMODEL,
            0,0, 0,0, 0,0, 1, 0);
        mma_gemm<128,128,64,32,false><<<grid, 256, SM1>>>(
            h, wk, bk, nullptr, k, DMODEL, DMODEL, DMODEL, DMODEL,
            0,0, 0,0, 0,0, 1, 0);
        mma_gemm<128,128,64,32,false><<<grid, 256, SM1>>>(
            h, wv, bv, nullptr, v, DMODEL, DMODEL, DMODEL, DMODEL,
            0,0, 0,0, 0,0, 1, 0);
    }

    // 5) scores[b,h] = Q_bh @ K_bh^T   (M=S, N=S, K=dk)
    {
        dim3 grid(SS / 128, SS / 128, BB * NHEADS);
        mma_gemm<128,128,64,32,true><<<grid, 256, SM1>>>(
            q, k, nullptr, nullptr, sc,
            DK, DMODEL, DMODEL, SS,
            (long long)SS * DMODEL, DK,
            (long long)SS * DMODEL, DK,
            (long long)NHEADS * SSsq, SSsq,
            NHEADS, 0);
    }

    // 6) masked scaled softmax, in place
    softmax_kernel<<<BB * NHEADS * SS, 256>>>(sc, mask);

    // 7) ctx[b,h] = attn_bh @ V_bh   (M=S, N=dk, K=S)
    {
        dim3 grid(DK / 64, SS / 128, BB * NHEADS);
        mma_gemm<128,64,32,32,false><<<grid, 256, SM2>>>(
            sc, v, nullptr, nullptr, ctx,
            SS, SS, DMODEL, DMODEL,
            (long long)NHEADS * SSsq, SSsq,
            (long long)SS * DMODEL, DK,
            (long long)SS * DMODEL, DK,
            NHEADS, 0);
    }

    // 8) x1 = x + ctx @ wo + bo
    {
        dim3 grid(DMODEL / 128, MTOK / 128, 1);
        mma_gemm<128,128,64,32,false><<<grid, 256, SM1>>>(
            ctx, wo, bo, x, x1, DMODEL, DMODEL, DMODEL, DMODEL,
            0,0, 0,0, 0,0, 1, 0);
    }

    // 9) LN2: h = ln(x1)
    ln_kernel<<<MTOK, 256>>>(x1, h, ln2a, ln2b);

    // 10) ff = relu(h @ w1 + b1)
    {
        dim3 grid(DFF / 128, MTOK / 128, 1);
        mma_gemm<128,128,64,32,false><<<grid, 256, SM1>>>(
            h, w1, b1, nullptr, ff, DMODEL, DMODEL, DFF, DFF,
            0,0, 0,0, 0,0, 1, 1);
    }

    // 11) out = x1 + ff @ w2 + b2
    {
        dim3 grid(DMODEL / 128, MTOK / 128, 1);
        mma_gemm<128,128,64,32,false><<<grid, 256, SM1>>>(
            ff, w2, b2, x1, out, DFF, DFF, DMODEL, DMODEL,
            0,0, 0,0, 0,0, 1, 0);
    }
}

// round 10
// speedup vs baseline: 2.8005x; 1.5526x over previous
#include <cuda_runtime.h>
#include <cuda_bf16.h>
#include <cstdint>

// Problem constants
#define DMODEL 768
#define NHEADS 12
#define DK     64
#define DFF    3072
#define BB     2
#define SS     2048
#define MTOK   (BB * SS)
#define L2E    1.44269504088896f

// ---------------------------------------------------------------------------
// Scratch (__device__ globals)
// ---------------------------------------------------------------------------
__device__ float g_h   [MTOK * DMODEL];
__device__ float g_qkv [MTOK * 3 * DMODEL];                // fused q|k|v, ld=2304
__device__ float g_vt  [(long long)BB * NHEADS * DK * SS]; // V^T per head [dk][S]
__device__ float g_ctx [MTOK * DMODEL];
__device__ float g_x1  [MTOK * DMODEL];
__device__ float g_ff  [MTOK * DFF];
__device__ float g_scores[(long long)BB * NHEADS * SS * SS];
__device__ float g_wqkvT[3 * DMODEL * DMODEL];             // [n][k] n=0..2303
__device__ float g_woT [DMODEL * DMODEL];
__device__ float g_w1T [DFF * DMODEL];
__device__ float g_w2T [DMODEL * DFF];
__device__ float g_bqkv[3 * DMODEL];

// ---------------------------------------------------------------------------
// Helpers
// ---------------------------------------------------------------------------
__device__ __forceinline__ uint32_t f2tf32(float f) {
    uint32_t r; asm("cvt.rna.tf32.f32 %0, %1;" : "=r"(r) : "f"(f)); return r;
}
__device__ __forceinline__ float rndtf(float f) { return __uint_as_float(f2tf32(f)); }

__device__ __forceinline__ void ldsm4(uint32_t addr, uint32_t* r) {
    asm volatile("ldmatrix.sync.aligned.m8n8.x4.shared.b16 {%0,%1,%2,%3}, [%4];"
                 : "=r"(r[0]), "=r"(r[1]), "=r"(r[2]), "=r"(r[3]) : "r"(addr));
}
__device__ __forceinline__ void cp16(uint32_t dst, const void* src) {
    asm volatile("cp.async.cg.shared.global [%0], [%1], 16;" :: "r"(dst), "l"(src));
}
__device__ __forceinline__ void mma_tf32(float* c, const uint32_t* a, const uint32_t* b) {
    asm volatile(
        "mma.sync.aligned.m16n8k8.row.col.f32.tf32.tf32.f32 "
        "{%0,%1,%2,%3}, {%4,%5,%6,%7}, {%8,%9}, {%0,%1,%2,%3};"
        : "+f"(c[0]), "+f"(c[1]), "+f"(c[2]), "+f"(c[3])
        : "r"(a[0]), "r"(a[1]), "r"(a[2]), "r"(a[3]), "r"(b[0]), "r"(b[1]));
}

// ---------------------------------------------------------------------------
// LayerNorm (torch-style, unbiased std). Output rounded to tf32 (feeds MMAs).
// ---------------------------------------------------------------------------
__global__ void ln_kernel(const float* __restrict__ x, float* __restrict__ out,
                          const float* __restrict__ alpha, const float* __restrict__ beta)
{
    const int row = blockIdx.x;
    const float* xr = x + (size_t)row * DMODEL;
    float* orow = out + (size_t)row * DMODEL;
    const int tid = threadIdx.x;   // 256

    float v0 = xr[tid], v1 = xr[tid + 256], v2 = xr[tid + 512];
    float s = v0 + v1 + v2;

    __shared__ float red[8];
    #pragma unroll
    for (int o = 16; o; o >>= 1) s += __shfl_xor_sync(0xffffffffu, s, o);
    if ((tid & 31) == 0) red[tid >> 5] = s;
    __syncthreads();
    if (tid < 32) {
        float t = (tid < 8) ? red[tid] : 0.0f;
        #pragma unroll
        for (int o = 4; o; o >>= 1) t += __shfl_xor_sync(0xffffffffu, t, o);
        if (tid == 0) red[0] = t;
    }
    __syncthreads();
    const float mean = red[0] * (1.0f / DMODEL);
    const float d0 = v0 - mean, d1 = v1 - mean, d2 = v2 - mean;
    float q = d0 * d0 + d1 * d1 + d2 * d2;
    __syncthreads();

    #pragma unroll
    for (int o = 16; o; o >>= 1) q += __shfl_xor_sync(0xffffffffu, q, o);
    if ((tid & 31) == 0) red[tid >> 5] = q;
    __syncthreads();
    if (tid < 32) {
        float t = (tid < 8) ? red[tid] : 0.0f;
        #pragma unroll
        for (int o = 4; o; o >>= 1) t += __shfl_xor_sync(0xffffffffu, t, o);
        if (tid == 0) red[0] = t;
    }
    __syncthreads();
    const float var = red[0] * (1.0f / (DMODEL - 1));
    const float inv = alpha[0] / (sqrtf(var) + 1e-6f);
    const float bb  = beta[0];

    orow[tid]       = rndtf(d0 * inv + bb);
    orow[tid + 256] = rndtf(d1 * inv + bb);
    orow[tid + 512] = rndtf(d2 * inv + bb);
}

// ---------------------------------------------------------------------------
// Masked scaled softmax; output rounded to tf32 (feeds AV MMA).
// ---------------------------------------------------------------------------
__global__ void softmax_kernel(float* __restrict__ scores, const int* __restrict__ mask)
{
    const long long row = blockIdx.x;
    const int b = (int)(row / ((long long)NHEADS * SS));
    float* sr = scores + row * (long long)SS;
    const int* mrow = mask + (long long)b * SS;
    const int tid = threadIdx.x;

    float v[8];
    float mx = -3.0e38f;
    #pragma unroll
    for (int i = 0; i < 8; i++) {
        const int c = tid + i * 256;
        float s = sr[c] * 0.125f;
        if (mrow[c] == 0) s = -1e9f;
        v[i] = s;
        mx = fmaxf(mx, s);
    }

    __shared__ float red[8];
    #pragma unroll
    for (int o = 16; o; o >>= 1) mx = fmaxf(mx, __shfl_xor_sync(0xffffffffu, mx, o));
    if ((tid & 31) == 0) red[tid >> 5] = mx;
    __syncthreads();
    if (tid < 32) {
        float t = (tid < 8) ? red[tid] : -3.0e38f;
        #pragma unroll
        for (int o = 4; o; o >>= 1) t = fmaxf(t, __shfl_xor_sync(0xffffffffu, t, o));
        if (tid == 0) red[0] = t;
    }
    __syncthreads();
    mx = red[0];
    __syncthreads();

    float sum = 0.0f;
    #pragma unroll
    for (int i = 0; i < 8; i++) {
        const float p = exp2f((v[i] - mx) * L2E);
        v[i] = p;
        sum += p;
    }
    #pragma unroll
    for (int o = 16; o; o >>= 1) sum += __shfl_xor_sync(0xffffffffu, sum, o);
    if ((tid & 31) == 0) red[tid >> 5] = sum;
    __syncthreads();
    if (tid < 32) {
        float t = (tid < 8) ? red[tid] : 0.0f;
        #pragma unroll
        for (int o = 4; o; o >>= 1) t += __shfl_xor_sync(0xffffffffu, t, o);
        if (tid == 0) red[0] = t;
    }
    __syncthreads();
    const float inv = 1.0f / red[0];
    #pragma unroll
    for (int i = 0; i < 8; i++) sr[tid + i * 256] = rndtf(v[i] * inv);
}

// ---------------------------------------------------------------------------
// Batched tiled transpose: out[c][r] = rndtf(in[r][c]).
// z -> (za=z/ZB, zb=z%ZB) with separate offsets (same scheme as GEMM).
// Requires R,C multiples of 32. Block (32,8).
// ---------------------------------------------------------------------------
__global__ void transpose_kernel(const float* __restrict__ in, float* __restrict__ out,
                                 int lda, int ldo,
                                 long long ioff1, long long ioff2,
                                 long long ooff1, long long ooff2, int ZB)
{
    __shared__ float t[32][33];
    const int z = blockIdx.z, za = z / ZB, zb = z % ZB;
    in  += (long long)za * ioff1 + (long long)zb * ioff2;
    out += (long long)za * ooff1 + (long long)zb * ooff2;
    const int r0 = blockIdx.y * 32, c0 = blockIdx.x * 32;
    #pragma unroll
    for (int i = threadIdx.y; i < 32; i += 8)
        t[i][threadIdx.x] = in[(long long)(r0 + i) * lda + c0 + threadIdx.x];
    __syncthreads();
    #pragma unroll
    for (int i = threadIdx.y; i < 32; i += 8)
        out[(long long)(c0 + i) * ldo + r0 + threadIdx.x] = rndtf(t[threadIdx.x][i]);
}

__global__ void concat_bias_kernel(const float* __restrict__ bq, const float* __restrict__ bk,
                                   const float* __restrict__ bv, float* __restrict__ o)
{
    const int i = blockIdx.x * 256 + threadIdx.x;   // 0..2303
    if (i < 768) o[i] = bq[i];
    else if (i < 1536) o[i] = bk[i - 768];
    else o[i] = bv[i - 1536];
}

// ---------------------------------------------------------------------------
// Tensor-core GEMM, tf32 m16n8k8, cp.async + ldmatrix.
//   C = A @ B^T-layout (+bias) (+Res) (relu?) (round-to-tf32?)
// A: [m][k] row-major (lda). B: [n][k] row-major (ldb). All K%32==0.
// Smem tiles [m][k]/[n][k], stride 36 floats (144B): ldmatrix phases hit 8
// distinct 16B bank groups (144 mod 128 = 16) -> conflict-free.
// 2-stage cp.async pipeline, one __syncthreads per K-iter.
// ---------------------------------------------------------------------------
template<int BM, int BN, int WM, int WN>
__global__ __launch_bounds__(256, 2)
void mma_gemm(const float* __restrict__ A, const float* __restrict__ Bm,
              const float* __restrict__ bias, const float* __restrict__ Res,
              float* __restrict__ C,
              int K, int lda, int ldb, int ldc,
              long long offA1, long long offA2,
              long long offB1, long long offB2,
              long long offC1, long long offC2,
              int ZB, int relu, int rnd)
{
    constexpr int BK  = 32;
    constexpr int STR = 36;                // floats per smem row
    constexpr int MT  = WM / 16;
    constexpr int NT  = WN / 8;
    constexpr int WCOLS = BN / WN;
    constexpr int ACP = BM * 8 / 256;      // cp.async (16B) per thread for A
    constexpr int BCP = BN * 8 / 256;

    extern __shared__ float sm[];
    float* As = sm;                        // [2][BM][STR]
    float* Bs = sm + 2 * BM * STR;         // [2][BN][STR]
    const uint32_t as_u = (uint32_t)__cvta_generic_to_shared(As);
    const uint32_t bs_u = (uint32_t)__cvta_generic_to_shared(Bs);

    const int z  = blockIdx.z;
    const int za = z / ZB, zb = z % ZB;
    A  += (long long)za * offA1 + (long long)zb * offA2;
    Bm += (long long)za * offB1 + (long long)zb * offB2;
    const long long coff = (long long)za * offC1 + (long long)zb * offC2;
    C += coff;
    if (Res) Res += coff;

    const int tid  = threadIdx.x;
    const int warp = tid >> 5, lane = tid & 31;
    const int g = lane >> 2, t4 = lane & 3;
    const int wm0 = (warp / WCOLS) * WM;
    const int wn0 = (warp % WCOLS) * WN;
    const int m0 = blockIdx.y * BM;
    const int n0 = blockIdx.x * BN;

    // ldmatrix per-lane source row/col
    const int j  = lane >> 3, r8 = lane & 7;
    const int lrow = (j & 1) * 8 + r8;
    const int lcol = (j >> 1) * 4;

    float acc[MT][NT][4] = {};
    const int nk = K / BK;

    auto LOAD = [&](int it, int buf) {
        const int k0 = it * BK;
        const uint32_t ab = as_u + (uint32_t)(buf * BM * STR) * 4u;
        #pragma unroll
        for (int u = 0; u < ACP; ++u) {
            const int f = u * 256 + tid;
            const int m = f >> 3;
            const int kc = (f & 7) * 4;
            cp16(ab + (uint32_t)(m * STR + kc) * 4u,
                 A + (long long)(m0 + m) * lda + k0 + kc);
        }
        const uint32_t bb = bs_u + (uint32_t)(buf * BN * STR) * 4u;
        #pragma unroll
        for (int u = 0; u < BCP; ++u) {
            const int f = u * 256 + tid;
            const int n = f >> 3;
            const int kc = (f & 7) * 4;
            cp16(bb + (uint32_t)(n * STR + kc) * 4u,
                 Bm + (long long)(n0 + n) * ldb + k0 + kc);
        }
        asm volatile("cp.async.commit_group;");
    };

    LOAD(0, 0);

    for (int it = 0; it < nk; ++it) {
        const int buf = it & 1;
        asm volatile("cp.async.wait_group 0;");
        __syncthreads();
        if (it + 1 < nk) LOAD(it + 1, buf ^ 1);

        const uint32_t ab = as_u + (uint32_t)(buf * BM * STR) * 4u;
        const uint32_t bb = bs_u + (uint32_t)(buf * BN * STR) * 4u;
        #pragma unroll
        for (int ks = 0; ks < BK / 8; ++ks) {
            uint32_t af[MT][4], bf[NT][2];
            #pragma unroll
            for (int mt = 0; mt < MT; ++mt)
                ldsm4(ab + (uint32_t)((wm0 + mt * 16 + lrow) * STR + ks * 8 + lcol) * 4u,
                      af[mt]);
            #pragma unroll
            for (int p = 0; p < NT / 2; ++p) {
                uint32_t tmp[4];
                ldsm4(bb + (uint32_t)((wn0 + p * 16 + lrow) * STR + ks * 8 + lcol) * 4u,
                      tmp);
                bf[2 * p][0]     = tmp[0]; bf[2 * p][1]     = tmp[2];
                bf[2 * p + 1][0] = tmp[1]; bf[2 * p + 1][1] = tmp[3];
            }
            #pragma unroll
            for (int mt = 0; mt < MT; ++mt)
                #pragma unroll
                for (int nt = 0; nt < NT; ++nt)
                    mma_tf32(acc[mt][nt], af[mt], bf[nt]);
        }
    }

    // Epilogue: c0,c1 -> row r0, cols (c,c+1); c2,c3 -> row r0+8
    #pragma unroll
    for (int mt = 0; mt < MT; ++mt) {
        const int r0 = m0 + wm0 + mt * 16 + g;
        #pragma unroll
        for (int nt = 0; nt < NT; ++nt) {
            const int c = n0 + wn0 + nt * 8 + 2 * t4;
            float2 v0 = make_float2(acc[mt][nt][0], acc[mt][nt][1]);
            float2 v1 = make_float2(acc[mt][nt][2], acc[mt][nt][3]);
            if (bias) {
                const float2 bv = *(const float2*)(bias + c);
                v0.x += bv.x; v0.y += bv.y;
                v1.x += bv.x; v1.y += bv.y;
            }
            if (Res) {
                const float2 a0 = *(const float2*)(Res + (long long)r0 * ldc + c);
                const float2 a1 = *(const float2*)(Res + (long long)(r0 + 8) * ldc + c);
                v0.x += a0.x; v0.y += a0.y;
                v1.x += a1.x; v1.y += a1.y;
            }
            if (relu) {
                v0.x = fmaxf(v0.x, 0.0f); v0.y = fmaxf(v0.y, 0.0f);
                v1.x = fmaxf(v1.x, 0.0f); v1.y = fmaxf(v1.y, 0.0f);
            }
            if (rnd) {
                v0.x = rndtf(v0.x); v0.y = rndtf(v0.y);
                v1.x = rndtf(v1.x); v1.y = rndtf(v1.y);
            }
            *(float2*)(C + (long long)r0 * ldc + c) = v0;
            *(float2*)(C + (long long)(r0 + 8) * ldc + c) = v1;
        }
    }
}

#define SMEM_BYTES(BM, BN) (2 * ((BM) + (BN)) * 36 * 4)

// ---------------------------------------------------------------------------
// Launch driver
// ---------------------------------------------------------------------------
extern "C" void kernel_launch(void* const* d_in, const int* in_sizes, int n_in,
                              void* d_out, int out_size)
{
    (void)in_sizes; (void)n_in; (void)out_size;
    const float* x    = (const float*)d_in[0];
    const int*   mask = (const int*)  d_in[1];
    const float* wq = (const float*)d_in[2],  *bq = (const float*)d_in[3];
    const float* wk = (const float*)d_in[4],  *bk = (const float*)d_in[5];
    const float* wv = (const float*)d_in[6],  *bv = (const float*)d_in[7];
    const float* wo = (const float*)d_in[8],  *bo = (const float*)d_in[9];
    const float* w1 = (const float*)d_in[10], *b1 = (const float*)d_in[11];
    const float* w2 = (const float*)d_in[12], *b2 = (const float*)d_in[13];
    const float* ln1a = (const float*)d_in[14], *ln1b = (const float*)d_in[15];
    const float* ln2a = (const float*)d_in[16], *ln2b = (const float*)d_in[17];
    float* out = (float*)d_out;

    float *h, *qkv, *vt, *ctx, *x1, *ff, *sc, *wqkvT, *woT, *w1T, *w2T, *bqkv;
    cudaGetSymbolAddress((void**)&h,    g_h);
    cudaGetSymbolAddress((void**)&qkv,  g_qkv);
    cudaGetSymbolAddress((void**)&vt,   g_vt);
    cudaGetSymbolAddress((void**)&ctx,  g_ctx);
    cudaGetSymbolAddress((void**)&x1,   g_x1);
    cudaGetSymbolAddress((void**)&ff,   g_ff);
    cudaGetSymbolAddress((void**)&sc,   g_scores);
    cudaGetSymbolAddress((void**)&wqkvT, g_wqkvT);
    cudaGetSymbolAddress((void**)&woT,  g_woT);
    cudaGetSymbolAddress((void**)&w1T,  g_w1T);
    cudaGetSymbolAddress((void**)&w2T,  g_w2T);
    cudaGetSymbolAddress((void**)&bqkv, g_bqkv);

    const long long SSsq = (long long)SS * SS;
    constexpr int SM1 = SMEM_BYTES(128, 128);   // 73728
    constexpr int SM2 = SMEM_BYTES(128, 64);    // 55296

    cudaFuncSetAttribute((const void*)mma_gemm<128,128,64,32>,
                         cudaFuncAttributeMaxDynamicSharedMemorySize, SM1);
    cudaFuncSetAttribute((const void*)mma_gemm<128,64,64,16>,
                         cudaFuncAttributeMaxDynamicSharedMemorySize, SM2);

    // --- Weight transposes into [n][k] layout (rounded to tf32) + bias concat
    {
        dim3 b(32, 8);
        transpose_kernel<<<dim3(24, 24, 1), b>>>(wq, wqkvT,                 768, 768, 0,0, 0,0, 1);
        transpose_kernel<<<dim3(24, 24, 1), b>>>(wk, wqkvT + 768 * 768,     768, 768, 0,0, 0,0, 1);
        transpose_kernel<<<dim3(24, 24, 1), b>>>(wv, wqkvT + 2 * 768 * 768, 768, 768, 0,0, 0,0, 1);
        transpose_kernel<<<dim3(24, 24, 1), b>>>(wo, woT,                   768, 768, 0,0, 0,0, 1);
        transpose_kernel<<<dim3(96, 24, 1), b>>>(w1, w1T,  3072, 768, 0,0, 0,0, 1);
        transpose_kernel<<<dim3(24, 96, 1), b>>>(w2, w2T,  768, 3072, 0,0, 0,0, 1);
        concat_bias_kernel<<<9, 256>>>(bq, bk, bv, bqkv);
    }

    // 1) LN1
    ln_kernel<<<MTOK, 256>>>(x, h, ln1a, ln1b);

    // 2) fused QKV: [4096,768] @ [768,2304] + bqkv -> qkv (ld 2304), rnd
    mma_gemm<128,128,64,32><<<dim3(2304 / 128, MTOK / 128, 1), 256, SM1>>>(
        h, wqkvT, bqkv, nullptr, qkv,
        DMODEL, DMODEL, DMODEL, 3 * DMODEL,
        0,0, 0,0, 0,0, 1, 0, 1);

    // 3) V^T per head: vt[b,h][dk][S]
    transpose_kernel<<<dim3(2, 64, BB * NHEADS), dim3(32, 8)>>>(
        qkv + 2 * DMODEL, vt, 3 * DMODEL, SS,
        (long long)SS * 3 * DMODEL, DK,
        (long long)NHEADS * DK * SS, (long long)DK * SS, NHEADS);

    // 4) scores[b,h] = Q @ K^T  (M=S, N=S, K=64)
    mma_gemm<128,128,64,32><<<dim3(SS / 128, SS / 128, BB * NHEADS), 256, SM1>>>(
        qkv, qkv + DMODEL, nullptr, nullptr, sc,
        DK, 3 * DMODEL, 3 * DMODEL, SS,
        (long long)SS * 3 * DMODEL, DK,
        (long long)SS * 3 * DMODEL, DK,
        (long long)NHEADS * SSsq, SSsq,
        NHEADS, 0, 0);

    // 5) masked scaled softmax (rounds output)
    softmax_kernel<<<BB * NHEADS * SS, 256>>>(sc, mask);

    // 6) ctx[b,h] = attn @ V  (M=S, N=64, K=S), B = vt[n=dk][k=S], rnd
    mma_gemm<128,64,64,16><<<dim3(1, SS / 128, BB * NHEADS), 256, SM2>>>(
        sc, vt, nullptr, nullptr, ctx,
        SS, SS, SS, DMODEL,
        (long long)NHEADS * SSsq, SSsq,
        (long long)NHEADS * DK * SS, (long long)DK * SS,
        (long long)SS * DMODEL, DK,
        NHEADS, 0, 1);

    // 7) x1 = x + ctx @ wo + bo
    mma_gemm<128,64,64,16><<<dim3(DMODEL / 64, MTOK / 128, 1), 256, SM2>>>(
        ctx, woT, bo, x, x1,
        DMODEL, DMODEL, DMODEL, DMODEL,
        0,0, 0,0, 0,0, 1, 0, 0);

    // 8) LN2
    ln_kernel<<<MTOK, 256>>>(x1, h, ln2a, ln2b);

    // 9) ff = relu(h @ w1 + b1), rnd
    mma_gemm<128,128,64,32><<<dim3(DFF / 128, MTOK / 128, 1), 256, SM1>>>(
        h, w1T, b1, nullptr, ff,
        DMODEL, DMODEL, DMODEL, DFF,
        0,0, 0,0, 0,0, 1, 1, 1);

    // 10) out = x1 + ff @ w2 + b2
    mma_gemm<128,64,64,16><<<dim3(DMODEL / 64, MTOK / 128, 1), 256, SM2>>>(
        ff, w2T, b2, x1, out,
        DFF, DFF, DFF, DMODEL,
        0,0, 0,0, 0,0, 1, 0, 0);
}

// round 11
// speedup vs baseline: 3.3028x; 1.1794x over previous
#include <cuda_runtime.h>
#include <cuda_bf16.h>
#include <cstdint>

// Problem constants
#define DMODEL 768
#define NHEADS 12
#define DK     64
#define DFF    3072
#define BB     2
#define SS     2048
#define MTOK   (BB * SS)
#define L2E    1.44269504088896f

// ---------------------------------------------------------------------------
// Scratch (__device__ globals)
// ---------------------------------------------------------------------------
__device__ float g_h   [MTOK * DMODEL];
__device__ float g_qkv [MTOK * 3 * DMODEL];                // fused q|k|v, ld=2304
__device__ float g_vt  [(long long)BB * NHEADS * DK * SS]; // V^T per head [dk][S]
__device__ float g_ctx [MTOK * DMODEL];
__device__ float g_x1  [MTOK * DMODEL];
__device__ float g_ff  [MTOK * DFF];
__device__ float g_wqkvT[3 * DMODEL * DMODEL];             // [n][k]
__device__ float g_woT [DMODEL * DMODEL];
__device__ float g_w1T [DFF * DMODEL];
__device__ float g_w2T [DMODEL * DFF];
__device__ float g_bqkv[3 * DMODEL];

// ---------------------------------------------------------------------------
// Helpers
// ---------------------------------------------------------------------------
__device__ __forceinline__ uint32_t f2tf32(float f) {
    uint32_t r; asm("cvt.rna.tf32.f32 %0, %1;" : "=r"(r) : "f"(f)); return r;
}
__device__ __forceinline__ float rndtf(float f) { return __uint_as_float(f2tf32(f)); }

__device__ __forceinline__ void ldsm4(uint32_t addr, uint32_t* r) {
    asm volatile("ldmatrix.sync.aligned.m8n8.x4.shared.b16 {%0,%1,%2,%3}, [%4];"
                 : "=r"(r[0]), "=r"(r[1]), "=r"(r[2]), "=r"(r[3]) : "r"(addr));
}
__device__ __forceinline__ void cp16(uint32_t dst, const void* src) {
    asm volatile("cp.async.cg.shared.global [%0], [%1], 16;" :: "r"(dst), "l"(src));
}
__device__ __forceinline__ void mma_tf32(float* c, const uint32_t* a, const uint32_t* b) {
    asm volatile(
        "mma.sync.aligned.m16n8k8.row.col.f32.tf32.tf32.f32 "
        "{%0,%1,%2,%3}, {%4,%5,%6,%7}, {%8,%9}, {%0,%1,%2,%3};"
        : "+f"(c[0]), "+f"(c[1]), "+f"(c[2]), "+f"(c[3])
        : "r"(a[0]), "r"(a[1]), "r"(a[2]), "r"(a[3]), "r"(b[0]), "r"(b[1]));
}

// ---------------------------------------------------------------------------
// LayerNorm (torch-style, unbiased std). Output rounded to tf32.
// ---------------------------------------------------------------------------
__global__ void ln_kernel(const float* __restrict__ x, float* __restrict__ out,
                          const float* __restrict__ alpha, const float* __restrict__ beta)
{
    const int row = blockIdx.x;
    const float* xr = x + (size_t)row * DMODEL;
    float* orow = out + (size_t)row * DMODEL;
    const int tid = threadIdx.x;   // 256

    float v0 = xr[tid], v1 = xr[tid + 256], v2 = xr[tid + 512];
    float s = v0 + v1 + v2;

    __shared__ float red[8];
    #pragma unroll
    for (int o = 16; o; o >>= 1) s += __shfl_xor_sync(0xffffffffu, s, o);
    if ((tid & 31) == 0) red[tid >> 5] = s;
    __syncthreads();
    if (tid < 32) {
        float t = (tid < 8) ? red[tid] : 0.0f;
        #pragma unroll
        for (int o = 4; o; o >>= 1) t += __shfl_xor_sync(0xffffffffu, t, o);
        if (tid == 0) red[0] = t;
    }
    __syncthreads();
    const float mean = red[0] * (1.0f / DMODEL);
    const float d0 = v0 - mean, d1 = v1 - mean, d2 = v2 - mean;
    float q = d0 * d0 + d1 * d1 + d2 * d2;
    __syncthreads();

    #pragma unroll
    for (int o = 16; o; o >>= 1) q += __shfl_xor_sync(0xffffffffu, q, o);
    if ((tid & 31) == 0) red[tid >> 5] = q;
    __syncthreads();
    if (tid < 32) {
        float t = (tid < 8) ? red[tid] : 0.0f;
        #pragma unroll
        for (int o = 4; o; o >>= 1) t += __shfl_xor_sync(0xffffffffu, t, o);
        if (tid == 0) red[0] = t;
    }
    __syncthreads();
    const float var = red[0] * (1.0f / (DMODEL - 1));
    const float inv = alpha[0] / (sqrtf(var) + 1e-6f);
    const float bb  = beta[0];

    orow[tid]       = rndtf(d0 * inv + bb);
    orow[tid + 256] = rndtf(d1 * inv + bb);
    orow[tid + 512] = rndtf(d2 * inv + bb);
}

// ---------------------------------------------------------------------------
// Batched tiled transpose: out[c][r] = rndtf(in[r][c]).
// ---------------------------------------------------------------------------
__global__ void transpose_kernel(const float* __restrict__ in, float* __restrict__ out,
                                 int lda, int ldo,
                                 long long ioff1, long long ioff2,
                                 long long ooff1, long long ooff2, int ZB)
{
    __shared__ float t[32][33];
    const int z = blockIdx.z, za = z / ZB, zb = z % ZB;
    in  += (long long)za * ioff1 + (long long)zb * ioff2;
    out += (long long)za * ooff1 + (long long)zb * ooff2;
    const int r0 = blockIdx.y * 32, c0 = blockIdx.x * 32;
    #pragma unroll
    for (int i = threadIdx.y; i < 32; i += 8)
        t[i][threadIdx.x] = in[(long long)(r0 + i) * lda + c0 + threadIdx.x];
    __syncthreads();
    #pragma unroll
    for (int i = threadIdx.y; i < 32; i += 8)
        out[(long long)(c0 + i) * ldo + r0 + threadIdx.x] = rndtf(t[threadIdx.x][i]);
}

__global__ void concat_bias_kernel(const float* __restrict__ bq, const float* __restrict__ bk,
                                   const float* __restrict__ bv, float* __restrict__ o)
{
    const int i = blockIdx.x * 256 + threadIdx.x;   // 0..2303
    if (i < 768) o[i] = bq[i];
    else if (i < 1536) o[i] = bk[i - 768];
    else o[i] = bv[i - 1536];
}

// ---------------------------------------------------------------------------
// Tensor-core GEMM, tf32 m16n8k8, cp.async + ldmatrix (unchanged from R10).
// ---------------------------------------------------------------------------
template<int BM, int BN, int WM, int WN>
__global__ __launch_bounds__(256, 2)
void mma_gemm(const float* __restrict__ A, const float* __restrict__ Bm,
              const float* __restrict__ bias, const float* __restrict__ Res,
              float* __restrict__ C,
              int K, int lda, int ldb, int ldc,
              long long offA1, long long offA2,
              long long offB1, long long offB2,
              long long offC1, long long offC2,
              int ZB, int relu, int rnd)
{
    constexpr int BK  = 32;
    constexpr int STR = 36;
    constexpr int MT  = WM / 16;
    constexpr int NT  = WN / 8;
    constexpr int WCOLS = BN / WN;
    constexpr int ACP = BM * 8 / 256;
    constexpr int BCP = BN * 8 / 256;

    extern __shared__ float sm[];
    float* As = sm;
    float* Bs = sm + 2 * BM * STR;
    const uint32_t as_u = (uint32_t)__cvta_generic_to_shared(As);
    const uint32_t bs_u = (uint32_t)__cvta_generic_to_shared(Bs);

    const int z  = blockIdx.z;
    const int za = z / ZB, zb = z % ZB;
    A  += (long long)za * offA1 + (long long)zb * offA2;
    Bm += (long long)za * offB1 + (long long)zb * offB2;
    const long long coff = (long long)za * offC1 + (long long)zb * offC2;
    C += coff;
    if (Res) Res += coff;

    const int tid  = threadIdx.x;
    const int warp = tid >> 5, lane = tid & 31;
    const int g = lane >> 2, t4 = lane & 3;
    const int wm0 = (warp / WCOLS) * WM;
    const int wn0 = (warp % WCOLS) * WN;
    const int m0 = blockIdx.y * BM;
    const int n0 = blockIdx.x * BN;

    const int j  = lane >> 3, r8 = lane & 7;
    const int lrow = (j & 1) * 8 + r8;
    const int lcol = (j >> 1) * 4;

    float acc[MT][NT][4] = {};
    const int nk = K / BK;

    auto LOAD = [&](int it, int buf) {
        const int k0 = it * BK;
        const uint32_t ab = as_u + (uint32_t)(buf * BM * STR) * 4u;
        #pragma unroll
        for (int u = 0; u < ACP; ++u) {
            const int f = u * 256 + tid;
            const int m = f >> 3;
            const int kc = (f & 7) * 4;
            cp16(ab + (uint32_t)(m * STR + kc) * 4u,
                 A + (long long)(m0 + m) * lda + k0 + kc);
        }
        const uint32_t bb = bs_u + (uint32_t)(buf * BN * STR) * 4u;
        #pragma unroll
        for (int u = 0; u < BCP; ++u) {
            const int f = u * 256 + tid;
            const int n = f >> 3;
            const int kc = (f & 7) * 4;
            cp16(bb + (uint32_t)(n * STR + kc) * 4u,
                 Bm + (long long)(n0 + n) * ldb + k0 + kc);
        }
        asm volatile("cp.async.commit_group;");
    };

    LOAD(0, 0);

    for (int it = 0; it < nk; ++it) {
        const int buf = it & 1;
        asm volatile("cp.async.wait_group 0;");
        __syncthreads();
        if (it + 1 < nk) LOAD(it + 1, buf ^ 1);

        const uint32_t ab = as_u + (uint32_t)(buf * BM * STR) * 4u;
        const uint32_t bb = bs_u + (uint32_t)(buf * BN * STR) * 4u;
        #pragma unroll
        for (int ks = 0; ks < BK / 8; ++ks) {
            uint32_t af[MT][4], bf[NT][2];
            #pragma unroll
            for (int mt = 0; mt < MT; ++mt)
                ldsm4(ab + (uint32_t)((wm0 + mt * 16 + lrow) * STR + ks * 8 + lcol) * 4u,
                      af[mt]);
            #pragma unroll
            for (int p = 0; p < NT / 2; ++p) {
                uint32_t tmp[4];
                ldsm4(bb + (uint32_t)((wn0 + p * 16 + lrow) * STR + ks * 8 + lcol) * 4u,
                      tmp);
                bf[2 * p][0]     = tmp[0]; bf[2 * p][1]     = tmp[2];
                bf[2 * p + 1][0] = tmp[1]; bf[2 * p + 1][1] = tmp[3];
            }
            #pragma unroll
            for (int mt = 0; mt < MT; ++mt)
                #pragma unroll
                for (int nt = 0; nt < NT; ++nt)
                    mma_tf32(acc[mt][nt], af[mt], bf[nt]);
        }
    }

    #pragma unroll
    for (int mt = 0; mt < MT; ++mt) {
        const int r0 = m0 + wm0 + mt * 16 + g;
        #pragma unroll
        for (int nt = 0; nt < NT; ++nt) {
            const int c = n0 + wn0 + nt * 8 + 2 * t4;
            float2 v0 = make_float2(acc[mt][nt][0], acc[mt][nt][1]);
            float2 v1 = make_float2(acc[mt][nt][2], acc[mt][nt][3]);
            if (bias) {
                const float2 bv = *(const float2*)(bias + c);
                v0.x += bv.x; v0.y += bv.y;
                v1.x += bv.x; v1.y += bv.y;
            }
            if (Res) {
                const float2 a0 = *(const float2*)(Res + (long long)r0 * ldc + c);
                const float2 a1 = *(const float2*)(Res + (long long)(r0 + 8) * ldc + c);
                v0.x += a0.x; v0.y += a0.y;
                v1.x += a1.x; v1.y += a1.y;
            }
            if (relu) {
                v0.x = fmaxf(v0.x, 0.0f); v0.y = fmaxf(v0.y, 0.0f);
                v1.x = fmaxf(v1.x, 0.0f); v1.y = fmaxf(v1.y, 0.0f);
            }
            if (rnd) {
                v0.x = rndtf(v0.x); v0.y = rndtf(v0.y);
                v1.x = rndtf(v1.x); v1.y = rndtf(v1.y);
            }
            *(float2*)(C + (long long)r0 * ldc + c) = v0;
            *(float2*)(C + (long long)(r0 + 8) * ldc + c) = v1;
        }
    }
}

#define SMEM_BYTES(BM, BN) (2 * ((BM) + (BN)) * 36 * 4)

// ---------------------------------------------------------------------------
// Fused flash attention, tf32 MMA, online softmax.
//   grid: (S/128, B*H). 8 warps; warp w owns Q rows w*16..w*16+15.
// Per 64-row KV step: S = Q@K^T; mask+scale+online softmax (quad shfl reduce);
// P (tf32) -> smem -> ldmatrix; O += P@V^T-tile. Double-buffered cp.async K/V.
// Smem tiles stride 68 floats (272B ≡ 16 mod 128 -> ldmatrix conflict-free).
// ---------------------------------------------------------------------------
#define BQ   128
#define BKV  64
#define FSTR 68

__global__ __launch_bounds__(256, 1)
void flash_kernel(const float* __restrict__ qkv, const float* __restrict__ vt,
                  const int* __restrict__ mask, float* __restrict__ ctx)
{
    extern __shared__ float sm[];
    float* Qs = sm;                              // [128][68]
    float* Ks = Qs + BQ * FSTR;                  // [2][64][68]
    float* Vs = Ks + 2 * BKV * FSTR;             // [2][64][68]
    float* Ps = Vs + 2 * BKV * FSTR;             // [128][68]
    int*   Ms = (int*)(Ps + BQ * FSTR);          // [2][64]
    const uint32_t qs_u = (uint32_t)__cvta_generic_to_shared(Qs);
    const uint32_t ks_u = (uint32_t)__cvta_generic_to_shared(Ks);
    const uint32_t vs_u = (uint32_t)__cvta_generic_to_shared(Vs);
    const uint32_t ps_u = (uint32_t)__cvta_generic_to_shared(Ps);
    const uint32_t ms_u = (uint32_t)__cvta_generic_to_shared(Ms);

    const int qb = blockIdx.x, bh = blockIdx.y;
    const int b = bh / NHEADS, hh = bh % NHEADS;
    const long long tok0 = (long long)b * SS + qb * BQ;
    const float* Qg = qkv + tok0 * (3 * DMODEL) + hh * DK;
    const float* Kg = qkv + (long long)b * SS * (3 * DMODEL) + DMODEL + hh * DK;
    const float* Vg = vt + (long long)bh * DK * SS;        // [dk][S], ld=SS
    const int*   mg = mask + (long long)b * SS;

    const int tid  = threadIdx.x;
    const int warp = tid >> 5, lane = tid & 31;
    const int g = lane >> 2, t4 = lane & 3;
    const int row0 = warp * 16;
    const int j  = lane >> 3, r8 = lane & 7;
    const int lrow = (j & 1) * 8 + r8;
    const int lcol = (j >> 1) * 4;

    // Q tile: 128 rows x 16 chunks = 2048 cp / 256 thr = 8 each
    #pragma unroll
    for (int u = 0; u < 8; ++u) {
        const int f = u * 256 + tid;
        const int r = f >> 4, kc = (f & 15) * 4;
        cp16(qs_u + (uint32_t)(r * FSTR + kc) * 4u, Qg + (long long)r * (3 * DMODEL) + kc);
    }

    auto LOAD = [&](int s, int buf) {
        const int kv0 = s * BKV;
        const uint32_t kb = ks_u + (uint32_t)(buf * BKV * FSTR) * 4u;
        #pragma unroll
        for (int u = 0; u < 4; ++u) {                       // K: 64x16 chunks
            const int f = u * 256 + tid;
            const int r = f >> 4, kc = (f & 15) * 4;
            cp16(kb + (uint32_t)(r * FSTR + kc) * 4u,
                 Kg + (long long)(kv0 + r) * (3 * DMODEL) + kc);
        }
        const uint32_t vb = vs_u + (uint32_t)(buf * BKV * FSTR) * 4u;
        #pragma unroll
        for (int u = 0; u < 4; ++u) {                       // V^T: 64x16 chunks
            const int f = u * 256 + tid;
            const int r = f >> 4, kc = (f & 15) * 4;
            cp16(vb + (uint32_t)(r * FSTR + kc) * 4u,
                 Vg + (long long)r * SS + kv0 + kc);
        }
        if (tid < 16)                                       // mask: 64 ints
            cp16(ms_u + (uint32_t)(buf * BKV + tid * 4) * 4u, mg + kv0 + tid * 4);
        asm volatile("cp.async.commit_group;");
    };

    LOAD(0, 0);

    float m_a = -3.0e38f, m_b = -3.0e38f, l_a = 0.0f, l_b = 0.0f;
    float oacc[8][4] = {};

    const int NSTEP = SS / BKV;   // 32
    for (int s = 0; s < NSTEP; ++s) {
        const int buf = s & 1;
        asm volatile("cp.async.wait_group 0;");
        __syncthreads();
        if (s + 1 < NSTEP) LOAD(s + 1, buf ^ 1);

        const uint32_t kb = ks_u + (uint32_t)(buf * BKV * FSTR) * 4u;
        const uint32_t vb = vs_u + (uint32_t)(buf * BKV * FSTR) * 4u;

        // --- S = Q @ K^T : sacc[nt][4], warp rows row0..row0+15, cols 0..63
        float sacc[8][4] = {};
        #pragma unroll
        for (int ks8 = 0; ks8 < 8; ++ks8) {
            uint32_t af[4], bf[8][2];
            ldsm4(qs_u + (uint32_t)((row0 + lrow) * FSTR + ks8 * 8 + lcol) * 4u, af);
            #pragma unroll
            for (int p = 0; p < 4; ++p) {
                uint32_t tmp[4];
                ldsm4(kb + (uint32_t)((p * 16 + lrow) * FSTR + ks8 * 8 + lcol) * 4u, tmp);
                bf[2 * p][0]     = tmp[0]; bf[2 * p][1]     = tmp[2];
                bf[2 * p + 1][0] = tmp[1]; bf[2 * p + 1][1] = tmp[3];
            }
            #pragma unroll
            for (int nt = 0; nt < 8; ++nt) mma_tf32(sacc[nt], af, bf[nt]);
        }

        // --- mask + scale + row max (rows g and g+8 of this warp's block)
        const int* mbuf = Ms + buf * BKV;
        float rmax_a = -3.0e38f, rmax_b = -3.0e38f;
        #pragma unroll
        for (int nt = 0; nt < 8; ++nt) {
            #pragma unroll
            for (int e = 0; e < 2; ++e) {
                const int c = nt * 8 + 2 * t4 + e;
                const bool live = (mbuf[c] != 0);
                float v0 = sacc[nt][e] * 0.125f;     if (!live) v0 = -1e9f;
                float v1 = sacc[nt][2 + e] * 0.125f; if (!live) v1 = -1e9f;
                sacc[nt][e] = v0; sacc[nt][2 + e] = v1;
                rmax_a = fmaxf(rmax_a, v0); rmax_b = fmaxf(rmax_b, v1);
            }
        }
        rmax_a = fmaxf(rmax_a, __shfl_xor_sync(0xffffffffu, rmax_a, 1));
        rmax_a = fmaxf(rmax_a, __shfl_xor_sync(0xffffffffu, rmax_a, 2));
        rmax_b = fmaxf(rmax_b, __shfl_xor_sync(0xffffffffu, rmax_b, 1));
        rmax_b = fmaxf(rmax_b, __shfl_xor_sync(0xffffffffu, rmax_b, 2));

        const float mna = fmaxf(m_a, rmax_a), mnb = fmaxf(m_b, rmax_b);
        const float ca = exp2f((m_a - mna) * L2E), cb = exp2f((m_b - mnb) * L2E);
        m_a = mna; m_b = mnb;

        // --- P = exp(s - m), sum, store tf32 P to smem
        float sum_a = 0.0f, sum_b = 0.0f;
        #pragma unroll
        for (int nt = 0; nt < 8; ++nt) {
            const float p0 = exp2f((sacc[nt][0] - mna) * L2E);
            const float p1 = exp2f((sacc[nt][1] - mna) * L2E);
            const float p2 = exp2f((sacc[nt][2] - mnb) * L2E);
            const float p3 = exp2f((sacc[nt][3] - mnb) * L2E);
            sum_a += p0 + p1; sum_b += p2 + p3;
            const int c = nt * 8 + 2 * t4;
            *(float2*)(Ps + (row0 + g) * FSTR + c)     = make_float2(rndtf(p0), rndtf(p1));
            *(float2*)(Ps + (row0 + g + 8) * FSTR + c) = make_float2(rndtf(p2), rndtf(p3));
        }
        sum_a += __shfl_xor_sync(0xffffffffu, sum_a, 1);
        sum_a += __shfl_xor_sync(0xffffffffu, sum_a, 2);
        sum_b += __shfl_xor_sync(0xffffffffu, sum_b, 1);
        sum_b += __shfl_xor_sync(0xffffffffu, sum_b, 2);
        l_a = l_a * ca + sum_a;
        l_b = l_b * cb + sum_b;

        #pragma unroll
        for (int nt = 0; nt < 8; ++nt) {
            oacc[nt][0] *= ca; oacc[nt][1] *= ca;
            oacc[nt][2] *= cb; oacc[nt][3] *= cb;
        }
        __syncwarp();

        // --- O += P @ V : A from Ps (warp-private rows), B from Vs [dk][kv]
        #pragma unroll
        for (int ks8 = 0; ks8 < 8; ++ks8) {
            uint32_t af[4], bf[8][2];
            ldsm4(ps_u + (uint32_t)((row0 + lrow) * FSTR + ks8 * 8 + lcol) * 4u, af);
            #pragma unroll
            for (int p = 0; p < 4; ++p) {
                uint32_t tmp[4];
                ldsm4(vb + (uint32_t)((p * 16 + lrow) * FSTR + ks8 * 8 + lcol) * 4u, tmp);
                bf[2 * p][0]     = tmp[0]; bf[2 * p][1]     = tmp[2];
                bf[2 * p + 1][0] = tmp[1]; bf[2 * p + 1][1] = tmp[3];
            }
            #pragma unroll
            for (int nt = 0; nt < 8; ++nt) mma_tf32(oacc[nt], af, bf[nt]);
        }
    }

    // --- epilogue: normalize and write ctx (tf32-rounded; feeds O-proj MMA)
    const float ia = 1.0f / l_a, ib = 1.0f / l_b;
    float* crow_a = ctx + (tok0 + row0 + g) * DMODEL + hh * DK;
    float* crow_b = ctx + (tok0 + row0 + g + 8) * DMODEL + hh * DK;
    #pragma unroll
    for (int nt = 0; nt < 8; ++nt) {
        const int c = nt * 8 + 2 * t4;
        *(float2*)(crow_a + c) = make_float2(rndtf(oacc[nt][0] * ia), rndtf(oacc[nt][1] * ia));
        *(float2*)(crow_b + c) = make_float2(rndtf(oacc[nt][2] * ib), rndtf(oacc[nt][3] * ib));
    }
}

#define FLASH_SMEM ((BQ * FSTR + 2 * BKV * FSTR + 2 * BKV * FSTR + BQ * FSTR) * 4 + 2 * BKV * 4)

// ---------------------------------------------------------------------------
// Launch driver
// ---------------------------------------------------------------------------
extern "C" void kernel_launch(void* const* d_in, const int* in_sizes, int n_in,
                              void* d_out, int out_size)
{
    (void)in_sizes; (void)n_in; (void)out_size;
    const float* x    = (const float*)d_in[0];
    const int*   mask = (const int*)  d_in[1];
    const float* wq = (const float*)d_in[2],  *bq = (const float*)d_in[3];
    const float* wk = (const float*)d_in[4],  *bk = (const float*)d_in[5];
    const float* wv = (const float*)d_in[6],  *bv = (const float*)d_in[7];
    const float* wo = (const float*)d_in[8],  *bo = (const float*)d_in[9];
    const float* w1 = (const float*)d_in[10], *b1 = (const float*)d_in[11];
    const float* w2 = (const float*)d_in[12], *b2 = (const float*)d_in[13];
    const float* ln1a = (const float*)d_in[14], *ln1b = (const float*)d_in[15];
    const float* ln2a = (const float*)d_in[16], *ln2b = (const float*)d_in[17];
    float* out = (float*)d_out;

    float *h, *qkv, *vt, *ctx, *x1, *ff, *wqkvT, *woT, *w1T, *w2T, *bqkv;
    cudaGetSymbolAddress((void**)&h,     g_h);
    cudaGetSymbolAddress((void**)&qkv,   g_qkv);
    cudaGetSymbolAddress((void**)&vt,    g_vt);
    cudaGetSymbolAddress((void**)&ctx,   g_ctx);
    cudaGetSymbolAddress((void**)&x1,    g_x1);
    cudaGetSymbolAddress((void**)&ff,    g_ff);
    cudaGetSymbolAddress((void**)&wqkvT, g_wqkvT);
    cudaGetSymbolAddress((void**)&woT,   g_woT);
    cudaGetSymbolAddress((void**)&w1T,   g_w1T);
    cudaGetSymbolAddress((void**)&w2T,   g_w2T);
    cudaGetSymbolAddress((void**)&bqkv,  g_bqkv);

    constexpr int SM1 = SMEM_BYTES(128, 128);   // 73728
    constexpr int SM2 = SMEM_BYTES(128, 64);    // 55296

    cudaFuncSetAttribute((const void*)mma_gemm<128,128,64,32>,
                         cudaFuncAttributeMaxDynamicSharedMemorySize, SM1);
    cudaFuncSetAttribute((const void*)mma_gemm<128,64,64,16>,
                         cudaFuncAttributeMaxDynamicSharedMemorySize, SM2);
    cudaFuncSetAttribute((const void*)flash_kernel,
                         cudaFuncAttributeMaxDynamicSharedMemorySize, FLASH_SMEM);

    // Weight transposes into [n][k] (tf32-rounded) + bias concat
    {
        dim3 b(32, 8);
        transpose_kernel<<<dim3(24, 24, 1), b>>>(wq, wqkvT,                 768, 768, 0,0, 0,0, 1);
        transpose_kernel<<<dim3(24, 24, 1), b>>>(wk, wqkvT + 768 * 768,     768, 768, 0,0, 0,0, 1);
        transpose_kernel<<<dim3(24, 24, 1), b>>>(wv, wqkvT + 2 * 768 * 768, 768, 768, 0,0, 0,0, 1);
        transpose_kernel<<<dim3(24, 24, 1), b>>>(wo, woT,                   768, 768, 0,0, 0,0, 1);
        transpose_kernel<<<dim3(96, 24, 1), b>>>(w1, w1T,  3072, 768, 0,0, 0,0, 1);
        transpose_kernel<<<dim3(24, 96, 1), b>>>(w2, w2T,  768, 3072, 0,0, 0,0, 1);
        concat_bias_kernel<<<9, 256>>>(bq, bk, bv, bqkv);
    }

    // 1) LN1
    ln_kernel<<<MTOK, 256>>>(x, h, ln1a, ln1b);

    // 2) fused QKV: [4096,768] @ [768,2304] + bqkv -> qkv (ld 2304), tf32-rnd
    mma_gemm<128,128,64,32><<<dim3(2304 / 128, MTOK / 128, 1), 256, SM1>>>(
        h, wqkvT, bqkv, nullptr, qkv,
        DMODEL, DMODEL, DMODEL, 3 * DMODEL,
        0,0, 0,0, 0,0, 1, 0, 1);

    // 3) V^T per head: vt[b,h][dk][S]
    transpose_kernel<<<dim3(2, 64, BB * NHEADS), dim3(32, 8)>>>(
        qkv + 2 * DMODEL, vt, 3 * DMODEL, SS,
        (long long)SS * 3 * DMODEL, DK,
        (long long)NHEADS * DK * SS, (long long)DK * SS, NHEADS);

    // 4) fused flash attention -> ctx
    flash_kernel<<<dim3(SS / BQ, BB * NHEADS), 256, FLASH_SMEM>>>(qkv, vt, mask, ctx);

    // 5) x1 = x + ctx @ wo + bo
    mma_gemm<128,64,64,16><<<dim3(DMODEL / 64, MTOK / 128, 1), 256, SM2>>>(
        ctx, woT, bo, x, x1,
        DMODEL, DMODEL, DMODEL, DMODEL,
        0,0, 0,0, 0,0, 1, 0, 0);

    // 6) LN2
    ln_kernel<<<MTOK, 256>>>(x1, h, ln2a, ln2b);

    // 7) ff = relu(h @ w1 + b1), tf32-rnd
    mma_gemm<128,128,64,32><<<dim3(DFF / 128, MTOK / 128, 1), 256, SM1>>>(
        h, w1T, b1, nullptr, ff,
        DMODEL, DMODEL, DMODEL, DFF,
        0,0, 0,0, 0,0, 1, 1, 1);

    // 8) out = x1 + ff @ w2 + b2
    mma_gemm<128,64,64,16><<<dim3(DMODEL / 64, MTOK / 128, 1), 256, SM2>>>(
        ff, w2T, b2, x1, out,
        DFF, DFF, DFF, DMODEL,
        0,0, 0,0, 0,0, 1, 0, 0);
}

// round 12
// speedup vs baseline: 3.3370x; 1.0103x over previous
#include <cuda_runtime.h>
#include <cuda_bf16.h>
#include <cstdint>

// Problem constants
#define DMODEL 768
#define NHEADS 12
#define DK     64
#define DFF    3072
#define BB     2
#define SS     2048
#define MTOK   (BB * SS)
#define L2E    1.44269504088896f

// ---------------------------------------------------------------------------
// Scratch (__device__ globals)
// ---------------------------------------------------------------------------
__device__ float g_h   [MTOK * DMODEL];
__device__ float g_qkv [MTOK * 3 * DMODEL];                // fused q|k|v, ld=2304
__device__ float g_vt  [(long long)BB * NHEADS * DK * SS]; // V^T per head [dk][S]
__device__ float g_ctx [MTOK * DMODEL];
__device__ float g_x1  [MTOK * DMODEL];
__device__ float g_ff  [MTOK * DFF];
__device__ float g_wqkvT[3 * DMODEL * DMODEL];             // [n][k]
__device__ float g_woT [DMODEL * DMODEL];
__device__ float g_w1T [DFF * DMODEL];
__device__ float g_w2T [DMODEL * DFF];
__device__ float g_bqkv[3 * DMODEL];

// ---------------------------------------------------------------------------
// Helpers
// ---------------------------------------------------------------------------
__device__ __forceinline__ uint32_t f2tf32(float f) {
    uint32_t r; asm("cvt.rna.tf32.f32 %0, %1;" : "=r"(r) : "f"(f)); return r;
}
__device__ __forceinline__ float rndtf(float f) { return __uint_as_float(f2tf32(f)); }
__device__ __forceinline__ float fex2(float x) {           // single MUFU.EX2
    float y; asm("ex2.approx.ftz.f32 %0, %1;" : "=f"(y) : "f"(x)); return y;
}

__device__ __forceinline__ void ldsm4(uint32_t addr, uint32_t* r) {
    asm volatile("ldmatrix.sync.aligned.m8n8.x4.shared.b16 {%0,%1,%2,%3}, [%4];"
                 : "=r"(r[0]), "=r"(r[1]), "=r"(r[2]), "=r"(r[3]) : "r"(addr));
}
__device__ __forceinline__ void cp16(uint32_t dst, const void* src) {
    asm volatile("cp.async.cg.shared.global [%0], [%1], 16;" :: "r"(dst), "l"(src));
}
__device__ __forceinline__ void mma_tf32(float* c, const uint32_t* a, const uint32_t* b) {
    asm volatile(
        "mma.sync.aligned.m16n8k8.row.col.f32.tf32.tf32.f32 "
        "{%0,%1,%2,%3}, {%4,%5,%6,%7}, {%8,%9}, {%0,%1,%2,%3};"
        : "+f"(c[0]), "+f"(c[1]), "+f"(c[2]), "+f"(c[3])
        : "r"(a[0]), "r"(a[1]), "r"(a[2]), "r"(a[3]), "r"(b[0]), "r"(b[1]));
}

// ---------------------------------------------------------------------------
// LayerNorm (torch-style, unbiased std). Output rounded to tf32.
// ---------------------------------------------------------------------------
__global__ void ln_kernel(const float* __restrict__ x, float* __restrict__ out,
                          const float* __restrict__ alpha, const float* __restrict__ beta)
{
    const int row = blockIdx.x;
    const float* xr = x + (size_t)row * DMODEL;
    float* orow = out + (size_t)row * DMODEL;
    const int tid = threadIdx.x;   // 256

    float v0 = xr[tid], v1 = xr[tid + 256], v2 = xr[tid + 512];
    float s = v0 + v1 + v2;

    __shared__ float red[8];
    #pragma unroll
    for (int o = 16; o; o >>= 1) s += __shfl_xor_sync(0xffffffffu, s, o);
    if ((tid & 31) == 0) red[tid >> 5] = s;
    __syncthreads();
    if (tid < 32) {
        float t = (tid < 8) ? red[tid] : 0.0f;
        #pragma unroll
        for (int o = 4; o; o >>= 1) t += __shfl_xor_sync(0xffffffffu, t, o);
        if (tid == 0) red[0] = t;
    }
    __syncthreads();
    const float mean = red[0] * (1.0f / DMODEL);
    const float d0 = v0 - mean, d1 = v1 - mean, d2 = v2 - mean;
    float q = d0 * d0 + d1 * d1 + d2 * d2;
    __syncthreads();

    #pragma unroll
    for (int o = 16; o; o >>= 1) q += __shfl_xor_sync(0xffffffffu, q, o);
    if ((tid & 31) == 0) red[tid >> 5] = q;
    __syncthreads();
    if (tid < 32) {
        float t = (tid < 8) ? red[tid] : 0.0f;
        #pragma unroll
        for (int o = 4; o; o >>= 1) t += __shfl_xor_sync(0xffffffffu, t, o);
        if (tid == 0) red[0] = t;
    }
    __syncthreads();
    const float var = red[0] * (1.0f / (DMODEL - 1));
    const float inv = alpha[0] / (sqrtf(var) + 1e-6f);
    const float bb  = beta[0];

    orow[tid]       = rndtf(d0 * inv + bb);
    orow[tid + 256] = rndtf(d1 * inv + bb);
    orow[tid + 512] = rndtf(d2 * inv + bb);
}

// ---------------------------------------------------------------------------
// Batched tiled transpose: out[c][r] = rndtf(in[r][c]).
// ---------------------------------------------------------------------------
__global__ void transpose_kernel(const float* __restrict__ in, float* __restrict__ out,
                                 int lda, int ldo,
                                 long long ioff1, long long ioff2,
                                 long long ooff1, long long ooff2, int ZB)
{
    __shared__ float t[32][33];
    const int z = blockIdx.z, za = z / ZB, zb = z % ZB;
    in  += (long long)za * ioff1 + (long long)zb * ioff2;
    out += (long long)za * ooff1 + (long long)zb * ooff2;
    const int r0 = blockIdx.y * 32, c0 = blockIdx.x * 32;
    #pragma unroll
    for (int i = threadIdx.y; i < 32; i += 8)
        t[i][threadIdx.x] = in[(long long)(r0 + i) * lda + c0 + threadIdx.x];
    __syncthreads();
    #pragma unroll
    for (int i = threadIdx.y; i < 32; i += 8)
        out[(long long)(c0 + i) * ldo + r0 + threadIdx.x] = rndtf(t[threadIdx.x][i]);
}

__global__ void concat_bias_kernel(const float* __restrict__ bq, const float* __restrict__ bk,
                                   const float* __restrict__ bv, float* __restrict__ o)
{
    const int i = blockIdx.x * 256 + threadIdx.x;   // 0..2303
    if (i < 768) o[i] = bq[i];
    else if (i < 1536) o[i] = bk[i - 768];
    else o[i] = bv[i - 1536];
}

// ---------------------------------------------------------------------------
// Tensor-core GEMM, tf32 m16n8k8, cp.async + ldmatrix, 3-stage pipeline.
//   C = A @ B^T-layout (+bias) (+Res) (relu?) (round-to-tf32?)
// A: [m][k] (lda), B: [n][k] (ldb). K % 32 == 0, K >= 64.
// ---------------------------------------------------------------------------
template<int BM, int BN, int WM, int WN>
__global__ __launch_bounds__(256, 2)
void mma_gemm(const float* __restrict__ A, const float* __restrict__ Bm,
              const float* __restrict__ bias, const float* __restrict__ Res,
              float* __restrict__ C,
              int K, int lda, int ldb, int ldc,
              long long offA1, long long offA2,
              long long offB1, long long offB2,
              long long offC1, long long offC2,
              int ZB, int relu, int rnd)
{
    constexpr int BK  = 32;
    constexpr int STR = 36;
    constexpr int MT  = WM / 16;
    constexpr int NT  = WN / 8;
    constexpr int WCOLS = BN / WN;
    constexpr int ACP = BM * 8 / 256;
    constexpr int BCP = BN * 8 / 256;

    extern __shared__ float sm[];
    float* As = sm;                        // [3][BM][STR]
    float* Bs = sm + 3 * BM * STR;         // [3][BN][STR]
    const uint32_t as_u = (uint32_t)__cvta_generic_to_shared(As);
    const uint32_t bs_u = (uint32_t)__cvta_generic_to_shared(Bs);

    const int z  = blockIdx.z;
    const int za = z / ZB, zb = z % ZB;
    A  += (long long)za * offA1 + (long long)zb * offA2;
    Bm += (long long)za * offB1 + (long long)zb * offB2;
    const long long coff = (long long)za * offC1 + (long long)zb * offC2;
    C += coff;
    if (Res) Res += coff;

    const int tid  = threadIdx.x;
    const int warp = tid >> 5, lane = tid & 31;
    const int g = lane >> 2, t4 = lane & 3;
    const int wm0 = (warp / WCOLS) * WM;
    const int wn0 = (warp % WCOLS) * WN;
    const int m0 = blockIdx.y * BM;
    const int n0 = blockIdx.x * BN;

    const int j  = lane >> 3, r8 = lane & 7;
    const int lrow = (j & 1) * 8 + r8;
    const int lcol = (j >> 1) * 4;

    float acc[MT][NT][4] = {};
    const int nk = K / BK;

    auto LOAD = [&](int it, int buf) {
        const int k0 = it * BK;
        const uint32_t ab = as_u + (uint32_t)(buf * BM * STR) * 4u;
        #pragma unroll
        for (int u = 0; u < ACP; ++u) {
            const int f = u * 256 + tid;
            const int m = f >> 3;
            const int kc = (f & 7) * 4;
            cp16(ab + (uint32_t)(m * STR + kc) * 4u,
                 A + (long long)(m0 + m) * lda + k0 + kc);
        }
        const uint32_t bb = bs_u + (uint32_t)(buf * BN * STR) * 4u;
        #pragma unroll
        for (int u = 0; u < BCP; ++u) {
            const int f = u * 256 + tid;
            const int n = f >> 3;
            const int kc = (f & 7) * 4;
            cp16(bb + (uint32_t)(n * STR + kc) * 4u,
                 Bm + (long long)(n0 + n) * ldb + k0 + kc);
        }
        asm volatile("cp.async.commit_group;");
    };

    LOAD(0, 0);
    if (nk > 1) LOAD(1, 1);

    for (int it = 0; it < nk; ++it) {
        const int buf = it % 3;
        if (it + 1 < nk) asm volatile("cp.async.wait_group 1;");
        else             asm volatile("cp.async.wait_group 0;");
        __syncthreads();
        if (it + 2 < nk) LOAD(it + 2, (it + 2) % 3);

        const uint32_t ab = as_u + (uint32_t)(buf * BM * STR) * 4u;
        const uint32_t bb = bs_u + (uint32_t)(buf * BN * STR) * 4u;
        #pragma unroll
        for (int ks = 0; ks < BK / 8; ++ks) {
            uint32_t af[MT][4], bf[NT][2];
            #pragma unroll
            for (int mt = 0; mt < MT; ++mt)
                ldsm4(ab + (uint32_t)((wm0 + mt * 16 + lrow) * STR + ks * 8 + lcol) * 4u,
                      af[mt]);
            #pragma unroll
            for (int p = 0; p < NT / 2; ++p) {
                uint32_t tmp[4];
                ldsm4(bb + (uint32_t)((wn0 + p * 16 + lrow) * STR + ks * 8 + lcol) * 4u,
                      tmp);
                bf[2 * p][0]     = tmp[0]; bf[2 * p][1]     = tmp[2];
                bf[2 * p + 1][0] = tmp[1]; bf[2 * p + 1][1] = tmp[3];
            }
            #pragma unroll
            for (int mt = 0; mt < MT; ++mt)
                #pragma unroll
                for (int nt = 0; nt < NT; ++nt)
                    mma_tf32(acc[mt][nt], af[mt], bf[nt]);
        }
    }

    #pragma unroll
    for (int mt = 0; mt < MT; ++mt) {
        const int r0 = m0 + wm0 + mt * 16 + g;
        #pragma unroll
        for (int nt = 0; nt < NT; ++nt) {
            const int c = n0 + wn0 + nt * 8 + 2 * t4;
            float2 v0 = make_float2(acc[mt][nt][0], acc[mt][nt][1]);
            float2 v1 = make_float2(acc[mt][nt][2], acc[mt][nt][3]);
            if (bias) {
                const float2 bv = *(const float2*)(bias + c);
                v0.x += bv.x; v0.y += bv.y;
                v1.x += bv.x; v1.y += bv.y;
            }
            if (Res) {
                const float2 a0 = *(const float2*)(Res + (long long)r0 * ldc + c);
                const float2 a1 = *(const float2*)(Res + (long long)(r0 + 8) * ldc + c);
                v0.x += a0.x; v0.y += a0.y;
                v1.x += a1.x; v1.y += a1.y;
            }
            if (relu) {
                v0.x = fmaxf(v0.x, 0.0f); v0.y = fmaxf(v0.y, 0.0f);
                v1.x = fmaxf(v1.x, 0.0f); v1.y = fmaxf(v1.y, 0.0f);
            }
            if (rnd) {
                v0.x = rndtf(v0.x); v0.y = rndtf(v0.y);
                v1.x = rndtf(v1.x); v1.y = rndtf(v1.y);
            }
            *(float2*)(C + (long long)r0 * ldc + c) = v0;
            *(float2*)(C + (long long)(r0 + 8) * ldc + c) = v1;
        }
    }
}

#define SMEM_BYTES(BM, BN) (3 * ((BM) + (BN)) * 36 * 4)

// ---------------------------------------------------------------------------
// Fused flash attention, tf32 MMA, online softmax.
//   grid: (S/128, B*H). 8 warps; warp w owns Q rows w*16..w*16+15.
// Q fragments hoisted to registers (loop-invariant). ex2.approx for exps.
// ---------------------------------------------------------------------------
#define BQ   128
#define BKV  64
#define FSTR 68

__global__ __launch_bounds__(256, 1)
void flash_kernel(const float* __restrict__ qkv, const float* __restrict__ vt,
                  const int* __restrict__ mask, float* __restrict__ ctx)
{
    extern __shared__ float sm[];
    float* Qs = sm;                              // [128][68]
    float* Ks = Qs + BQ * FSTR;                  // [2][64][68]
    float* Vs = Ks + 2 * BKV * FSTR;             // [2][64][68]
    float* Ps = Vs + 2 * BKV * FSTR;             // [128][68]
    int*   Ms = (int*)(Ps + BQ * FSTR);          // [2][64]
    const uint32_t qs_u = (uint32_t)__cvta_generic_to_shared(Qs);
    const uint32_t ks_u = (uint32_t)__cvta_generic_to_shared(Ks);
    const uint32_t vs_u = (uint32_t)__cvta_generic_to_shared(Vs);
    const uint32_t ps_u = (uint32_t)__cvta_generic_to_shared(Ps);
    const uint32_t ms_u = (uint32_t)__cvta_generic_to_shared(Ms);

    const int qb = blockIdx.x, bh = blockIdx.y;
    const int b = bh / NHEADS, hh = bh % NHEADS;
    const long long tok0 = (long long)b * SS + qb * BQ;
    const float* Qg = qkv + tok0 * (3 * DMODEL) + hh * DK;
    const float* Kg = qkv + (long long)b * SS * (3 * DMODEL) + DMODEL + hh * DK;
    const float* Vg = vt + (long long)bh * DK * SS;        // [dk][S], ld=SS
    const int*   mg = mask + (long long)b * SS;

    const int tid  = threadIdx.x;
    const int warp = tid >> 5, lane = tid & 31;
    const int g = lane >> 2, t4 = lane & 3;
    const int row0 = warp * 16;
    const int j  = lane >> 3, r8 = lane & 7;
    const int lrow = (j & 1) * 8 + r8;
    const int lcol = (j >> 1) * 4;

    // Q tile -> smem (group 0)
    #pragma unroll
    for (int u = 0; u < 8; ++u) {
        const int f = u * 256 + tid;
        const int r = f >> 4, kc = (f & 15) * 4;
        cp16(qs_u + (uint32_t)(r * FSTR + kc) * 4u, Qg + (long long)r * (3 * DMODEL) + kc);
    }
    asm volatile("cp.async.commit_group;");

    auto LOAD = [&](int s, int buf) {
        const int kv0 = s * BKV;
        const uint32_t kb = ks_u + (uint32_t)(buf * BKV * FSTR) * 4u;
        #pragma unroll
        for (int u = 0; u < 4; ++u) {                       // K: 64x16 chunks
            const int f = u * 256 + tid;
            const int r = f >> 4, kc = (f & 15) * 4;
            cp16(kb + (uint32_t)(r * FSTR + kc) * 4u,
                 Kg + (long long)(kv0 + r) * (3 * DMODEL) + kc);
        }
        const uint32_t vb = vs_u + (uint32_t)(buf * BKV * FSTR) * 4u;
        #pragma unroll
        for (int u = 0; u < 4; ++u) {                       // V^T: 64x16 chunks
            const int f = u * 256 + tid;
            const int r = f >> 4, kc = (f & 15) * 4;
            cp16(vb + (uint32_t)(r * FSTR + kc) * 4u,
                 Vg + (long long)r * SS + kv0 + kc);
        }
        if (tid < 16)                                       // mask: 64 ints
            cp16(ms_u + (uint32_t)(buf * BKV + tid * 4) * 4u, mg + kv0 + tid * 4);
        asm volatile("cp.async.commit_group;");
    };

    LOAD(0, 0);

    // Hoist Q fragments: wait for Q group (leave LOAD(0) in flight)
    asm volatile("cp.async.wait_group 1;");
    __syncthreads();
    uint32_t qf[8][4];
    #pragma unroll
    for (int ks8 = 0; ks8 < 8; ++ks8)
        ldsm4(qs_u + (uint32_t)((row0 + lrow) * FSTR + ks8 * 8 + lcol) * 4u, qf[ks8]);

    float m_a = -3.0e38f, m_b = -3.0e38f, l_a = 0.0f, l_b = 0.0f;
    float oacc[8][4] = {};

    const int NSTEP = SS / BKV;   // 32
    for (int s = 0; s < NSTEP; ++s) {
        const int buf = s & 1;
        asm volatile("cp.async.wait_group 0;");
        __syncthreads();
        if (s + 1 < NSTEP) LOAD(s + 1, buf ^ 1);

        const uint32_t kb = ks_u + (uint32_t)(buf * BKV * FSTR) * 4u;
        const uint32_t vb = vs_u + (uint32_t)(buf * BKV * FSTR) * 4u;

        // --- S = Q @ K^T
        float sacc[8][4] = {};
        #pragma unroll
        for (int ks8 = 0; ks8 < 8; ++ks8) {
            uint32_t bf[8][2];
            #pragma unroll
            for (int p = 0; p < 4; ++p) {
                uint32_t tmp[4];
                ldsm4(kb + (uint32_t)((p * 16 + lrow) * FSTR + ks8 * 8 + lcol) * 4u, tmp);
                bf[2 * p][0]     = tmp[0]; bf[2 * p][1]     = tmp[2];
                bf[2 * p + 1][0] = tmp[1]; bf[2 * p + 1][1] = tmp[3];
            }
            #pragma unroll
            for (int nt = 0; nt < 8; ++nt) mma_tf32(sacc[nt], qf[ks8], bf[nt]);
        }

        // --- mask + scale + row max
        const int* mbuf = Ms + buf * BKV;
        float rmax_a = -3.0e38f, rmax_b = -3.0e38f;
        #pragma unroll
        for (int nt = 0; nt < 8; ++nt) {
            #pragma unroll
            for (int e = 0; e < 2; ++e) {
                const int c = nt * 8 + 2 * t4 + e;
                const bool live = (mbuf[c] != 0);
                float v0 = sacc[nt][e] * 0.125f;     if (!live) v0 = -1e9f;
                float v1 = sacc[nt][2 + e] * 0.125f; if (!live) v1 = -1e9f;
                sacc[nt][e] = v0; sacc[nt][2 + e] = v1;
                rmax_a = fmaxf(rmax_a, v0); rmax_b = fmaxf(rmax_b, v1);
            }
        }
        rmax_a = fmaxf(rmax_a, __shfl_xor_sync(0xffffffffu, rmax_a, 1));
        rmax_a = fmaxf(rmax_a, __shfl_xor_sync(0xffffffffu, rmax_a, 2));
        rmax_b = fmaxf(rmax_b, __shfl_xor_sync(0xffffffffu, rmax_b, 1));
        rmax_b = fmaxf(rmax_b, __shfl_xor_sync(0xffffffffu, rmax_b, 2));

        const float mna = fmaxf(m_a, rmax_a), mnb = fmaxf(m_b, rmax_b);
        const float ca = fex2((m_a - mna) * L2E), cb = fex2((m_b - mnb) * L2E);
        m_a = mna; m_b = mnb;

        // --- P = exp(s - m), sum, store tf32 P to smem
        float sum_a = 0.0f, sum_b = 0.0f;
        #pragma unroll
        for (int nt = 0; nt < 8; ++nt) {
            const float p0 = fex2((sacc[nt][0] - mna) * L2E);
            const float p1 = fex2((sacc[nt][1] - mna) * L2E);
            const float p2 = fex2((sacc[nt][2] - mnb) * L2E);
            const float p3 = fex2((sacc[nt][3] - mnb) * L2E);
            sum_a += p0 + p1; sum_b += p2 + p3;
            const int c = nt * 8 + 2 * t4;
            *(float2*)(Ps + (row0 + g) * FSTR + c)     = make_float2(rndtf(p0), rndtf(p1));
            *(float2*)(Ps + (row0 + g + 8) * FSTR + c) = make_float2(rndtf(p2), rndtf(p3));
        }
        sum_a += __shfl_xor_sync(0xffffffffu, sum_a, 1);
        sum_a += __shfl_xor_sync(0xffffffffu, sum_a, 2);
        sum_b += __shfl_xor_sync(0xffffffffu, sum_b, 1);
        sum_b += __shfl_xor_sync(0xffffffffu, sum_b, 2);
        l_a = l_a * ca + sum_a;
        l_b = l_b * cb + sum_b;

        #pragma unroll
        for (int nt = 0; nt < 8; ++nt) {
            oacc[nt][0] *= ca; oacc[nt][1] *= ca;
            oacc[nt][2] *= cb; oacc[nt][3] *= cb;
        }
        __syncwarp();

        // --- O += P @ V
        #pragma unroll
        for (int ks8 = 0; ks8 < 8; ++ks8) {
            uint32_t af[4], bf[8][2];
            ldsm4(ps_u + (uint32_t)((row0 + lrow) * FSTR + ks8 * 8 + lcol) * 4u, af);
            #pragma unroll
            for (int p = 0; p < 4; ++p) {
                uint32_t tmp[4];
                ldsm4(vb + (uint32_t)((p * 16 + lrow) * FSTR + ks8 * 8 + lcol) * 4u, tmp);
                bf[2 * p][0]     = tmp[0]; bf[2 * p][1]     = tmp[2];
                bf[2 * p + 1][0] = tmp[1]; bf[2 * p + 1][1] = tmp[3];
            }
            #pragma unroll
            for (int nt = 0; nt < 8; ++nt) mma_tf32(oacc[nt], af, bf[nt]);
        }
    }

    // --- epilogue
    const float ia = 1.0f / l_a, ib = 1.0f / l_b;
    float* crow_a = ctx + (tok0 + row0 + g) * DMODEL + hh * DK;
    float* crow_b = ctx + (tok0 + row0 + g + 8) * DMODEL + hh * DK;
    #pragma unroll
    for (int nt = 0; nt < 8; ++nt) {
        const int c = nt * 8 + 2 * t4;
        *(float2*)(crow_a + c) = make_float2(rndtf(oacc[nt][0] * ia), rndtf(oacc[nt][1] * ia));
        *(float2*)(crow_b + c) = make_float2(rndtf(oacc[nt][2] * ib), rndtf(oacc[nt][3] * ib));
    }
}

#define FLASH_SMEM ((BQ * FSTR + 2 * BKV * FSTR + 2 * BKV * FSTR + BQ * FSTR) * 4 + 2 * BKV * 4)

// ---------------------------------------------------------------------------
// Launch driver
// ---------------------------------------------------------------------------
extern "C" void kernel_launch(void* const* d_in, const int* in_sizes, int n_in,
                              void* d_out, int out_size)
{
    (void)in_sizes; (void)n_in; (void)out_size;
    const float* x    = (const float*)d_in[0];
    const int*   mask = (const int*)  d_in[1];
    const float* wq = (const float*)d_in[2],  *bq = (const float*)d_in[3];
    const float* wk = (const float*)d_in[4],  *bk = (const float*)d_in[5];
    const float* wv = (const float*)d_in[6],  *bv = (const float*)d_in[7];
    const float* wo = (const float*)d_in[8],  *bo = (const float*)d_in[9];
    const float* w1 = (const float*)d_in[10], *b1 = (const float*)d_in[11];
    const float* w2 = (const float*)d_in[12], *b2 = (const float*)d_in[13];
    const float* ln1a = (const float*)d_in[14], *ln1b = (const float*)d_in[15];
    const float* ln2a = (const float*)d_in[16], *ln2b = (const float*)d_in[17];
    float* out = (float*)d_out;

    float *h, *qkv, *vt, *ctx, *x1, *ff, *wqkvT, *woT, *w1T, *w2T, *bqkv;
    cudaGetSymbolAddress((void**)&h,     g_h);
    cudaGetSymbolAddress((void**)&qkv,   g_qkv);
    cudaGetSymbolAddress((void**)&vt,    g_vt);
    cudaGetSymbolAddress((void**)&ctx,   g_ctx);
    cudaGetSymbolAddress((void**)&x1,    g_x1);
    cudaGetSymbolAddress((void**)&ff,    g_ff);
    cudaGetSymbolAddress((void**)&wqkvT, g_wqkvT);
    cudaGetSymbolAddress((void**)&woT,   g_woT);
    cudaGetSymbolAddress((void**)&w1T,   g_w1T);
    cudaGetSymbolAddress((void**)&w2T,   g_w2T);
    cudaGetSymbolAddress((void**)&bqkv,  g_bqkv);

    constexpr int SM1 = SMEM_BYTES(128, 128);   // 110592
    constexpr int SM2 = SMEM_BYTES(128, 64);    // 82944

    cudaFuncSetAttribute((const void*)mma_gemm<128,128,64,32>,
                         cudaFuncAttributeMaxDynamicSharedMemorySize, SM1);
    cudaFuncSetAttribute((const void*)mma_gemm<128,64,64,16>,
                         cudaFuncAttributeMaxDynamicSharedMemorySize, SM2);
    cudaFuncSetAttribute((const void*)flash_kernel,
                         cudaFuncAttributeMaxDynamicSharedMemorySize, FLASH_SMEM);

    // Weight transposes into [n][k] (tf32-rounded) + bias concat
    {
        dim3 b(32, 8);
        transpose_kernel<<<dim3(24, 24, 1), b>>>(wq, wqkvT,                 768, 768, 0,0, 0,0, 1);
        transpose_kernel<<<dim3(24, 24, 1), b>>>(wk, wqkvT + 768 * 768,     768, 768, 0,0, 0,0, 1);
        transpose_kernel<<<dim3(24, 24, 1), b>>>(wv, wqkvT + 2 * 768 * 768, 768, 768, 0,0, 0,0, 1);
        transpose_kernel<<<dim3(24, 24, 1), b>>>(wo, woT,                   768, 768, 0,0, 0,0, 1);
        transpose_kernel<<<dim3(96, 24, 1), b>>>(w1, w1T,  3072, 768, 0,0, 0,0, 1);
        transpose_kernel<<<dim3(24, 96, 1), b>>>(w2, w2T,  768, 3072, 0,0, 0,0, 1);
        concat_bias_kernel<<<9, 256>>>(bq, bk, bv, bqkv);
    }

    // 1) LN1
    ln_kernel<<<MTOK, 256>>>(x, h, ln1a, ln1b);

    // 2) fused QKV
    mma_gemm<128,128,64,32><<<dim3(2304 / 128, MTOK / 128, 1), 256, SM1>>>(
        h, wqkvT, bqkv, nullptr, qkv,
        DMODEL, DMODEL, DMODEL, 3 * DMODEL,
        0,0, 0,0, 0,0, 1, 0, 1);

    // 3) V^T per head
    transpose_kernel<<<dim3(2, 64, BB * NHEADS), dim3(32, 8)>>>(
        qkv + 2 * DMODEL, vt, 3 * DMODEL, SS,
        (long long)SS * 3 * DMODEL, DK,
        (long long)NHEADS * DK * SS, (long long)DK * SS, NHEADS);

    // 4) fused flash attention -> ctx
    flash_kernel<<<dim3(SS / BQ, BB * NHEADS), 256, FLASH_SMEM>>>(qkv, vt, mask, ctx);

    // 5) x1 = x + ctx @ wo + bo
    mma_gemm<128,64,64,16><<<dim3(DMODEL / 64, MTOK / 128, 1), 256, SM2>>>(
        ctx, woT, bo, x, x1,
        DMODEL, DMODEL, DMODEL, DMODEL,
        0,0, 0,0, 0,0, 1, 0, 0);

    // 6) LN2
    ln_kernel<<<MTOK, 256>>>(x1, h, ln2a, ln2b);

    // 7) ff = relu(h @ w1 + b1)
    mma_gemm<128,128,64,32><<<dim3(DFF / 128, MTOK / 128, 1), 256, SM1>>>(
        h, w1T, b1, nullptr, ff,
        DMODEL, DMODEL, DMODEL, DFF,
        0,0, 0,0, 0,0, 1, 1, 1);

    // 8) out = x1 + ff @ w2 + b2
    mma_gemm<128,64,64,16><<<dim3(DMODEL / 64, MTOK / 128, 1), 256, SM2>>>(
        ff, w2T, b2, x1, out,
        DFF, DFF, DFF, DMODEL,
        0,0, 0,0, 0,0, 1, 0, 0);
}

// round 13
// speedup vs baseline: 3.3392x; 1.0007x over previous
#include <cuda_runtime.h>
#include <cuda_bf16.h>
#include <cstdint>

// Problem constants
#define DMODEL 768
#define NHEADS 12
#define DK     64
#define DFF    3072
#define BB     2
#define SS     2048
#define MTOK   (BB * SS)
#define L2E    1.44269504088896f

// ---------------------------------------------------------------------------
// Scratch (__device__ globals)
// ---------------------------------------------------------------------------
__device__ float g_h   [MTOK * DMODEL];
__device__ float g_qkv [MTOK * 3 * DMODEL];                // fused q|k|v, ld=2304
__device__ float g_vt  [(long long)BB * NHEADS * DK * SS]; // V^T per head [dk][S]
__device__ float g_ctx [MTOK * DMODEL];
__device__ float g_x1  [MTOK * DMODEL];
__device__ float g_ff  [MTOK * DFF];
__device__ float g_wqkvT[3 * DMODEL * DMODEL];             // [n][k]
__device__ float g_woT [DMODEL * DMODEL];
__device__ float g_w1T [DFF * DMODEL];
__device__ float g_w2T [DMODEL * DFF];
__device__ float g_bqkv[3 * DMODEL];

// ---------------------------------------------------------------------------
// Helpers
// ---------------------------------------------------------------------------
__device__ __forceinline__ uint32_t f2tf32(float f) {
    uint32_t r; asm("cvt.rna.tf32.f32 %0, %1;" : "=r"(r) : "f"(f)); return r;
}
__device__ __forceinline__ float rndtf(float f) { return __uint_as_float(f2tf32(f)); }
__device__ __forceinline__ float fex2(float x) {
    float y; asm("ex2.approx.ftz.f32 %0, %1;" : "=f"(y) : "f"(x)); return y;
}

__device__ __forceinline__ void ldsm4(uint32_t addr, uint32_t* r) {
    asm volatile("ldmatrix.sync.aligned.m8n8.x4.shared.b16 {%0,%1,%2,%3}, [%4];"
                 : "=r"(r[0]), "=r"(r[1]), "=r"(r[2]), "=r"(r[3]) : "r"(addr));
}
__device__ __forceinline__ void cp16(uint32_t dst, const void* src) {
    asm volatile("cp.async.cg.shared.global [%0], [%1], 16;" :: "r"(dst), "l"(src));
}
__device__ __forceinline__ void mma_tf32(float* c, const uint32_t* a, const uint32_t* b) {
    asm volatile(
        "mma.sync.aligned.m16n8k8.row.col.f32.tf32.tf32.f32 "
        "{%0,%1,%2,%3}, {%4,%5,%6,%7}, {%8,%9}, {%0,%1,%2,%3};"
        : "+f"(c[0]), "+f"(c[1]), "+f"(c[2]), "+f"(c[3])
        : "r"(a[0]), "r"(a[1]), "r"(a[2]), "r"(a[3]), "r"(b[0]), "r"(b[1]));
}

// ---------------------------------------------------------------------------
// LayerNorm (torch-style, unbiased std). Output rounded to tf32.
// ---------------------------------------------------------------------------
__global__ void ln_kernel(const float* __restrict__ x, float* __restrict__ out,
                          const float* __restrict__ alpha, const float* __restrict__ beta)
{
    const int row = blockIdx.x;
    const float* xr = x + (size_t)row * DMODEL;
    float* orow = out + (size_t)row * DMODEL;
    const int tid = threadIdx.x;   // 256

    float v0 = xr[tid], v1 = xr[tid + 256], v2 = xr[tid + 512];
    float s = v0 + v1 + v2;

    __shared__ float red[8];
    #pragma unroll
    for (int o = 16; o; o >>= 1) s += __shfl_xor_sync(0xffffffffu, s, o);
    if ((tid & 31) == 0) red[tid >> 5] = s;
    __syncthreads();
    if (tid < 32) {
        float t = (tid < 8) ? red[tid] : 0.0f;
        #pragma unroll
        for (int o = 4; o; o >>= 1) t += __shfl_xor_sync(0xffffffffu, t, o);
        if (tid == 0) red[0] = t;
    }
    __syncthreads();
    const float mean = red[0] * (1.0f / DMODEL);
    const float d0 = v0 - mean, d1 = v1 - mean, d2 = v2 - mean;
    float q = d0 * d0 + d1 * d1 + d2 * d2;
    __syncthreads();

    #pragma unroll
    for (int o = 16; o; o >>= 1) q += __shfl_xor_sync(0xffffffffu, q, o);
    if ((tid & 31) == 0) red[tid >> 5] = q;
    __syncthreads();
    if (tid < 32) {
        float t = (tid < 8) ? red[tid] : 0.0f;
        #pragma unroll
        for (int o = 4; o; o >>= 1) t += __shfl_xor_sync(0xffffffffu, t, o);
        if (tid == 0) red[0] = t;
    }
    __syncthreads();
    const float var = red[0] * (1.0f / (DMODEL - 1));
    const float inv = alpha[0] / (sqrtf(var) + 1e-6f);
    const float bb  = beta[0];

    orow[tid]       = rndtf(d0 * inv + bb);
    orow[tid + 256] = rndtf(d1 * inv + bb);
    orow[tid + 512] = rndtf(d2 * inv + bb);
}

// ---------------------------------------------------------------------------
// Fused weight preprocessing: one launch transposes all 6 weights into [n][k]
// layout (tf32-rounded) and concatenates qkv biases (last block).
// Block ids: [0,576) wq | [576,1152) wk | [1152,1728) wv | [1728,2304) wo |
//            [2304,4608) w1 | [4608,6912) w2 | 6912 bias concat.
// ---------------------------------------------------------------------------
__global__ void transpose_all_kernel(
    const float* __restrict__ wq, const float* __restrict__ wk,
    const float* __restrict__ wv, const float* __restrict__ wo,
    const float* __restrict__ w1, const float* __restrict__ w2,
    float* __restrict__ wqkvT, float* __restrict__ woT,
    float* __restrict__ w1T,   float* __restrict__ w2T,
    const float* __restrict__ bq, const float* __restrict__ bk,
    const float* __restrict__ bv, float* __restrict__ bqkv)
{
    int id = blockIdx.x;
    const int tx = threadIdx.x, ty = threadIdx.y;     // (32, 8)

    if (id == 6912) {                                  // bias concat
        for (int i = ty * 32 + tx; i < 3 * DMODEL; i += 256) {
            float v;
            if (i < 768) v = bq[i];
            else if (i < 1536) v = bk[i - 768];
            else v = bv[i - 1536];
            bqkv[i] = v;
        }
        return;
    }

    const float* in; float* out; int R, C;
    if      (id < 576)  {            in = wq; out = wqkvT;                 R = 768;  C = 768; }
    else if (id < 1152) { id -= 576; in = wk; out = wqkvT + 768 * 768;     R = 768;  C = 768; }
    else if (id < 1728) { id -= 1152; in = wv; out = wqkvT + 2 * 768 * 768; R = 768; C = 768; }
    else if (id < 2304) { id -= 1728; in = wo; out = woT;                  R = 768;  C = 768; }
    else if (id < 4608) { id -= 2304; in = w1; out = w1T;                  R = 768;  C = 3072; }
    else                { id -= 4608; in = w2; out = w2T;                  R = 3072; C = 768; }

    const int cb = C / 32;
    const int r0 = (id / cb) * 32, c0 = (id % cb) * 32;

    __shared__ float t[32][33];
    #pragma unroll
    for (int i = ty; i < 32; i += 8)
        t[i][tx] = in[(long long)(r0 + i) * C + c0 + tx];
    __syncthreads();
    #pragma unroll
    for (int i = ty; i < 32; i += 8)
        out[(long long)(c0 + i) * R + r0 + tx] = rndtf(t[tx][i]);
}

// ---------------------------------------------------------------------------
// Batched tiled transpose (used for per-head V^T): out[c][r] = rndtf(in[r][c]).
// ---------------------------------------------------------------------------
__global__ void transpose_kernel(const float* __restrict__ in, float* __restrict__ out,
                                 int lda, int ldo,
                                 long long ioff1, long long ioff2,
                                 long long ooff1, long long ooff2, int ZB)
{
    __shared__ float t[32][33];
    const int z = blockIdx.z, za = z / ZB, zb = z % ZB;
    in  += (long long)za * ioff1 + (long long)zb * ioff2;
    out += (long long)za * ooff1 + (long long)zb * ooff2;
    const int r0 = blockIdx.y * 32, c0 = blockIdx.x * 32;
    #pragma unroll
    for (int i = threadIdx.y; i < 32; i += 8)
        t[i][threadIdx.x] = in[(long long)(r0 + i) * lda + c0 + threadIdx.x];
    __syncthreads();
    #pragma unroll
    for (int i = threadIdx.y; i < 32; i += 8)
        out[(long long)(c0 + i) * ldo + r0 + threadIdx.x] = rndtf(t[threadIdx.x][i]);
}

// ---------------------------------------------------------------------------
// Tensor-core GEMM, tf32 m16n8k8, cp.async + ldmatrix, 3-stage pipeline.
//   C = A @ B^T-layout (+bias) (+Res) (relu?) (round-to-tf32?)
// A: [m][k] (lda), B: [n][k] (ldb). K % 32 == 0, K >= 64.
// ---------------------------------------------------------------------------
template<int BM, int BN, int WM, int WN>
__global__ __launch_bounds__(256, 2)
void mma_gemm(const float* __restrict__ A, const float* __restrict__ Bm,
              const float* __restrict__ bias, const float* __restrict__ Res,
              float* __restrict__ C,
              int K, int lda, int ldb, int ldc,
              long long offA1, long long offA2,
              long long offB1, long long offB2,
              long long offC1, long long offC2,
              int ZB, int relu, int rnd)
{
    constexpr int BK  = 32;
    constexpr int STR = 36;
    constexpr int MT  = WM / 16;
    constexpr int NT  = WN / 8;
    constexpr int WCOLS = BN / WN;
    constexpr int ACP = BM * 8 / 256;
    constexpr int BCP = BN * 8 / 256;

    extern __shared__ float sm[];
    float* As = sm;                        // [3][BM][STR]
    float* Bs = sm + 3 * BM * STR;         // [3][BN][STR]
    const uint32_t as_u = (uint32_t)__cvta_generic_to_shared(As);
    const uint32_t bs_u = (uint32_t)__cvta_generic_to_shared(Bs);

    const int z  = blockIdx.z;
    const int za = z / ZB, zb = z % ZB;
    A  += (long long)za * offA1 + (long long)zb * offA2;
    Bm += (long long)za * offB1 + (long long)zb * offB2;
    const long long coff = (long long)za * offC1 + (long long)zb * offC2;
    C += coff;
    if (Res) Res += coff;

    const int tid  = threadIdx.x;
    const int warp = tid >> 5, lane = tid & 31;
    const int g = lane >> 2, t4 = lane & 3;
    const int wm0 = (warp / WCOLS) * WM;
    const int wn0 = (warp % WCOLS) * WN;
    const int m0 = blockIdx.y * BM;
    const int n0 = blockIdx.x * BN;

    const int j  = lane >> 3, r8 = lane & 7;
    const int lrow = (j & 1) * 8 + r8;
    const int lcol = (j >> 1) * 4;

    float acc[MT][NT][4] = {};
    const int nk = K / BK;

    auto LOAD = [&](int it, int buf) {
        const int k0 = it * BK;
        const uint32_t ab = as_u + (uint32_t)(buf * BM * STR) * 4u;
        #pragma unroll
        for (int u = 0; u < ACP; ++u) {
            const int f = u * 256 + tid;
            const int m = f >> 3;
            const int kc = (f & 7) * 4;
            cp16(ab + (uint32_t)(m * STR + kc) * 4u,
                 A + (long long)(m0 + m) * lda + k0 + kc);
        }
        const uint32_t bb = bs_u + (uint32_t)(buf * BN * STR) * 4u;
        #pragma unroll
        for (int u = 0; u < BCP; ++u) {
            const int f = u * 256 + tid;
            const int n = f >> 3;
            const int kc = (f & 7) * 4;
            cp16(bb + (uint32_t)(n * STR + kc) * 4u,
                 Bm + (long long)(n0 + n) * ldb + k0 + kc);
        }
        asm volatile("cp.async.commit_group;");
    };

    LOAD(0, 0);
    if (nk > 1) LOAD(1, 1);

    for (int it = 0; it < nk; ++it) {
        const int buf = it % 3;
        if (it + 1 < nk) asm volatile("cp.async.wait_group 1;");
        else             asm volatile("cp.async.wait_group 0;");
        __syncthreads();
        if (it + 2 < nk) LOAD(it + 2, (it + 2) % 3);

        const uint32_t ab = as_u + (uint32_t)(buf * BM * STR) * 4u;
        const uint32_t bb = bs_u + (uint32_t)(buf * BN * STR) * 4u;
        #pragma unroll
        for (int ks = 0; ks < BK / 8; ++ks) {
            uint32_t af[MT][4], bf[NT][2];
            #pragma unroll
            for (int mt = 0; mt < MT; ++mt)
                ldsm4(ab + (uint32_t)((wm0 + mt * 16 + lrow) * STR + ks * 8 + lcol) * 4u,
                      af[mt]);
            #pragma unroll
            for (int p = 0; p < NT / 2; ++p) {
                uint32_t tmp[4];
                ldsm4(bb + (uint32_t)((wn0 + p * 16 + lrow) * STR + ks * 8 + lcol) * 4u,
                      tmp);
                bf[2 * p][0]     = tmp[0]; bf[2 * p][1]     = tmp[2];
                bf[2 * p + 1][0] = tmp[1]; bf[2 * p + 1][1] = tmp[3];
            }
            #pragma unroll
            for (int mt = 0; mt < MT; ++mt)
                #pragma unroll
                for (int nt = 0; nt < NT; ++nt)
                    mma_tf32(acc[mt][nt], af[mt], bf[nt]);
        }
    }

    #pragma unroll
    for (int mt = 0; mt < MT; ++mt) {
        const int r0 = m0 + wm0 + mt * 16 + g;
        #pragma unroll
        for (int nt = 0; nt < NT; ++nt) {
            const int c = n0 + wn0 + nt * 8 + 2 * t4;
            float2 v0 = make_float2(acc[mt][nt][0], acc[mt][nt][1]);
            float2 v1 = make_float2(acc[mt][nt][2], acc[mt][nt][3]);
            if (bias) {
                const float2 bv = *(const float2*)(bias + c);
                v0.x += bv.x; v0.y += bv.y;
                v1.x += bv.x; v1.y += bv.y;
            }
            if (Res) {
                const float2 a0 = *(const float2*)(Res + (long long)r0 * ldc + c);
                const float2 a1 = *(const float2*)(Res + (long long)(r0 + 8) * ldc + c);
                v0.x += a0.x; v0.y += a0.y;
                v1.x += a1.x; v1.y += a1.y;
            }
            if (relu) {
                v0.x = fmaxf(v0.x, 0.0f); v0.y = fmaxf(v0.y, 0.0f);
                v1.x = fmaxf(v1.x, 0.0f); v1.y = fmaxf(v1.y, 0.0f);
            }
            if (rnd) {
                v0.x = rndtf(v0.x); v0.y = rndtf(v0.y);
                v1.x = rndtf(v1.x); v1.y = rndtf(v1.y);
            }
            *(float2*)(C + (long long)r0 * ldc + c) = v0;
            *(float2*)(C + (long long)(r0 + 8) * ldc + c) = v1;
        }
    }
}

#define SMEM_BYTES(BM, BN) (3 * ((BM) + (BN)) * 36 * 4)

// ---------------------------------------------------------------------------
// Fused flash attention, tf32 MMA, online softmax. Occupancy-2 version.
//   grid: (S/128, B*H). 8 warps; warp w owns Q rows w*16..w*16+15.
// BKV=32 KV steps; Q/K tiles stride 68 (dk cols), P/V^T tiles stride 36
// (kv cols). Smem 89.3KB -> 2 CTAs/SM. Double-buffered cp.async K/V/mask.
// ---------------------------------------------------------------------------
#define BQ   128
#define BKV  32
#define QSTR 68
#define PSTR 36

__global__ __launch_bounds__(256, 2)
void flash_kernel(const float* __restrict__ qkv, const float* __restrict__ vt,
                  const int* __restrict__ mask, float* __restrict__ ctx)
{
    extern __shared__ float sm[];
    float* Qs = sm;                              // [128][QSTR]
    float* Ks = Qs + BQ * QSTR;                  // [2][32][QSTR]
    float* Vs = Ks + 2 * BKV * QSTR;             // [2][64][PSTR]  (V^T: dk rows)
    float* Ps = Vs + 2 * DK * PSTR;              // [128][PSTR]
    int*   Ms = (int*)(Ps + BQ * PSTR);          // [2][32]
    const uint32_t qs_u = (uint32_t)__cvta_generic_to_shared(Qs);
    const uint32_t ks_u = (uint32_t)__cvta_generic_to_shared(Ks);
    const uint32_t vs_u = (uint32_t)__cvta_generic_to_shared(Vs);
    const uint32_t ps_u = (uint32_t)__cvta_generic_to_shared(Ps);
    const uint32_t ms_u = (uint32_t)__cvta_generic_to_shared(Ms);

    const int qb = blockIdx.x, bh = blockIdx.y;
    const int b = bh / NHEADS, hh = bh % NHEADS;
    const long long tok0 = (long long)b * SS + qb * BQ;
    const float* Qg = qkv + tok0 * (3 * DMODEL) + hh * DK;
    const float* Kg = qkv + (long long)b * SS * (3 * DMODEL) + DMODEL + hh * DK;
    const float* Vg = vt + (long long)bh * DK * SS;        // [dk][S], ld=SS
    const int*   mg = mask + (long long)b * SS;

    const int tid  = threadIdx.x;
    const int warp = tid >> 5, lane = tid & 31;
    const int g = lane >> 2, t4 = lane & 3;
    const int row0 = warp * 16;
    const int j  = lane >> 3, r8 = lane & 7;
    const int lrow = (j & 1) * 8 + r8;
    const int lcol = (j >> 1) * 4;

    // Q tile -> smem: 128 rows x 16 chunks = 2048 cp / 256 thr = 8 each
    #pragma unroll
    for (int u = 0; u < 8; ++u) {
        const int f = u * 256 + tid;
        const int r = f >> 4, kc = (f & 15) * 4;
        cp16(qs_u + (uint32_t)(r * QSTR + kc) * 4u, Qg + (long long)r * (3 * DMODEL) + kc);
    }
    asm volatile("cp.async.commit_group;");

    auto LOAD = [&](int s, int buf) {
        const int kv0 = s * BKV;
        const uint32_t kb = ks_u + (uint32_t)(buf * BKV * QSTR) * 4u;
        #pragma unroll
        for (int u = 0; u < 2; ++u) {                       // K: 32 rows x 16 chunks
            const int f = u * 256 + tid;
            const int r = f >> 4, kc = (f & 15) * 4;
            cp16(kb + (uint32_t)(r * QSTR + kc) * 4u,
                 Kg + (long long)(kv0 + r) * (3 * DMODEL) + kc);
        }
        const uint32_t vb = vs_u + (uint32_t)(buf * DK * PSTR) * 4u;
        #pragma unroll
        for (int u = 0; u < 2; ++u) {                       // V^T: 64 rows x 8 chunks
            const int f = u * 256 + tid;
            const int r = f >> 3, cc = (f & 7) * 4;
            cp16(vb + (uint32_t)(r * PSTR + cc) * 4u,
                 Vg + (long long)r * SS + kv0 + cc);
        }
        if (tid < 8)                                        // mask: 32 ints
            cp16(ms_u + (uint32_t)(buf * BKV + tid * 4) * 4u, mg + kv0 + tid * 4);
        asm volatile("cp.async.commit_group;");
    };

    LOAD(0, 0);

    float m_a = -3.0e38f, m_b = -3.0e38f, l_a = 0.0f, l_b = 0.0f;
    float oacc[8][4] = {};

    const int NSTEP = SS / BKV;   // 64
    for (int s = 0; s < NSTEP; ++s) {
        const int buf = s & 1;
        asm volatile("cp.async.wait_group 0;");
        __syncthreads();
        if (s + 1 < NSTEP) LOAD(s + 1, buf ^ 1);

        const uint32_t kb = ks_u + (uint32_t)(buf * BKV * QSTR) * 4u;
        const uint32_t vb = vs_u + (uint32_t)(buf * DK * PSTR) * 4u;

        // --- S = Q @ K^T : rows row0..row0+15, cols 0..31
        float sacc[4][4] = {};
        #pragma unroll
        for (int ks8 = 0; ks8 < 8; ++ks8) {
            uint32_t af[4], bf[4][2];
            ldsm4(qs_u + (uint32_t)((row0 + lrow) * QSTR + ks8 * 8 + lcol) * 4u, af);
            #pragma unroll
            for (int p = 0; p < 2; ++p) {
                uint32_t tmp[4];
                ldsm4(kb + (uint32_t)((p * 16 + lrow) * QSTR + ks8 * 8 + lcol) * 4u, tmp);
                bf[2 * p][0]     = tmp[0]; bf[2 * p][1]     = tmp[2];
                bf[2 * p + 1][0] = tmp[1]; bf[2 * p + 1][1] = tmp[3];
            }
            #pragma unroll
            for (int nt = 0; nt < 4; ++nt) mma_tf32(sacc[nt], af, bf[nt]);
        }

        // --- mask + scale + row max
        const int* mbuf = Ms + buf * BKV;
        float rmax_a = -3.0e38f, rmax_b = -3.0e38f;
        #pragma unroll
        for (int nt = 0; nt < 4; ++nt) {
            #pragma unroll
            for (int e = 0; e < 2; ++e) {
                const int c = nt * 8 + 2 * t4 + e;
                const bool live = (mbuf[c] != 0);
                float v0 = sacc[nt][e] * 0.125f;     if (!live) v0 = -1e9f;
                float v1 = sacc[nt][2 + e] * 0.125f; if (!live) v1 = -1e9f;
                sacc[nt][e] = v0; sacc[nt][2 + e] = v1;
                rmax_a = fmaxf(rmax_a, v0); rmax_b = fmaxf(rmax_b, v1);
            }
        }
        rmax_a = fmaxf(rmax_a, __shfl_xor_sync(0xffffffffu, rmax_a, 1));
        rmax_a = fmaxf(rmax_a, __shfl_xor_sync(0xffffffffu, rmax_a, 2));
        rmax_b = fmaxf(rmax_b, __shfl_xor_sync(0xffffffffu, rmax_b, 1));
        rmax_b = fmaxf(rmax_b, __shfl_xor_sync(0xffffffffu, rmax_b, 2));

        const float mna = fmaxf(m_a, rmax_a), mnb = fmaxf(m_b, rmax_b);
        const float ca = fex2((m_a - mna) * L2E), cb = fex2((m_b - mnb) * L2E);
        m_a = mna; m_b = mnb;

        // --- P = exp(s - m), sum, store tf32 P to smem
        float sum_a = 0.0f, sum_b = 0.0f;
        #pragma unroll
        for (int nt = 0; nt < 4; ++nt) {
            const float p0 = fex2((sacc[nt][0] - mna) * L2E);
            const float p1 = fex2((sacc[nt][1] - mna) * L2E);
            const float p2 = fex2((sacc[nt][2] - mnb) * L2E);
            const float p3 = fex2((sacc[nt][3] - mnb) * L2E);
            sum_a += p0 + p1; sum_b += p2 + p3;
            const int c = nt * 8 + 2 * t4;
            *(float2*)(Ps + (row0 + g) * PSTR + c)     = make_float2(rndtf(p0), rndtf(p1));
            *(float2*)(Ps + (row0 + g + 8) * PSTR + c) = make_float2(rndtf(p2), rndtf(p3));
        }
        sum_a += __shfl_xor_sync(0xffffffffu, sum_a, 1);
        sum_a += __shfl_xor_sync(0xffffffffu, sum_a, 2);
        sum_b += __shfl_xor_sync(0xffffffffu, sum_b, 1);
        sum_b += __shfl_xor_sync(0xffffffffu, sum_b, 2);
        l_a = l_a * ca + sum_a;
        l_b = l_b * cb + sum_b;

        #pragma unroll
        for (int nt = 0; nt < 8; ++nt) {
            oacc[nt][0] *= ca; oacc[nt][1] *= ca;
            oacc[nt][2] *= cb; oacc[nt][3] *= cb;
        }
        __syncwarp();

        // --- O += P @ V : A from Ps (warp rows, kv cols), B from Vs (dk rows)
        #pragma unroll
        for (int ks8 = 0; ks8 < 4; ++ks8) {
            uint32_t af[4], bf[8][2];
            ldsm4(ps_u + (uint32_t)((row0 + lrow) * PSTR + ks8 * 8 + lcol) * 4u, af);
            #pragma unroll
            for (int p = 0; p < 4; ++p) {
                uint32_t tmp[4];
                ldsm4(vb + (uint32_t)((p * 16 + lrow) * PSTR + ks8 * 8 + lcol) * 4u, tmp);
                bf[2 * p][0]     = tmp[0]; bf[2 * p][1]     = tmp[2];
                bf[2 * p + 1][0] = tmp[1]; bf[2 * p + 1][1] = tmp[3];
            }
            #pragma unroll
            for (int nt = 0; nt < 8; ++nt) mma_tf32(oacc[nt], af, bf[nt]);
        }
    }

    // --- epilogue
    const float ia = 1.0f / l_a, ib = 1.0f / l_b;
    float* crow_a = ctx + (tok0 + row0 + g) * DMODEL + hh * DK;
    float* crow_b = ctx + (tok0 + row0 + g + 8) * DMODEL + hh * DK;
    #pragma unroll
    for (int nt = 0; nt < 8; ++nt) {
        const int c = nt * 8 + 2 * t4;
        *(float2*)(crow_a + c) = make_float2(rndtf(oacc[nt][0] * ia), rndtf(oacc[nt][1] * ia));
        *(float2*)(crow_b + c) = make_float2(rndtf(oacc[nt][2] * ib), rndtf(oacc[nt][3] * ib));
    }
}

#define FLASH_SMEM ((BQ * QSTR + 2 * BKV * QSTR + 2 * DK * PSTR + BQ * PSTR) * 4 + 2 * BKV * 4)

// ---------------------------------------------------------------------------
// Launch driver
// ---------------------------------------------------------------------------
extern "C" void kernel_launch(void* const* d_in, const int* in_sizes, int n_in,
                              void* d_out, int out_size)
{
    (void)in_sizes; (void)n_in; (void)out_size;
    const float* x    = (const float*)d_in[0];
    const int*   mask = (const int*)  d_in[1];
    const float* wq = (const float*)d_in[2],  *bq = (const float*)d_in[3];
    const float* wk = (const float*)d_in[4],  *bk = (const float*)d_in[5];
    const float* wv = (const float*)d_in[6],  *bv = (const float*)d_in[7];
    const float* wo = (const float*)d_in[8],  *bo = (const float*)d_in[9];
    const float* w1 = (const float*)d_in[10], *b1 = (const float*)d_in[11];
    const float* w2 = (const float*)d_in[12], *b2 = (const float*)d_in[13];
    const float* ln1a = (const float*)d_in[14], *ln1b = (const float*)d_in[15];
    const float* ln2a = (const float*)d_in[16], *ln2b = (const float*)d_in[17];
    float* out = (float*)d_out;

    float *h, *qkv, *vt, *ctx, *x1, *ff, *wqkvT, *woT, *w1T, *w2T, *bqkv;
    cudaGetSymbolAddress((void**)&h,     g_h);
    cudaGetSymbolAddress((void**)&qkv,   g_qkv);
    cudaGetSymbolAddress((void**)&vt,    g_vt);
    cudaGetSymbolAddress((void**)&ctx,   g_ctx);
    cudaGetSymbolAddress((void**)&x1,    g_x1);
    cudaGetSymbolAddress((void**)&ff,    g_ff);
    cudaGetSymbolAddress((void**)&wqkvT, g_wqkvT);
    cudaGetSymbolAddress((void**)&woT,   g_woT);
    cudaGetSymbolAddress((void**)&w1T,   g_w1T);
    cudaGetSymbolAddress((void**)&w2T,   g_w2T);
    cudaGetSymbolAddress((void**)&bqkv,  g_bqkv);

    constexpr int SM1 = SMEM_BYTES(128, 128);   // 110592

    cudaFuncSetAttribute((const void*)mma_gemm<128,128,64,32>,
                         cudaFuncAttributeMaxDynamicSharedMemorySize, SM1);
    cudaFuncSetAttribute((const void*)flash_kernel,
                         cudaFuncAttributeMaxDynamicSharedMemorySize, FLASH_SMEM);

    // 0) fused weight preprocessing (transposes + bias concat), 1 launch
    transpose_all_kernel<<<6913, dim3(32, 8)>>>(
        wq, wk, wv, wo, w1, w2, wqkvT, woT, w1T, w2T, bq, bk, bv, bqkv);

    // 1) LN1
    ln_kernel<<<MTOK, 256>>>(x, h, ln1a, ln1b);

    // 2) fused QKV: [4096,768] @ [768,2304] + bqkv, tf32-rnd
    mma_gemm<128,128,64,32><<<dim3(2304 / 128, MTOK / 128, 1), 256, SM1>>>(
        h, wqkvT, bqkv, nullptr, qkv,
        DMODEL, DMODEL, DMODEL, 3 * DMODEL,
        0,0, 0,0, 0,0, 1, 0, 1);

    // 3) V^T per head
    transpose_kernel<<<dim3(2, 64, BB * NHEADS), dim3(32, 8)>>>(
        qkv + 2 * DMODEL, vt, 3 * DMODEL, SS,
        (long long)SS * 3 * DMODEL, DK,
        (long long)NHEADS * DK * SS, (long long)DK * SS, NHEADS);

    // 4) fused flash attention -> ctx
    flash_kernel<<<dim3(SS / BQ, BB * NHEADS), 256, FLASH_SMEM>>>(qkv, vt, mask, ctx);

    // 5) x1 = x + ctx @ wo + bo   (128x128 tiles, 1 wave @ occ2; ncu s5 target)
    mma_gemm<128,128,64,32><<<dim3(DMODEL / 128, MTOK / 128, 1), 256, SM1>>>(
        ctx, woT, bo, x, x1,
        DMODEL, DMODEL, DMODEL, DMODEL,
        0,0, 0,0, 0,0, 1, 0, 0);

    // 6) LN2
    ln_kernel<<<MTOK, 256>>>(x1, h, ln2a, ln2b);

    // 7) ff = relu(h @ w1 + b1), tf32-rnd
    mma_gemm<128,128,64,32><<<dim3(DFF / 128, MTOK / 128, 1), 256, SM1>>>(
        h, w1T, b1, nullptr, ff,
        DMODEL, DMODEL, DMODEL, DFF,
        0,0, 0,0, 0,0, 1, 1, 1);

    // 8) out = x1 + ff @ w2 + b2   (128x128 tiles)
    mma_gemm<128,128,64,32><<<dim3(DMODEL / 128, MTOK / 128, 1), 256, SM1>>>(
        ff, w2T, b2, x1, out,
        DFF, DFF, DFF, DMODEL,
        0,0, 0,0, 0,0, 1, 0, 0);
}

// round 14
// speedup vs baseline: 5.4233x; 1.6242x over previous
#include <cuda_runtime.h>
#include <cuda_bf16.h>
#include <cuda_fp16.h>
#include <cstdint>

// Problem constants
#define DMODEL 768
#define NHEADS 12
#define DK     64
#define DFF    3072
#define BB     2
#define SS     2048
#define MTOK   (BB * SS)
#define L2E    1.44269504088896f

// ---------------------------------------------------------------------------
// Scratch (__device__ globals)
// ---------------------------------------------------------------------------
__device__ __half g_h   [MTOK * DMODEL];
__device__ __half g_qkv [MTOK * 3 * DMODEL];                 // fused q|k|v, ld=2304
__device__ __half g_vt  [(long long)BB * NHEADS * DK * SS];  // V^T per head [dk][S]
__device__ __half g_ctx [MTOK * DMODEL];
__device__ float  g_x1  [MTOK * DMODEL];
__device__ __half g_ff  [MTOK * DFF];
__device__ __half g_wqkvT[3 * DMODEL * DMODEL];              // [n][k]
__device__ __half g_woT [DMODEL * DMODEL];
__device__ __half g_w1T [DFF * DMODEL];
__device__ __half g_w2T [DMODEL * DFF];
__device__ float  g_bqkv[3 * DMODEL];

// ---------------------------------------------------------------------------
// Helpers
// ---------------------------------------------------------------------------
__device__ __forceinline__ float fex2(float x) {
    float y; asm("ex2.approx.ftz.f32 %0, %1;" : "=f"(y) : "f"(x)); return y;
}
__device__ __forceinline__ void ldsm4(uint32_t addr, uint32_t* r) {
    asm volatile("ldmatrix.sync.aligned.m8n8.x4.shared.b16 {%0,%1,%2,%3}, [%4];"
                 : "=r"(r[0]), "=r"(r[1]), "=r"(r[2]), "=r"(r[3]) : "r"(addr));
}
__device__ __forceinline__ void cp16(uint32_t dst, const void* src) {
    asm volatile("cp.async.cg.shared.global [%0], [%1], 16;" :: "r"(dst), "l"(src));
}
// m16n8k16 fp16, fp32 accumulate
__device__ __forceinline__ void mma_f16(float* c, const uint32_t* a, const uint32_t* b) {
    asm volatile(
        "mma.sync.aligned.m16n8k16.row.col.f32.f16.f16.f32 "
        "{%0,%1,%2,%3}, {%4,%5,%6,%7}, {%8,%9}, {%0,%1,%2,%3};"
        : "+f"(c[0]), "+f"(c[1]), "+f"(c[2]), "+f"(c[3])
        : "r"(a[0]), "r"(a[1]), "r"(a[2]), "r"(a[3]), "r"(b[0]), "r"(b[1]));
}

// ---------------------------------------------------------------------------
// LayerNorm (torch-style, unbiased std). Output in fp16 (feeds MMAs).
// ---------------------------------------------------------------------------
__global__ void ln_kernel(const float* __restrict__ x, __half* __restrict__ out,
                          const float* __restrict__ alpha, const float* __restrict__ beta)
{
    const int row = blockIdx.x;
    const float* xr = x + (size_t)row * DMODEL;
    __half* orow = out + (size_t)row * DMODEL;
    const int tid = threadIdx.x;   // 256

    float v0 = xr[tid], v1 = xr[tid + 256], v2 = xr[tid + 512];
    float s = v0 + v1 + v2;

    __shared__ float red[8];
    #pragma unroll
    for (int o = 16; o; o >>= 1) s += __shfl_xor_sync(0xffffffffu, s, o);
    if ((tid & 31) == 0) red[tid >> 5] = s;
    __syncthreads();
    if (tid < 32) {
        float t = (tid < 8) ? red[tid] : 0.0f;
        #pragma unroll
        for (int o = 4; o; o >>= 1) t += __shfl_xor_sync(0xffffffffu, t, o);
        if (tid == 0) red[0] = t;
    }
    __syncthreads();
    const float mean = red[0] * (1.0f / DMODEL);
    const float d0 = v0 - mean, d1 = v1 - mean, d2 = v2 - mean;
    float q = d0 * d0 + d1 * d1 + d2 * d2;
    __syncthreads();

    #pragma unroll
    for (int o = 16; o; o >>= 1) q += __shfl_xor_sync(0xffffffffu, q, o);
    if ((tid & 31) == 0) red[tid >> 5] = q;
    __syncthreads();
    if (tid < 32) {
        float t = (tid < 8) ? red[tid] : 0.0f;
        #pragma unroll
        for (int o = 4; o; o >>= 1) t += __shfl_xor_sync(0xffffffffu, t, o);
        if (tid == 0) red[0] = t;
    }
    __syncthreads();
    const float var = red[0] * (1.0f / (DMODEL - 1));
    const float inv = alpha[0] / (sqrtf(var) + 1e-6f);
    const float bb  = beta[0];

    orow[tid]       = __float2half(d0 * inv + bb);
    orow[tid + 256] = __float2half(d1 * inv + bb);
    orow[tid + 512] = __float2half(d2 * inv + bb);
}

// ---------------------------------------------------------------------------
// Fused weight preprocessing: transpose all 6 weights fp32->[n][k] fp16 and
// concatenate qkv biases (last block).
// ---------------------------------------------------------------------------
__global__ void transpose_all_kernel(
    const float* __restrict__ wq, const float* __restrict__ wk,
    const float* __restrict__ wv, const float* __restrict__ wo,
    const float* __restrict__ w1, const float* __restrict__ w2,
    __half* __restrict__ wqkvT, __half* __restrict__ woT,
    __half* __restrict__ w1T,   __half* __restrict__ w2T,
    const float* __restrict__ bq, const float* __restrict__ bk,
    const float* __restrict__ bv, float* __restrict__ bqkv)
{
    int id = blockIdx.x;
    const int tx = threadIdx.x, ty = threadIdx.y;     // (32, 8)

    if (id == 6912) {
        for (int i = ty * 32 + tx; i < 3 * DMODEL; i += 256) {
            float v;
            if (i < 768) v = bq[i];
            else if (i < 1536) v = bk[i - 768];
            else v = bv[i - 1536];
            bqkv[i] = v;
        }
        return;
    }

    const float* in; __half* out; int R, C;
    if      (id < 576)  {            in = wq; out = wqkvT;                 R = 768;  C = 768; }
    else if (id < 1152) { id -= 576; in = wk; out = wqkvT + 768 * 768;     R = 768;  C = 768; }
    else if (id < 1728) { id -= 1152; in = wv; out = wqkvT + 2 * 768 * 768; R = 768; C = 768; }
    else if (id < 2304) { id -= 1728; in = wo; out = woT;                  R = 768;  C = 768; }
    else if (id < 4608) { id -= 2304; in = w1; out = w1T;                  R = 768;  C = 3072; }
    else                { id -= 4608; in = w2; out = w2T;                  R = 3072; C = 768; }

    const int cb = C / 32;
    const int r0 = (id / cb) * 32, c0 = (id % cb) * 32;

    __shared__ float t[32][33];
    #pragma unroll
    for (int i = ty; i < 32; i += 8)
        t[i][tx] = in[(long long)(r0 + i) * C + c0 + tx];
    __syncthreads();
    #pragma unroll
    for (int i = ty; i < 32; i += 8)
        out[(long long)(c0 + i) * R + r0 + tx] = __float2half(t[tx][i]);
}

// ---------------------------------------------------------------------------
// Per-head V^T: vt[bh][dk][S] from qkv's V slice (half -> half).
// grid (2, 64, B*H), block (32, 8).
// ---------------------------------------------------------------------------
__global__ void vtrans_kernel(const __half* __restrict__ qkv, __half* __restrict__ vt)
{
    __shared__ __half t[32][34];
    const int z = blockIdx.z;
    const int b = z / NHEADS, hh = z % NHEADS;
    const __half* in = qkv + ((long long)b * SS) * (3 * DMODEL) + 2 * DMODEL + hh * DK;
    __half* out = vt + (long long)z * DK * SS;
    const int r0 = blockIdx.y * 32, c0 = blockIdx.x * 32;   // r = token, c = dk
    const int tx = threadIdx.x, ty = threadIdx.y;
    #pragma unroll
    for (int i = ty; i < 32; i += 8)
        t[i][tx] = in[(long long)(r0 + i) * (3 * DMODEL) + c0 + tx];
    __syncthreads();
    #pragma unroll
    for (int i = ty; i < 32; i += 8)
        out[(long long)(c0 + i) * SS + r0 + tx] = t[tx][i];
}

// ---------------------------------------------------------------------------
// Tensor-core GEMM, fp16 m16n8k16, cp.async + ldmatrix, 3-stage pipeline.
//   C = A @ B^T-layout (+bias) (+Res) (relu?), C fp32 or fp16 (out_half).
// A: [m][k] half (lda), B: [n][k] half (ldb). K % 32 == 0, K >= 64.
// Smem rows: 32 halves + 8 pad = 80B stride -> ldmatrix phases conflict-free.
// ---------------------------------------------------------------------------
template<int BM, int BN, int WM, int WN>
__global__ __launch_bounds__(256, 2)
void mma_gemm(const __half* __restrict__ A, const __half* __restrict__ Bm,
              const float* __restrict__ bias, const float* __restrict__ Res,
              void* __restrict__ Cv,
              int K, int lda, int ldb, int ldc,
              int relu, int out_half)
{
    constexpr int BK  = 32;                // halves per K-iter
    constexpr int STR = 40;                // halves per smem row (80 B)
    constexpr int MT  = WM / 16;
    constexpr int NT  = WN / 8;
    constexpr int WCOLS = BN / WN;
    constexpr int ACP = BM * 4 / 256;      // 16B chunks per thread (A)
    constexpr int BCP = BN * 4 / 256;

    extern __shared__ __half smh[];
    const uint32_t as_u = (uint32_t)__cvta_generic_to_shared(smh);
    const uint32_t bs_u = as_u + 3 * BM * STR * 2;

    const int tid  = threadIdx.x;
    const int warp = tid >> 5, lane = tid & 31;
    const int g = lane >> 2, t4 = lane & 3;
    const int wm0 = (warp / WCOLS) * WM;
    const int wn0 = (warp % WCOLS) * WN;
    const int m0 = blockIdx.y * BM;
    const int n0 = blockIdx.x * BN;
    const int l16 = lane & 15;
    const int lhi = (lane >> 4) * 16;      // byte offset for col-halves 8..15

    float acc[MT][NT][4] = {};
    const int nk = K / BK;

    auto LOAD = [&](int it, int buf) {
        const int k0 = it * BK;
        const uint32_t ab = as_u + (uint32_t)(buf * BM * STR) * 2u;
        #pragma unroll
        for (int u = 0; u < ACP; ++u) {
            const int f = u * 256 + tid;
            const int m = f >> 2;
            const int kc = (f & 3) * 8;
            cp16(ab + (uint32_t)(m * STR + kc) * 2u,
                 A + (long long)(m0 + m) * lda + k0 + kc);
        }
        const uint32_t bb = bs_u + (uint32_t)(buf * BN * STR) * 2u;
        #pragma unroll
        for (int u = 0; u < BCP; ++u) {
            const int f = u * 256 + tid;
            const int n = f >> 2;
            const int kc = (f & 3) * 8;
            cp16(bb + (uint32_t)(n * STR + kc) * 2u,
                 Bm + (long long)(n0 + n) * ldb + k0 + kc);
        }
        asm volatile("cp.async.commit_group;");
    };

    LOAD(0, 0);
    if (nk > 1) LOAD(1, 1);

    for (int it = 0; it < nk; ++it) {
        const int buf = it % 3;
        if (it + 1 < nk) asm volatile("cp.async.wait_group 1;");
        else             asm volatile("cp.async.wait_group 0;");
        __syncthreads();
        if (it + 2 < nk) LOAD(it + 2, (it + 2) % 3);

        const uint32_t ab = as_u + (uint32_t)(buf * BM * STR) * 2u;
        const uint32_t bb = bs_u + (uint32_t)(buf * BN * STR) * 2u;
        #pragma unroll
        for (int ks = 0; ks < 2; ++ks) {           // two k16 steps per BK=32
            uint32_t af[MT][4], bf[NT][2];
            #pragma unroll
            for (int mt = 0; mt < MT; ++mt)
                ldsm4(ab + (uint32_t)((wm0 + mt * 16 + l16) * STR) * 2u + ks * 32 + lhi,
                      af[mt]);
            #pragma unroll
            for (int p = 0; p < NT / 2; ++p) {
                uint32_t tmp[4];
                ldsm4(bb + (uint32_t)((wn0 + p * 16 + l16) * STR) * 2u + ks * 32 + lhi,
                      tmp);
                bf[2 * p][0]     = tmp[0]; bf[2 * p][1]     = tmp[2];
                bf[2 * p + 1][0] = tmp[1]; bf[2 * p + 1][1] = tmp[3];
            }
            #pragma unroll
            for (int mt = 0; mt < MT; ++mt)
                #pragma unroll
                for (int nt = 0; nt < NT; ++nt)
                    mma_f16(acc[mt][nt], af[mt], bf[nt]);
        }
    }

    #pragma unroll
    for (int mt = 0; mt < MT; ++mt) {
        const int r0 = m0 + wm0 + mt * 16 + g;
        #pragma unroll
        for (int nt = 0; nt < NT; ++nt) {
            const int c = n0 + wn0 + nt * 8 + 2 * t4;
            float2 v0 = make_float2(acc[mt][nt][0], acc[mt][nt][1]);
            float2 v1 = make_float2(acc[mt][nt][2], acc[mt][nt][3]);
            if (bias) {
                const float2 bv = *(const float2*)(bias + c);
                v0.x += bv.x; v0.y += bv.y;
                v1.x += bv.x; v1.y += bv.y;
            }
            if (Res) {
                const float2 a0 = *(const float2*)(Res + (long long)r0 * ldc + c);
                const float2 a1 = *(const float2*)(Res + (long long)(r0 + 8) * ldc + c);
                v0.x += a0.x; v0.y += a0.y;
                v1.x += a1.x; v1.y += a1.y;
            }
            if (relu) {
                v0.x = fmaxf(v0.x, 0.0f); v0.y = fmaxf(v0.y, 0.0f);
                v1.x = fmaxf(v1.x, 0.0f); v1.y = fmaxf(v1.y, 0.0f);
            }
            if (out_half) {
                __half* Ch = (__half*)Cv;
                *(__half2*)(Ch + (long long)r0 * ldc + c)       = __floats2half2_rn(v0.x, v0.y);
                *(__half2*)(Ch + (long long)(r0 + 8) * ldc + c) = __floats2half2_rn(v1.x, v1.y);
            } else {
                float* Cf = (float*)Cv;
                *(float2*)(Cf + (long long)r0 * ldc + c) = v0;
                *(float2*)(Cf + (long long)(r0 + 8) * ldc + c) = v1;
            }
        }
    }
}

#define SMEM_BYTES(BM, BN) (3 * ((BM) + (BN)) * 40 * 2)

// ---------------------------------------------------------------------------
// Fused flash attention, fp16 m16n8k16 MMA, online softmax.
//   grid: (S/128, B*H). 8 warps; warp w owns Q rows w*16..w*16+15.
// Q/K tiles: 64 halves + 8 pad = 144B stride. P/V^T tiles: 32+8 = 80B stride.
// BKV=32 per step, double-buffered cp.async. Smem ~48KB.
// ---------------------------------------------------------------------------
#define BQ   128
#define BKV  32
#define QSTR 72
#define PSTR 40

__global__ __launch_bounds__(256, 2)
void flash_kernel(const __half* __restrict__ qkv, const __half* __restrict__ vt,
                  const int* __restrict__ mask, __half* __restrict__ ctx)
{
    extern __shared__ __half smh[];
    // offsets in halves
    const int QS = 0;                         // [128][72]
    const int KS = QS + BQ * QSTR;            // [2][32][72]
    const int VS = KS + 2 * BKV * QSTR;       // [2][64][40]
    const int PS = VS + 2 * DK * PSTR;        // [128][40]
    const int MS = PS + BQ * PSTR;            // int [2][32] (reinterpreted)
    __half* Psh = smh + PS;
    int*    Msh = (int*)(smh + MS);
    const uint32_t base_u = (uint32_t)__cvta_generic_to_shared(smh);
    const uint32_t qs_u = base_u + QS * 2;
    const uint32_t ks_u = base_u + KS * 2;
    const uint32_t vs_u = base_u + VS * 2;
    const uint32_t ps_u = base_u + PS * 2;
    const uint32_t ms_u = base_u + MS * 2;

    const int qb = blockIdx.x, bh = blockIdx.y;
    const int b = bh / NHEADS, hh = bh % NHEADS;
    const long long tok0 = (long long)b * SS + qb * BQ;
    const __half* Qg = qkv + tok0 * (3 * DMODEL) + hh * DK;
    const __half* Kg = qkv + (long long)b * SS * (3 * DMODEL) + DMODEL + hh * DK;
    const __half* Vg = vt + (long long)bh * DK * SS;        // [dk][S], ld=SS
    const int*    mg = mask + (long long)b * SS;

    const int tid  = threadIdx.x;
    const int warp = tid >> 5, lane = tid & 31;
    const int g = lane >> 2, t4 = lane & 3;
    const int row0 = warp * 16;
    const int l16 = lane & 15;
    const int lhi = (lane >> 4) * 16;

    // Q tile: 128 rows x 8 chunks(8 halves) = 1024 -> 4/thread
    #pragma unroll
    for (int u = 0; u < 4; ++u) {
        const int f = u * 256 + tid;
        const int r = f >> 3, kc = (f & 7) * 8;
        cp16(qs_u + (uint32_t)(r * QSTR + kc) * 2u, Qg + (long long)r * (3 * DMODEL) + kc);
    }
    asm volatile("cp.async.commit_group;");

    auto LOAD = [&](int s, int buf) {
        const int kv0 = s * BKV;
        const uint32_t kb = ks_u + (uint32_t)(buf * BKV * QSTR) * 2u;
        {   // K: 32 rows x 8 chunks = 256 -> 1/thread
            const int r = tid >> 3, kc = (tid & 7) * 8;
            cp16(kb + (uint32_t)(r * QSTR + kc) * 2u,
                 Kg + (long long)(kv0 + r) * (3 * DMODEL) + kc);
        }
        const uint32_t vb = vs_u + (uint32_t)(buf * DK * PSTR) * 2u;
        {   // V^T: 64 rows x 4 chunks = 256 -> 1/thread
            const int r = tid >> 2, cc = (tid & 3) * 8;
            cp16(vb + (uint32_t)(r * PSTR + cc) * 2u,
                 Vg + (long long)r * SS + kv0 + cc);
        }
        if (tid < 8)                                        // mask: 32 ints
            cp16(ms_u + (uint32_t)(buf * BKV + tid * 4) * 4u, mg + kv0 + tid * 4);
        asm volatile("cp.async.commit_group;");
    };

    LOAD(0, 0);

    float m_a = -3.0e38f, m_b = -3.0e38f, l_a = 0.0f, l_b = 0.0f;
    float oacc[8][4] = {};

    const int NSTEP = SS / BKV;   // 64
    for (int s = 0; s < NSTEP; ++s) {
        const int buf = s & 1;
        asm volatile("cp.async.wait_group 0;");
        __syncthreads();
        if (s + 1 < NSTEP) LOAD(s + 1, buf ^ 1);

        const uint32_t kb = ks_u + (uint32_t)(buf * BKV * QSTR) * 2u;
        const uint32_t vb = vs_u + (uint32_t)(buf * DK * PSTR) * 2u;

        // --- S = Q @ K^T : rows row0..row0+15, cols 0..31 (4 k16 steps)
        float sacc[4][4] = {};
        #pragma unroll
        for (int ks = 0; ks < 4; ++ks) {
            uint32_t af[4], bf[4][2];
            ldsm4(qs_u + (uint32_t)((row0 + l16) * QSTR) * 2u + ks * 32 + lhi, af);
            #pragma unroll
            for (int p = 0; p < 2; ++p) {
                uint32_t tmp[4];
                ldsm4(kb + (uint32_t)((p * 16 + l16) * QSTR) * 2u + ks * 32 + lhi, tmp);
                bf[2 * p][0]     = tmp[0]; bf[2 * p][1]     = tmp[2];
                bf[2 * p + 1][0] = tmp[1]; bf[2 * p + 1][1] = tmp[3];
            }
            #pragma unroll
            for (int nt = 0; nt < 4; ++nt) mma_f16(sacc[nt], af, bf[nt]);
        }

        // --- mask + scale + row max
        const int* mbuf = Msh + buf * BKV;
        float rmax_a = -3.0e38f, rmax_b = -3.0e38f;
        #pragma unroll
        for (int nt = 0; nt < 4; ++nt) {
            #pragma unroll
            for (int e = 0; e < 2; ++e) {
                const int c = nt * 8 + 2 * t4 + e;
                const bool live = (mbuf[c] != 0);
                float v0 = sacc[nt][e] * 0.125f;     if (!live) v0 = -1e9f;
                float v1 = sacc[nt][2 + e] * 0.125f; if (!live) v1 = -1e9f;
                sacc[nt][e] = v0; sacc[nt][2 + e] = v1;
                rmax_a = fmaxf(rmax_a, v0); rmax_b = fmaxf(rmax_b, v1);
            }
        }
        rmax_a = fmaxf(rmax_a, __shfl_xor_sync(0xffffffffu, rmax_a, 1));
        rmax_a = fmaxf(rmax_a, __shfl_xor_sync(0xffffffffu, rmax_a, 2));
        rmax_b = fmaxf(rmax_b, __shfl_xor_sync(0xffffffffu, rmax_b, 1));
        rmax_b = fmaxf(rmax_b, __shfl_xor_sync(0xffffffffu, rmax_b, 2));

        const float mna = fmaxf(m_a, rmax_a), mnb = fmaxf(m_b, rmax_b);
        const float ca = fex2((m_a - mna) * L2E), cb = fex2((m_b - mnb) * L2E);
        m_a = mna; m_b = mnb;

        // --- P = exp(s - m), sum, store fp16 P to smem
        float sum_a = 0.0f, sum_b = 0.0f;
        #pragma unroll
        for (int nt = 0; nt < 4; ++nt) {
            const float p0 = fex2((sacc[nt][0] - mna) * L2E);
            const float p1 = fex2((sacc[nt][1] - mna) * L2E);
            const float p2 = fex2((sacc[nt][2] - mnb) * L2E);
            const float p3 = fex2((sacc[nt][3] - mnb) * L2E);
            sum_a += p0 + p1; sum_b += p2 + p3;
            const int c = nt * 8 + 2 * t4;
            *(__half2*)(Psh + (row0 + g) * PSTR + c)     = __floats2half2_rn(p0, p1);
            *(__half2*)(Psh + (row0 + g + 8) * PSTR + c) = __floats2half2_rn(p2, p3);
        }
        sum_a += __shfl_xor_sync(0xffffffffu, sum_a, 1);
        sum_a += __shfl_xor_sync(0xffffffffu, sum_a, 2);
        sum_b += __shfl_xor_sync(0xffffffffu, sum_b, 1);
        sum_b += __shfl_xor_sync(0xffffffffu, sum_b, 2);
        l_a = l_a * ca + sum_a;
        l_b = l_b * cb + sum_b;

        #pragma unroll
        for (int nt = 0; nt < 8; ++nt) {
            oacc[nt][0] *= ca; oacc[nt][1] *= ca;
            oacc[nt][2] *= cb; oacc[nt][3] *= cb;
        }
        __syncwarp();

        // --- O += P @ V : A from Ps (q rows x kv), B from Vs (dk rows x kv)
        #pragma unroll
        for (int ks = 0; ks < 2; ++ks) {
            uint32_t af[4], bf[8][2];
            ldsm4(ps_u + (uint32_t)((row0 + l16) * PSTR) * 2u + ks * 32 + lhi, af);
            #pragma unroll
            for (int p = 0; p < 4; ++p) {
                uint32_t tmp[4];
                ldsm4(vb + (uint32_t)((p * 16 + l16) * PSTR) * 2u + ks * 32 + lhi, tmp);
                bf[2 * p][0]     = tmp[0]; bf[2 * p][1]     = tmp[2];
                bf[2 * p + 1][0] = tmp[1]; bf[2 * p + 1][1] = tmp[3];
            }
            #pragma unroll
            for (int nt = 0; nt < 8; ++nt) mma_f16(oacc[nt], af, bf[nt]);
        }
    }

    // --- epilogue: normalize, write ctx (fp16; feeds O-proj MMA)
    const float ia = 1.0f / l_a, ib = 1.0f / l_b;
    __half* crow_a = ctx + (tok0 + row0 + g) * DMODEL + hh * DK;
    __half* crow_b = ctx + (tok0 + row0 + g + 8) * DMODEL + hh * DK;
    #pragma unroll
    for (int nt = 0; nt < 8; ++nt) {
        const int c = nt * 8 + 2 * t4;
        *(__half2*)(crow_a + c) = __floats2half2_rn(oacc[nt][0] * ia, oacc[nt][1] * ia);
        *(__half2*)(crow_b + c) = __floats2half2_rn(oacc[nt][2] * ib, oacc[nt][3] * ib);
    }
}

#define FLASH_SMEM ((BQ * QSTR + 2 * BKV * QSTR + 2 * DK * PSTR + BQ * PSTR) * 2 + 2 * BKV * 4)

// ---------------------------------------------------------------------------
// Launch driver
// ---------------------------------------------------------------------------
extern "C" void kernel_launch(void* const* d_in, const int* in_sizes, int n_in,
                              void* d_out, int out_size)
{
    (void)in_sizes; (void)n_in; (void)out_size;
    const float* x    = (const float*)d_in[0];
    const int*   mask = (const int*)  d_in[1];
    const float* wq = (const float*)d_in[2],  *bq = (const float*)d_in[3];
    const float* wk = (const float*)d_in[4],  *bk = (const float*)d_in[5];
    const float* wv = (const float*)d_in[6],  *bv = (const float*)d_in[7];
    const float* wo = (const float*)d_in[8],  *bo = (const float*)d_in[9];
    const float* w1 = (const float*)d_in[10], *b1 = (const float*)d_in[11];
    const float* w2 = (const float*)d_in[12], *b2 = (const float*)d_in[13];
    const float* ln1a = (const float*)d_in[14], *ln1b = (const float*)d_in[15];
    const float* ln2a = (const float*)d_in[16], *ln2b = (const float*)d_in[17];
    float* out = (float*)d_out;

    __half *h, *qkv, *vt, *ctx, *ff, *wqkvT, *woT, *w1T, *w2T;
    float *x1, *bqkv;
    cudaGetSymbolAddress((void**)&h,     g_h);
    cudaGetSymbolAddress((void**)&qkv,   g_qkv);
    cudaGetSymbolAddress((void**)&vt,    g_vt);
    cudaGetSymbolAddress((void**)&ctx,   g_ctx);
    cudaGetSymbolAddress((void**)&x1,    g_x1);
    cudaGetSymbolAddress((void**)&ff,    g_ff);
    cudaGetSymbolAddress((void**)&wqkvT, g_wqkvT);
    cudaGetSymbolAddress((void**)&woT,   g_woT);
    cudaGetSymbolAddress((void**)&w1T,   g_w1T);
    cudaGetSymbolAddress((void**)&w2T,   g_w2T);
    cudaGetSymbolAddress((void**)&bqkv,  g_bqkv);

    constexpr int SM1 = SMEM_BYTES(128, 128);   // 61440

    cudaFuncSetAttribute((const void*)mma_gemm<128,128,64,32>,
                         cudaFuncAttributeMaxDynamicSharedMemorySize, SM1);
    cudaFuncSetAttribute((const void*)flash_kernel,
                         cudaFuncAttributeMaxDynamicSharedMemorySize, FLASH_SMEM);

    // 0) fused weight preprocessing (fp32 -> fp16 [n][k] + bias concat)
    transpose_all_kernel<<<6913, dim3(32, 8)>>>(
        wq, wk, wv, wo, w1, w2, wqkvT, woT, w1T, w2T, bq, bk, bv, bqkv);

    // 1) LN1 -> h (fp16)
    ln_kernel<<<MTOK, 256>>>(x, h, ln1a, ln1b);

    // 2) fused QKV: [4096,768] @ [768,2304] + bqkv -> qkv (fp16)
    mma_gemm<128,128,64,32><<<dim3(2304 / 128, MTOK / 128, 1), 256, SM1>>>(
        h, wqkvT, bqkv, nullptr, qkv,
        DMODEL, DMODEL, DMODEL, 3 * DMODEL, 0, 1);

    // 3) V^T per head (fp16)
    vtrans_kernel<<<dim3(2, 64, BB * NHEADS), dim3(32, 8)>>>(qkv, vt);

    // 4) fused flash attention -> ctx (fp16)
    flash_kernel<<<dim3(SS / BQ, BB * NHEADS), 256, FLASH_SMEM>>>(qkv, vt, mask, ctx);

    // 5) x1 = x + ctx @ wo + bo   (fp32 out)
    mma_gemm<128,128,64,32><<<dim3(DMODEL / 128, MTOK / 128, 1), 256, SM1>>>(
        ctx, woT, bo, x, x1,
        DMODEL, DMODEL, DMODEL, DMODEL, 0, 0);

    // 6) LN2 -> h (fp16)
    ln_kernel<<<MTOK, 256>>>(x1, h, ln2a, ln2b);

    // 7) ff = relu(h @ w1 + b1)  (fp16 out)
    mma_gemm<128,128,64,32><<<dim3(DFF / 128, MTOK / 128, 1), 256, SM1>>>(
        h, w1T, b1, nullptr, ff,
        DMODEL, DMODEL, DMODEL, DFF, 1, 1);

    // 8) out = x1 + ff @ w2 + b2  (fp32 out)
    mma_gemm<128,128,64,32><<<dim3(DMODEL / 128, MTOK / 128, 1), 256, SM1>>>(
        ff, w2T, b2, x1, out,
        DFF, DFF, DFF, DMODEL, 0, 0);
}

// round 17
// speedup vs baseline: 6.0835x; 1.1217x over previous
#include <cuda_runtime.h>
#include <cuda_bf16.h>
#include <cuda_fp16.h>
#include <cstdint>

// Problem constants
#define DMODEL 768
#define NHEADS 12
#define DK     64
#define DFF    3072
#define BB     2
#define SS     2048
#define MTOK   (BB * SS)
#define L2E    1.44269504088896f

// ---------------------------------------------------------------------------
// Scratch (__device__ globals)
// ---------------------------------------------------------------------------
__device__ __half g_h   [MTOK * DMODEL];
__device__ __half g_qkv [MTOK * 3 * DMODEL];                 // fused q|k|v, ld=2304
__device__ __half g_vt  [(long long)BB * NHEADS * DK * SS];  // V^T per head [dk][S]
__device__ __half g_ctx [MTOK * DMODEL];
__device__ float  g_x1  [MTOK * DMODEL];
__device__ __half g_ff  [MTOK * DFF];
__device__ __half g_wqkvT[3 * DMODEL * DMODEL];              // [n][k]
__device__ __half g_woT [DMODEL * DMODEL];
__device__ __half g_w1T [DFF * DMODEL];
__device__ __half g_w2T [DMODEL * DFF];
__device__ float  g_bqkv[3 * DMODEL];

// ---------------------------------------------------------------------------
// Helpers
// ---------------------------------------------------------------------------
__device__ __forceinline__ float fex2(float x) {
    float y; asm("ex2.approx.ftz.f32 %0, %1;" : "=f"(y) : "f"(x)); return y;
}
__device__ __forceinline__ void ldsm4(uint32_t addr, uint32_t* r) {
    asm volatile("ldmatrix.sync.aligned.m8n8.x4.shared.b16 {%0,%1,%2,%3}, [%4];"
                 : "=r"(r[0]), "=r"(r[1]), "=r"(r[2]), "=r"(r[3]) : "r"(addr));
}
__device__ __forceinline__ void cp16(uint32_t dst, const void* src) {
    asm volatile("cp.async.cg.shared.global [%0], [%1], 16;" :: "r"(dst), "l"(src));
}
// m16n8k16 fp16, fp32 accumulate
__device__ __forceinline__ void mma_f16(float* c, const uint32_t* a, const uint32_t* b) {
    asm volatile(
        "mma.sync.aligned.m16n8k16.row.col.f32.f16.f16.f32 "
        "{%0,%1,%2,%3}, {%4,%5,%6,%7}, {%8,%9}, {%0,%1,%2,%3};"
        : "+f"(c[0]), "+f"(c[1]), "+f"(c[2]), "+f"(c[3])
        : "r"(a[0]), "r"(a[1]), "r"(a[2]), "r"(a[3]), "r"(b[0]), "r"(b[1]));
}

// ---------------------------------------------------------------------------
// LayerNorm (torch-style, unbiased std). Output in fp16 (feeds MMAs).
// ---------------------------------------------------------------------------
__global__ void ln_kernel(const float* __restrict__ x, __half* __restrict__ out,
                          const float* __restrict__ alpha, const float* __restrict__ beta)
{
    const int row = blockIdx.x;
    const float* xr = x + (size_t)row * DMODEL;
    __half* orow = out + (size_t)row * DMODEL;
    const int tid = threadIdx.x;   // 256

    float v0 = xr[tid], v1 = xr[tid + 256], v2 = xr[tid + 512];
    float s = v0 + v1 + v2;

    __shared__ float red[8];
    #pragma unroll
    for (int o = 16; o; o >>= 1) s += __shfl_xor_sync(0xffffffffu, s, o);
    if ((tid & 31) == 0) red[tid >> 5] = s;
    __syncthreads();
    if (tid < 32) {
        float t = (tid < 8) ? red[tid] : 0.0f;
        #pragma unroll
        for (int o = 4; o; o >>= 1) t += __shfl_xor_sync(0xffffffffu, t, o);
        if (tid == 0) red[0] = t;
    }
    __syncthreads();
    const float mean = red[0] * (1.0f / DMODEL);
    const float d0 = v0 - mean, d1 = v1 - mean, d2 = v2 - mean;
    float q = d0 * d0 + d1 * d1 + d2 * d2;
    __syncthreads();

    #pragma unroll
    for (int o = 16; o; o >>= 1) q += __shfl_xor_sync(0xffffffffu, q, o);
    if ((tid & 31) == 0) red[tid >> 5] = q;
    __syncthreads();
    if (tid < 32) {
        float t = (tid < 8) ? red[tid] : 0.0f;
        #pragma unroll
        for (int o = 4; o; o >>= 1) t += __shfl_xor_sync(0xffffffffu, t, o);
        if (tid == 0) red[0] = t;
    }
    __syncthreads();
    const float var = red[0] * (1.0f / (DMODEL - 1));
    const float inv = alpha[0] / (sqrtf(var) + 1e-6f);
    const float bb  = beta[0];

    orow[tid]       = __float2half(d0 * inv + bb);
    orow[tid + 256] = __float2half(d1 * inv + bb);
    orow[tid + 512] = __float2half(d2 * inv + bb);
}

// ---------------------------------------------------------------------------
// Fused weight preprocessing (fp32 -> fp16 [n][k] + bias concat).
// ---------------------------------------------------------------------------
__global__ void transpose_all_kernel(
    const float* __restrict__ wq, const float* __restrict__ wk,
    const float* __restrict__ wv, const float* __restrict__ wo,
    const float* __restrict__ w1, const float* __restrict__ w2,
    __half* __restrict__ wqkvT, __half* __restrict__ woT,
    __half* __restrict__ w1T,   __half* __restrict__ w2T,
    const float* __restrict__ bq, const float* __restrict__ bk,
    const float* __restrict__ bv, float* __restrict__ bqkv)
{
    int id = blockIdx.x;
    const int tx = threadIdx.x, ty = threadIdx.y;     // (32, 8)

    if (id == 6912) {
        for (int i = ty * 32 + tx; i < 3 * DMODEL; i += 256) {
            float v;
            if (i < 768) v = bq[i];
            else if (i < 1536) v = bk[i - 768];
            else v = bv[i - 1536];
            bqkv[i] = v;
        }
        return;
    }

    const float* in; __half* out; int R, C;
    if      (id < 576)  {            in = wq; out = wqkvT;                 R = 768;  C = 768; }
    else if (id < 1152) { id -= 576; in = wk; out = wqkvT + 768 * 768;     R = 768;  C = 768; }
    else if (id < 1728) { id -= 1152; in = wv; out = wqkvT + 2 * 768 * 768; R = 768; C = 768; }
    else if (id < 2304) { id -= 1728; in = wo; out = woT;                  R = 768;  C = 768; }
    else if (id < 4608) { id -= 2304; in = w1; out = w1T;                  R = 768;  C = 3072; }
    else                { id -= 4608; in = w2; out = w2T;                  R = 3072; C = 768; }

    const int cb = C / 32;
    const int r0 = (id / cb) * 32, c0 = (id % cb) * 32;

    __shared__ float t[32][33];
    #pragma unroll
    for (int i = ty; i < 32; i += 8)
        t[i][tx] = in[(long long)(r0 + i) * C + c0 + tx];
    __syncthreads();
    #pragma unroll
    for (int i = ty; i < 32; i += 8)
        out[(long long)(c0 + i) * R + r0 + tx] = __float2half(t[tx][i]);
}

// ---------------------------------------------------------------------------
// Per-head V^T: vt[bh][dk][S] from qkv's V slice.
// ---------------------------------------------------------------------------
__global__ void vtrans_kernel(const __half* __restrict__ qkv, __half* __restrict__ vt)
{
    __shared__ __half t[32][34];
    const int z = blockIdx.z;
    const int b = z / NHEADS, hh = z % NHEADS;
    const __half* in = qkv + ((long long)b * SS) * (3 * DMODEL) + 2 * DMODEL + hh * DK;
    __half* out = vt + (long long)z * DK * SS;
    const int r0 = blockIdx.y * 32, c0 = blockIdx.x * 32;
    const int tx = threadIdx.x, ty = threadIdx.y;
    #pragma unroll
    for (int i = ty; i < 32; i += 8)
        t[i][tx] = in[(long long)(r0 + i) * (3 * DMODEL) + c0 + tx];
    __syncthreads();
    #pragma unroll
    for (int i = ty; i < 32; i += 8)
        out[(long long)(c0 + i) * SS + r0 + tx] = t[tx][i];
}

// ---------------------------------------------------------------------------
// Tensor-core GEMM, fp16 m16n8k16, cp.async + ldmatrix, 3-stage pipeline.
//   C = A @ B^T-layout (+bias) (+Res) (relu?), C fp32 or fp16 (out_half).
// A: [m][k] half (lda), B: [n][k] half (ldb). K % 64 == 0, K >= 192.
// BK=64 halves/iter (4 k16 MMA steps) -> half the sync/wait rounds vs BK=32.
// Smem rows: 64 halves + 8 pad = 144B stride (=16 mod 128, conflict-free).
// ---------------------------------------------------------------------------
template<int BM, int BN, int WM, int WN>
__global__ __launch_bounds__(256, 2)
void mma_gemm(const __half* __restrict__ A, const __half* __restrict__ Bm,
              const float* __restrict__ bias, const float* __restrict__ Res,
              void* __restrict__ Cv,
              int K, int lda, int ldb, int ldc,
              int relu, int out_half)
{
    constexpr int BK  = 64;                // halves per K-iter
    constexpr int STR = 72;                // halves per smem row (144 B)
    constexpr int MT  = WM / 16;
    constexpr int NT  = WN / 8;
    constexpr int WCOLS = BN / WN;
    constexpr int ACP = BM * 8 / 256;      // 16B chunks per thread (A)
    constexpr int BCP = BN * 8 / 256;

    extern __shared__ __half smh[];
    const uint32_t as_u = (uint32_t)__cvta_generic_to_shared(smh);
    const uint32_t bs_u = as_u + 3 * BM * STR * 2;

    const int tid  = threadIdx.x;
    const int warp = tid >> 5, lane = tid & 31;
    const int g = lane >> 2, t4 = lane & 3;
    const int wm0 = (warp / WCOLS) * WM;
    const int wn0 = (warp % WCOLS) * WN;
    const int m0 = blockIdx.y * BM;
    const int n0 = blockIdx.x * BN;
    const int l16 = lane & 15;
    const int lhi = (lane >> 4) * 16;      // byte offset for col-halves 8..15

    float acc[MT][NT][4] = {};
    const int nk = K / BK;

    auto LOAD = [&](int it, int buf) {
        const int k0 = it * BK;
        const uint32_t ab = as_u + (uint32_t)(buf * BM * STR) * 2u;
        #pragma unroll
        for (int u = 0; u < ACP; ++u) {
            const int f = u * 256 + tid;
            const int m = f >> 3;
            const int kc = (f & 7) * 8;
            cp16(ab + (uint32_t)(m * STR + kc) * 2u,
                 A + (long long)(m0 + m) * lda + k0 + kc);
        }
        const uint32_t bb = bs_u + (uint32_t)(buf * BN * STR) * 2u;
        #pragma unroll
        for (int u = 0; u < BCP; ++u) {
            const int f = u * 256 + tid;
            const int n = f >> 3;
            const int kc = (f & 7) * 8;
            cp16(bb + (uint32_t)(n * STR + kc) * 2u,
                 Bm + (long long)(n0 + n) * ldb + k0 + kc);
        }
        asm volatile("cp.async.commit_group;");
    };

    LOAD(0, 0);
    if (nk > 1) LOAD(1, 1);

    for (int it = 0; it < nk; ++it) {
        const int buf = it % 3;
        if (it + 1 < nk) asm volatile("cp.async.wait_group 1;");
        else             asm volatile("cp.async.wait_group 0;");
        __syncthreads();
        if (it + 2 < nk) LOAD(it + 2, (it + 2) % 3);

        const uint32_t ab = as_u + (uint32_t)(buf * BM * STR) * 2u;
        const uint32_t bb = bs_u + (uint32_t)(buf * BN * STR) * 2u;
        #pragma unroll
        for (int ks = 0; ks < 4; ++ks) {           // four k16 steps per BK=64
            uint32_t af[MT][4], bf[NT][2];
            #pragma unroll
            for (int mt = 0; mt < MT; ++mt)
                ldsm4(ab + (uint32_t)((wm0 + mt * 16 + l16) * STR) * 2u + ks * 32 + lhi,
                      af[mt]);
            #pragma unroll
            for (int p = 0; p < NT / 2; ++p) {
                uint32_t tmp[4];
                ldsm4(bb + (uint32_t)((wn0 + p * 16 + l16) * STR) * 2u + ks * 32 + lhi,
                      tmp);
                bf[2 * p][0]     = tmp[0]; bf[2 * p][1]     = tmp[2];
                bf[2 * p + 1][0] = tmp[1]; bf[2 * p + 1][1] = tmp[3];
            }
            #pragma unroll
            for (int mt = 0; mt < MT; ++mt)
                #pragma unroll
                for (int nt = 0; nt < NT; ++nt)
                    mma_f16(acc[mt][nt], af[mt], bf[nt]);
        }
    }

    #pragma unroll
    for (int mt = 0; mt < MT; ++mt) {
        const int r0 = m0 + wm0 + mt * 16 + g;
        #pragma unroll
        for (int nt = 0; nt < NT; ++nt) {
            const int c = n0 + wn0 + nt * 8 + 2 * t4;
            float2 v0 = make_float2(acc[mt][nt][0], acc[mt][nt][1]);
            float2 v1 = make_float2(acc[mt][nt][2], acc[mt][nt][3]);
            if (bias) {
                const float2 bv = *(const float2*)(bias + c);
                v0.x += bv.x; v0.y += bv.y;
                v1.x += bv.x; v1.y += bv.y;
            }
            if (Res) {
                const float2 a0 = *(const float2*)(Res + (long long)r0 * ldc + c);
                const float2 a1 = *(const float2*)(Res + (long long)(r0 + 8) * ldc + c);
                v0.x += a0.x; v0.y += a0.y;
                v1.x += a1.x; v1.y += a1.y;
            }
            if (relu) {
                v0.x = fmaxf(v0.x, 0.0f); v0.y = fmaxf(v0.y, 0.0f);
                v1.x = fmaxf(v1.x, 0.0f); v1.y = fmaxf(v1.y, 0.0f);
            }
            if (out_half) {
                __half* Ch = (__half*)Cv;
                *(__half2*)(Ch + (long long)r0 * ldc + c)       = __floats2half2_rn(v0.x, v0.y);
                *(__half2*)(Ch + (long long)(r0 + 8) * ldc + c) = __floats2half2_rn(v1.x, v1.y);
            } else {
                float* Cf = (float*)Cv;
                *(float2*)(Cf + (long long)r0 * ldc + c) = v0;
                *(float2*)(Cf + (long long)(r0 + 8) * ldc + c) = v1;
            }
        }
    }
}

#define SMEM_BYTES(BM, BN) (3 * ((BM) + (BN)) * 72 * 2)

// ---------------------------------------------------------------------------
// Fused flash attention, fp16 m16n8k16 MMA, online softmax.
//   grid: (S/128, B*H). 8 warps; warp w owns Q rows w*16..w*16+15.
// BKV=64 per step (32 steps): halves per-step barrier/softmax overhead.
// All tiles stride 72 halves (144B). Smem ~74KB -> 2 CTAs/SM.
// ---------------------------------------------------------------------------
#define BQ   128
#define BKV  64
#define FSTR 72

__global__ __launch_bounds__(256, 2)
void flash_kernel(const __half* __restrict__ qkv, const __half* __restrict__ vt,
                  const int* __restrict__ mask, __half* __restrict__ ctx)
{
    extern __shared__ __half smh[];
    const int QS = 0;                         // [128][72]
    const int KS = QS + BQ * FSTR;            // [2][64][72]
    const int VS = KS + 2 * BKV * FSTR;       // [2][64][72]  (V^T: dk rows, kv cols)
    const int PS = VS + 2 * DK * FSTR;        // [128][72]
    const int MS = PS + BQ * FSTR;            // int [2][64]
    __half* Psh = smh + PS;
    int*    Msh = (int*)(smh + MS);
    const uint32_t base_u = (uint32_t)__cvta_generic_to_shared(smh);
    const uint32_t qs_u = base_u + QS * 2;
    const uint32_t ks_u = base_u + KS * 2;
    const uint32_t vs_u = base_u + VS * 2;
    const uint32_t ps_u = base_u + PS * 2;
    const uint32_t ms_u = base_u + MS * 2;

    const int qb = blockIdx.x, bh = blockIdx.y;
    const int b = bh / NHEADS, hh = bh % NHEADS;
    const long long tok0 = (long long)b * SS + qb * BQ;
    const __half* Qg = qkv + tok0 * (3 * DMODEL) + hh * DK;
    const __half* Kg = qkv + (long long)b * SS * (3 * DMODEL) + DMODEL + hh * DK;
    const __half* Vg = vt + (long long)bh * DK * SS;        // [dk][S], ld=SS
    const int*    mg = mask + (long long)b * SS;

    const int tid  = threadIdx.x;
    const int warp = tid >> 5, lane = tid & 31;
    const int g = lane >> 2, t4 = lane & 3;
    const int row0 = warp * 16;
    const int l16 = lane & 15;
    const int lhi = (lane >> 4) * 16;

    // Q tile: 128 rows x 8 chunks = 1024 -> 4/thread
    #pragma unroll
    for (int u = 0; u < 4; ++u) {
        const int f = u * 256 + tid;
        const int r = f >> 3, kc = (f & 7) * 8;
        cp16(qs_u + (uint32_t)(r * FSTR + kc) * 2u, Qg + (long long)r * (3 * DMODEL) + kc);
    }
    asm volatile("cp.async.commit_group;");

    auto LOAD = [&](int s, int buf) {
        const int kv0 = s * BKV;
        const uint32_t kb = ks_u + (uint32_t)(buf * BKV * FSTR) * 2u;
        #pragma unroll
        for (int u = 0; u < 2; ++u) {              // K: 64 rows x 8 chunks
            const int f = u * 256 + tid;
            const int r = f >> 3, kc = (f & 7) * 8;
            cp16(kb + (uint32_t)(r * FSTR + kc) * 2u,
                 Kg + (long long)(kv0 + r) * (3 * DMODEL) + kc);
        }
        const uint32_t vb = vs_u + (uint32_t)(buf * DK * FSTR) * 2u;
        #pragma unroll
        for (int u = 0; u < 2; ++u) {              // V^T: 64 rows x 8 chunks
            const int f = u * 256 + tid;
            const int r = f >> 3, cc = (f & 7) * 8;
            cp16(vb + (uint32_t)(r * FSTR + cc) * 2u,
                 Vg + (long long)r * SS + kv0 + cc);
        }
        if (tid < 16)                              // mask: 64 ints
            cp16(ms_u + (uint32_t)(buf * BKV + tid * 4) * 4u, mg + kv0 + tid * 4);
        asm volatile("cp.async.commit_group;");
    };

    LOAD(0, 0);

    float m_a = -3.0e38f, m_b = -3.0e38f, l_a = 0.0f, l_b = 0.0f;
    float oacc[8][4] = {};

    const int NSTEP = SS / BKV;   // 32
    for (int s = 0; s < NSTEP; ++s) {
        const int buf = s & 1;
        asm volatile("cp.async.wait_group 0;");
        __syncthreads();
        if (s + 1 < NSTEP) LOAD(s + 1, buf ^ 1);

        const uint32_t kb = ks_u + (uint32_t)(buf * BKV * FSTR) * 2u;
        const uint32_t vb = vs_u + (uint32_t)(buf * DK * FSTR) * 2u;

        // --- S = Q @ K^T : rows row0..row0+15, cols 0..63 (4 k16 steps)
        float sacc[8][4] = {};
        #pragma unroll
        for (int ks = 0; ks < 4; ++ks) {
            uint32_t af[4];
            ldsm4(qs_u + (uint32_t)((row0 + l16) * FSTR) * 2u + ks * 32 + lhi, af);
            #pragma unroll
            for (int p = 0; p < 4; ++p) {
                uint32_t tmp[4], bf0[2], bf1[2];
                ldsm4(kb + (uint32_t)((p * 16 + l16) * FSTR) * 2u + ks * 32 + lhi, tmp);
                bf0[0] = tmp[0]; bf0[1] = tmp[2];
                bf1[0] = tmp[1]; bf1[1] = tmp[3];
                mma_f16(sacc[2 * p], af, bf0);
                mma_f16(sacc[2 * p + 1], af, bf1);
            }
        }

        // --- mask + scale + row max
        const int* mbuf = Msh + buf * BKV;
        float rmax_a = -3.0e38f, rmax_b = -3.0e38f;
        #pragma unroll
        for (int nt = 0; nt < 8; ++nt) {
            #pragma unroll
            for (int e = 0; e < 2; ++e) {
                const int c = nt * 8 + 2 * t4 + e;
                const bool live = (mbuf[c] != 0);
                float v0 = sacc[nt][e] * 0.125f;     if (!live) v0 = -1e9f;
                float v1 = sacc[nt][2 + e] * 0.125f; if (!live) v1 = -1e9f;
                sacc[nt][e] = v0; sacc[nt][2 + e] = v1;
                rmax_a = fmaxf(rmax_a, v0); rmax_b = fmaxf(rmax_b, v1);
            }
        }
        rmax_a = fmaxf(rmax_a, __shfl_xor_sync(0xffffffffu, rmax_a, 1));
        rmax_a = fmaxf(rmax_a, __shfl_xor_sync(0xffffffffu, rmax_a, 2));
        rmax_b = fmaxf(rmax_b, __shfl_xor_sync(0xffffffffu, rmax_b, 1));
        rmax_b = fmaxf(rmax_b, __shfl_xor_sync(0xffffffffu, rmax_b, 2));

        const float mna = fmaxf(m_a, rmax_a), mnb = fmaxf(m_b, rmax_b);
        const float ca = fex2((m_a - mna) * L2E), cb = fex2((m_b - mnb) * L2E);
        m_a = mna; m_b = mnb;

        // --- P = exp(s - m), sum, store fp16 P to smem
        float sum_a = 0.0f, sum_b = 0.0f;
        #pragma unroll
        for (int nt = 0; nt < 8; ++nt) {
            const float p0 = fex2((sacc[nt][0] - mna) * L2E);
            const float p1 = fex2((sacc[nt][1] - mna) * L2E);
            const float p2 = fex2((sacc[nt][2] - mnb) * L2E);
            const float p3 = fex2((sacc[nt][3] - mnb) * L2E);
            sum_a += p0 + p1; sum_b += p2 + p3;
            const int c = nt * 8 + 2 * t4;
            *(__half2*)(Psh + (row0 + g) * FSTR + c)     = __floats2half2_rn(p0, p1);
            *(__half2*)(Psh + (row0 + g + 8) * FSTR + c) = __floats2half2_rn(p2, p3);
        }
        sum_a += __shfl_xor_sync(0xffffffffu, sum_a, 1);
        sum_a += __shfl_xor_sync(0xffffffffu, sum_a, 2);
        sum_b += __shfl_xor_sync(0xffffffffu, sum_b, 1);
        sum_b += __shfl_xor_sync(0xffffffffu, sum_b, 2);
        l_a = l_a * ca + sum_a;
        l_b = l_b * cb + sum_b;

        #pragma unroll
        for (int nt = 0; nt < 8; ++nt) {
            oacc[nt][0] *= ca; oacc[nt][1] *= ca;
            oacc[nt][2] *= cb; oacc[nt][3] *= cb;
        }
        __syncwarp();

        // --- O += P @ V : A from Ps (q rows x kv), B from Vs (dk rows x kv)
        #pragma unroll
        for (int ks = 0; ks < 4; ++ks) {
            uint32_t af[4];
            ldsm4(ps_u + (uint32_t)((row0 + l16) * FSTR) * 2u + ks * 32 + lhi, af);
            #pragma unroll
            for (int p = 0; p < 4; ++p) {
                uint32_t tmp[4], bf0[2], bf1[2];
                ldsm4(vb + (uint32_t)((p * 16 + l16) * FSTR) * 2u + ks * 32 + lhi, tmp);
                bf0[0] = tmp[0]; bf0[1] = tmp[2];
                bf1[0] = tmp[1]; bf1[1] = tmp[3];
                mma_f16(oacc[2 * p], af, bf0);
                mma_f16(oacc[2 * p + 1], af, bf1);
            }
        }
    }

    // --- epilogue: normalize, write ctx (fp16; feeds O-proj MMA)
    const float ia = 1.0f / l_a, ib = 1.0f / l_b;
    __half* crow_a = ctx + (tok0 + row0 + g) * DMODEL + hh * DK;
    __half* crow_b = ctx + (tok0 + row0 + g + 8) * DMODEL + hh * DK;
    #pragma unroll
    for (int nt = 0; nt < 8; ++nt) {
        const int c = nt * 8 + 2 * t4;
        *(__half2*)(crow_a + c) = __floats2half2_rn(oacc[nt][0] * ia, oacc[nt][1] * ia);
        *(__half2*)(crow_b + c) = __floats2half2_rn(oacc[nt][2] * ib, oacc[nt][3] * ib);
    }
}

#define FLASH_SMEM ((BQ * FSTR + 2 * BKV * FSTR + 2 * DK * FSTR + BQ * FSTR) * 2 + 2 * BKV * 4)

// ---------------------------------------------------------------------------
// Launch driver
// ---------------------------------------------------------------------------
extern "C" void kernel_launch(void* const* d_in, const int* in_sizes, int n_in,
                              void* d_out, int out_size)
{
    (void)in_sizes; (void)n_in; (void)out_size;
    const float* x    = (const float*)d_in[0];
    const int*   mask = (const int*)  d_in[1];
    const float* wq = (const float*)d_in[2],  *bq = (const float*)d_in[3];
    const float* wk = (const float*)d_in[4],  *bk = (const float*)d_in[5];
    const float* wv = (const float*)d_in[6],  *bv = (const float*)d_in[7];
    const float* wo = (const float*)d_in[8],  *bo = (const float*)d_in[9];
    const float* w1 = (const float*)d_in[10], *b1 = (const float*)d_in[11];
    const float* w2 = (const float*)d_in[12], *b2 = (const float*)d_in[13];
    const float* ln1a = (const float*)d_in[14], *ln1b = (const float*)d_in[15];
    const float* ln2a = (const float*)d_in[16], *ln2b = (const float*)d_in[17];
    float* out = (float*)d_out;

    __half *h, *qkv, *vt, *ctx, *ff, *wqkvT, *woT, *w1T, *w2T;
    float *x1, *bqkv;
    cudaGetSymbolAddress((void**)&h,     g_h);
    cudaGetSymbolAddress((void**)&qkv,   g_qkv);
    cudaGetSymbolAddress((void**)&vt,    g_vt);
    cudaGetSymbolAddress((void**)&ctx,   g_ctx);
    cudaGetSymbolAddress((void**)&x1,    g_x1);
    cudaGetSymbolAddress((void**)&ff,    g_ff);
    cudaGetSymbolAddress((void**)&wqkvT, g_wqkvT);
    cudaGetSymbolAddress((void**)&woT,   g_woT);
    cudaGetSymbolAddress((void**)&w1T,   g_w1T);
    cudaGetSymbolAddress((void**)&w2T,   g_w2T);
    cudaGetSymbolAddress((void**)&bqkv,  g_bqkv);

    constexpr int SM1 = SMEM_BYTES(128, 128);   // 110592

    cudaFuncSetAttribute((const void*)mma_gemm<128,128,64,32>,
                         cudaFuncAttributeMaxDynamicSharedMemorySize, SM1);
    cudaFuncSetAttribute((const void*)flash_kernel,
                         cudaFuncAttributeMaxDynamicSharedMemorySize, FLASH_SMEM);

    // 0) weight preprocessing (fp32 -> fp16 [n][k] + bias concat)
    transpose_all_kernel<<<6913, dim3(32, 8)>>>(
        wq, wk, wv, wo, w1, w2, wqkvT, woT, w1T, w2T, bq, bk, bv, bqkv);

    // 1) LN1 -> h (fp16)
    ln_kernel<<<MTOK, 256>>>(x, h, ln1a, ln1b);

    // 2) fused QKV: [4096,768] @ [768,2304] + bqkv -> qkv (fp16)
    mma_gemm<128,128,64,32><<<dim3(2304 / 128, MTOK / 128, 1), 256, SM1>>>(
        h, wqkvT, bqkv, nullptr, qkv,
        DMODEL, DMODEL, DMODEL, 3 * DMODEL, 0, 1);

    // 3) V^T per head (fp16)
    vtrans_kernel<<<dim3(2, 64, BB * NHEADS), dim3(32, 8)>>>(qkv, vt);

    // 4) fused flash attention -> ctx (fp16)
    flash_kernel<<<dim3(SS / BQ, BB * NHEADS), 256, FLASH_SMEM>>>(qkv, vt, mask, ctx);

    // 5) x1 = x + ctx @ wo + bo   (fp32 out)
    mma_gemm<128,128,64,32><<<dim3(DMODEL / 128, MTOK / 128, 1), 256, SM1>>>(
        ctx, woT, bo, x, x1,
        DMODEL, DMODEL, DMODEL, DMODEL, 0, 0);

    // 6) LN2 -> h (fp16)
    ln_kernel<<<MTOK, 256>>>(x1, h, ln2a, ln2b);

    // 7) ff = relu(h @ w1 + b1)  (fp16 out)
    mma_gemm<128,128,64,32><<<dim3(DFF / 128, MTOK / 128, 1), 256, SM1>>>(
        h, w1T, b1, nullptr, ff,
        DMODEL, DMODEL, DMODEL, DFF, 1, 1);

    // 8) out = x1 + ff @ w2 + b2  (fp32 out)
    mma_gemm<128,128,64,32><<<dim3(DMODEL / 128, MTOK / 128, 1), 256, SM1>>>(
        ff, w2T, b2, x1, out,
        DFF, DFF, DFF, DMODEL, 0, 0);
}